// round 7
// baseline (speedup 1.0000x reference)
#include <cuda_runtime.h>
#include <cuda_bf16.h>
#include <math.h>
#include <stdint.h>

#define KDIM 384
#define NEL 25165824   // 16*64*64*384

// fp32 buffers
static __device__ float g_xs[NEL];      // xs (pre-DCT)
static __device__ float g_z [NEL];      // silu(z)
static __device__ float g_s [NEL];      // modulation scalar
static __device__ float g_f1[NEL];
static __device__ float g_W[4096];      // 64x64 DCT-II matrix (fp32, for dct_ln)
// bf16 split W planes: [orient][plane hi/lo][64][72]
static __device__ __nv_bfloat16 g_Wsp[2][2][64][72];
// bf16 split buffers ([row][768]: hi 384 | lo 384)
static __device__ float g_xd[NEL];      // split conv output
static __device__ float g_fq[NEL];      // split freq_embed
static __device__ float g_f2[NEL];      // split LN output / fp32 scratch
static __device__ float g_wl[294912];   // split lin_w  (768 rows)
static __device__ float g_wt[147456];   // split tok_w  (384 rows)
static __device__ float g_wo[147456];   // split out_w  (384 rows)

// ================================================================ helpers
__device__ __forceinline__ uint32_t smem_u32(const void* p) {
    uint32_t a;
    asm("{ .reg .u64 t; cvta.to.shared.u64 t, %1; cvt.u32.u64 %0, t; }" : "=r"(a) : "l"(p));
    return a;
}
__device__ __forceinline__ void ldsm4(uint32_t (&r)[4], uint32_t addr) {
    asm volatile("ldmatrix.sync.aligned.m8n8.x4.shared.b16 {%0,%1,%2,%3}, [%4];"
                 : "=r"(r[0]), "=r"(r[1]), "=r"(r[2]), "=r"(r[3]) : "r"(addr));
}
__device__ __forceinline__ void ldsm4t(uint32_t (&r)[4], uint32_t addr) {
    asm volatile("ldmatrix.sync.aligned.m8n8.x4.trans.shared.b16 {%0,%1,%2,%3}, [%4];"
                 : "=r"(r[0]), "=r"(r[1]), "=r"(r[2]), "=r"(r[3]) : "r"(addr));
}
__device__ __forceinline__ void mma16816(float (&d)[4], const uint32_t (&a)[4],
                                         uint32_t b0, uint32_t b1) {
    asm volatile(
        "mma.sync.aligned.m16n8k16.row.col.f32.bf16.bf16.f32 "
        "{%0,%1,%2,%3}, {%4,%5,%6,%7}, {%8,%9}, {%0,%1,%2,%3};"
        : "+f"(d[0]), "+f"(d[1]), "+f"(d[2]), "+f"(d[3])
        : "r"(a[0]), "r"(a[1]), "r"(a[2]), "r"(a[3]), "r"(b0), "r"(b1));
}
__device__ __forceinline__ unsigned swz(unsigned off) {
    return off ^ ((off >> 3) & 0x70);
}
__device__ __forceinline__ void cp16(uint32_t dst, const void* src) {
    asm volatile("cp.async.cg.shared.global [%0], [%1], 16;" :: "r"(dst), "l"(src) : "memory");
}
__device__ __forceinline__ void cp_commit() {
    asm volatile("cp.async.commit_group;" ::: "memory");
}
template<int N> __device__ __forceinline__ void cp_wait() {
    asm volatile("cp.async.wait_group %0;" :: "n"(N) : "memory");
}
__device__ __forceinline__ void split2(float v, __nv_bfloat16& h, __nv_bfloat16& l) {
    h = __float2bfloat16(v);
    l = __float2bfloat16(v - __bfloat162float(h));
}

// ================================================================ build W
__global__ void build_w_k() {
    int i = blockIdx.x * 256 + threadIdx.x;
    int n = i >> 6, h = i & 63;
    float v = cosf((float)n * (((float)h + 0.5f) * (3.14159265358979323846f / 64.0f)))
            * 0.17677669529663687f;
    if (n == 0) v *= 0.70710678118654752f;
    g_W[i] = v;
    __nv_bfloat16 hi, lo; split2(v, hi, lo);
    g_Wsp[0][0][n][h] = hi;
    g_Wsp[0][1][n][h] = lo;
    g_Wsp[1][0][h][n] = hi;
    g_Wsp[1][1][h][n] = lo;
}

// ================================================================ split fp32 [rows][384] -> bf16 [rows][768]
__global__ void split_k(const float* __restrict__ src, __nv_bfloat16* __restrict__ dst, int n4) {
    int i = blockIdx.x * 256 + threadIdx.x;
    if (i >= n4) return;
    int row = i / 96;
    int col = (i - row * 96) * 4;
    float4 v = *(const float4*)(src + (size_t)row * 384 + col);
    __nv_bfloat16 h0,h1,h2,h3,l0,l1,l2,l3;
    split2(v.x,h0,l0); split2(v.y,h1,l1); split2(v.z,h2,l2); split2(v.w,h3,l3);
    __nv_bfloat16* d = dst + (size_t)row * 768 + col;
    d[0]=h0; d[1]=h1; d[2]=h2; d[3]=h3;
    d[384]=l0; d[385]=l1; d[386]=l2; d[387]=l3;
}

// ================================================================ depthwise conv 3x3, NCHW -> NHWC split bf16
__global__ void dwconv_k(const float* __restrict__ x, const float* __restrict__ w9,
                         const float* __restrict__ bias, __nv_bfloat16* __restrict__ outp)
{
    const int bh = blockIdx.x;
    const int c  = threadIdx.x;
    const int b  = bh >> 6, h = bh & 63;
    const float* xp = x + (size_t)(b * 384 + c) * 64 * 64;
    float k0 = w9[c*9+0], k1 = w9[c*9+1], k2 = w9[c*9+2];
    float k3 = w9[c*9+3], k4 = w9[c*9+4], k5 = w9[c*9+5];
    float k6 = w9[c*9+6], k7 = w9[c*9+7], k8 = w9[c*9+8];
    const float bi = bias[c];
    const float* r0 = (h > 0)  ? xp + (h-1)*64 : 0;
    const float* r1 = xp + h*64;
    const float* r2 = (h < 63) ? xp + (h+1)*64 : 0;
    float a0 = 0.f, a1 = 0.f, a2 = 0.f;
    float m0 = r0 ? r0[0] : 0.f;
    float m1 = r1[0];
    float m2 = r2 ? r2[0] : 0.f;
    __nv_bfloat16* ob = outp + (size_t)bh * 64 * 768 + c;
    #pragma unroll 4
    for (int w = 0; w < 64; w++) {
        float n0, n1, n2;
        if (w < 63) {
            n0 = r0 ? r0[w+1] : 0.f;
            n1 = r1[w+1];
            n2 = r2 ? r2[w+1] : 0.f;
        } else { n0 = n1 = n2 = 0.f; }
        float acc = bi
            + a0*k0 + m0*k1 + n0*k2
            + a1*k3 + m1*k4 + n1*k5
            + a2*k6 + m2*k7 + n2*k8;
        __nv_bfloat16 hi, lo; split2(acc, hi, lo);
        ob[(size_t)w * 768]       = hi;
        ob[(size_t)w * 768 + 384] = lo;
        a0 = m0; a1 = m1; a2 = m2;
        m0 = n0; m1 = n1; m2 = n2;
    }
}

// ================================================================ mma.sync split-bf16 GEMM
// 128(M) x 192(N) tile, 384 threads (12 warps: 4 m-slices x 3 n-slices)
// smem: [A0 16K][A1 16K][B0 24K][B1 24K] = 80KB, 2-stage cp.async
template<int MODE>
__global__ void __launch_bounds__(384) tgemm_k(
    const __nv_bfloat16* __restrict__ A, const __nv_bfloat16* __restrict__ Wt,
    const float* __restrict__ bias,
    float* __restrict__ o0, float* __restrict__ o1,
    const float* __restrict__ cp_, const float* __restrict__ ap)
{
    extern __shared__ char sm[];
    const int t    = threadIdx.x;
    const int wid  = t >> 5;
    const int lane = t & 31;
    const int m0 = blockIdx.y * 128;
    const int n0 = blockIdx.x * 192;
    const uint32_t smemBase = smem_u32(sm);

    // ---- loader: threads 0..127 -> A row t; 128..319 -> B row t-128; rest idle
    const bool lact = t < 320;
    const int lmat = (t >= 128) ? 1 : 0;
    const int lrw  = lmat ? (t - 128) : t;
    const __nv_bfloat16* lsrc = lmat ? (Wt + (size_t)(n0 + lrw) * 768)
                                     : (A  + (size_t)(m0 + lrw) * 768);
    const unsigned sx = (unsigned)(lrw & 7) * 16;
    const uint32_t ldst0 = smemBase + (lmat ? 32768u : 0u) + (unsigned)lrw * 128;
    const unsigned lstride = lmat ? 24576u : 16384u;

    #define TG_ISSUE(CH, STG) do { if (lact) {                       \
        const __nv_bfloat16* s_ = lsrc + (CH) * 32;                  \
        uint32_t d_ = ldst0 + (STG) * lstride;                       \
        cp16(d_ + (0u   ^ sx), s_ + 0);                              \
        cp16(d_ + (16u  ^ sx), s_ + 8);                              \
        cp16(d_ + (32u  ^ sx), s_ + 16);                             \
        cp16(d_ + (48u  ^ sx), s_ + 24);                             \
        cp16(d_ + (64u  ^ sx), s_ + 384);                           \
        cp16(d_ + (80u  ^ sx), s_ + 392);                           \
        cp16(d_ + (96u  ^ sx), s_ + 400);                           \
        cp16(d_ + (112u ^ sx), s_ + 408);                           \
    } } while (0)

    TG_ISSUE(0, 0); cp_commit();

    const int wm = wid & 3;        // 0..3, 32-row slice
    const int wn = wid >> 2;       // 0..2, 64-col slice
    float acc[2][8][4];
    #pragma unroll
    for (int i = 0; i < 2; i++)
        #pragma unroll
        for (int j = 0; j < 8; j++)
            #pragma unroll
            for (int q = 0; q < 4; q++) acc[i][j][q] = 0.f;

    const int lr = lane & 15;
    const int lh = lane >> 4;

    const int NCH = KDIM / 32;   // 12
    for (int ch = 0; ch < NCH; ch++) {
        const int buf = ch & 1;
        if (ch + 1 < NCH) {
            TG_ISSUE(ch + 1, (ch + 1) & 1);
            cp_commit();
            cp_wait<1>();
        } else {
            cp_wait<0>();
        }
        __syncthreads();

        const uint32_t aS = smemBase + (unsigned)buf * 16384;
        const uint32_t bS = smemBase + 32768 + (unsigned)buf * 24576;
        #pragma unroll
        for (int ks = 0; ks < 2; ks++) {
            const unsigned kc2 = (unsigned)(ks * 16 + lh * 8) * 2;
            uint32_t ahi[2][4], alo[2][4];
            #pragma unroll
            for (int mt = 0; mt < 2; mt++) {
                unsigned off = (unsigned)(wm * 32 + mt * 16 + lr) * 128 + kc2;
                ldsm4(ahi[mt], aS + swz(off));
                ldsm4(alo[mt], aS + swz(off + 64));
            }
            uint32_t bhi[4][4], blo[4][4];
            #pragma unroll
            for (int ng = 0; ng < 4; ng++) {
                unsigned off = (unsigned)(wn * 64 + ng * 16 + lr) * 128 + kc2;
                ldsm4(bhi[ng], bS + swz(off));
                ldsm4(blo[ng], bS + swz(off + 64));
            }
            #pragma unroll
            for (int mt = 0; mt < 2; mt++)
                #pragma unroll
                for (int ng = 0; ng < 4; ng++) {
                    mma16816(acc[mt][2*ng],   ahi[mt], bhi[ng][0], bhi[ng][2]);
                    mma16816(acc[mt][2*ng+1], ahi[mt], bhi[ng][1], bhi[ng][3]);
                    mma16816(acc[mt][2*ng],   ahi[mt], blo[ng][0], blo[ng][2]);
                    mma16816(acc[mt][2*ng+1], ahi[mt], blo[ng][1], blo[ng][3]);
                    mma16816(acc[mt][2*ng],   alo[mt], bhi[ng][0], bhi[ng][2]);
                    mma16816(acc[mt][2*ng+1], alo[mt], bhi[ng][1], bhi[ng][3]);
                }
        }
        __syncthreads();
    }
    #undef TG_ISSUE

    // ---- epilogue
    const int qr = lane >> 2;
    const int qc = lane & 3;
    const int mbw = m0 + wm * 32;
    const int nbw = n0 + wn * 64;

    float cc0 = 0.f, css = 0.f;
    if (MODE == 1) {
        cc0 = cp_[0];
        css = (1.0f + 0.5f * ap[0]) / (cc0 + 1e-8f);
    }

    #pragma unroll
    for (int mt = 0; mt < 2; mt++) {
        #pragma unroll
        for (int half = 0; half < 2; half++) {
            const int m = mbw + mt * 16 + qr + half * 8;
            float ee = 0.f;
            if (MODE == 1) {
                const float kp = 3.14159265358979323846f / 64.0f;
                int hh = (m >> 6) & 63, ww = m & 63;
                ee = kp * kp * (float)(hh * hh + ww * ww);
            }
            #pragma unroll
            for (int nt = 0; nt < 8; nt++) {
                const int n = nbw + nt * 8 + qc * 2;
                float v0 = acc[mt][nt][half * 2 + 0] + __ldg(bias + n);
                float v1 = acc[mt][nt][half * 2 + 1] + __ldg(bias + n + 1);
                if (MODE == 0) {
                    if (n >= 384) {
                        v0 *= 1.0f / (1.0f + __expf(-v0));
                        v1 *= 1.0f / (1.0f + __expf(-v1));
                        *(float2*)(o1 + (size_t)m * 384 + (n - 384)) = make_float2(v0, v1);
                    } else {
                        *(float2*)(o0 + (size_t)m * 384 + n) = make_float2(v0, v1);
                    }
                } else if (MODE == 1) {
                    float tg0 = 0.5f * v0 * (1.0f + erff(v0 * 0.70710678118654752f));
                    float tg1 = 0.5f * v1 * (1.0f + erff(v1 * 0.70710678118654752f));
                    float ct0 = cc0 * tg0, ct1 = cc0 * tg1;
                    float r0 = (__cosf(ct0) + __sinf(ct0) * css) * __expf(-ee * tg0);
                    float r1 = (__cosf(ct1) + __sinf(ct1) * css) * __expf(-ee * tg1);
                    *(float2*)(o0 + (size_t)m * 384 + n) = make_float2(r0, r1);
                } else {
                    *(float2*)(o0 + (size_t)m * 384 + n) = make_float2(v0, v1);
                }
            }
        }
    }
}

// ================================================================ tensorized 64-pt cosine transform (split bf16)
#define DT_SMEM (17408*2 + 9216*2)
template<bool FWD, bool MOD>
__global__ void __launch_bounds__(256) dctT_k(
    float* __restrict__ out, const float* __restrict__ X,
    const float* __restrict__ S, int ldRow)
{
    extern __shared__ char ds[];
    __nv_bfloat16* sXhi = (__nv_bfloat16*)ds;
    __nv_bfloat16* sXlo = (__nv_bfloat16*)(ds + 17408);
    __nv_bfloat16* sWp  = (__nv_bfloat16*)(ds + 34816);
    const int t = threadIdx.x;
    const int bb = blockIdx.y;
    const int j0 = blockIdx.x << 7;

    {
        const uint4* src = (const uint4*)&g_Wsp[FWD ? 0 : 1][0][0][0];
        uint4* dst = (uint4*)sWp;
        for (int u = t; u < 1152; u += 256) dst[u] = src[u];
    }
    const float* Xb = X + (size_t)bb * 64 * ldRow + j0;
    #pragma unroll
    for (int it = 0; it < 8; it++) {
        int idx = t + 256 * it;
        int row = idx >> 5, c4 = (idx & 31) << 2;
        float4 v = *(const float4*)(Xb + (size_t)row * ldRow + c4);
        __nv_bfloat16 h0,h1,h2,h3,l0,l1,l2,l3;
        split2(v.x,h0,l0); split2(v.y,h1,l1); split2(v.z,h2,l2); split2(v.w,h3,l3);
        unsigned hw0 = ((unsigned)__bfloat16_as_ushort(h1) << 16) | __bfloat16_as_ushort(h0);
        unsigned hw1 = ((unsigned)__bfloat16_as_ushort(h3) << 16) | __bfloat16_as_ushort(h2);
        unsigned lw0 = ((unsigned)__bfloat16_as_ushort(l1) << 16) | __bfloat16_as_ushort(l0);
        unsigned lw1 = ((unsigned)__bfloat16_as_ushort(l3) << 16) | __bfloat16_as_ushort(l2);
        *(uint2*)(sXhi + row * 136 + c4) = make_uint2(hw0, hw1);
        *(uint2*)(sXlo + row * 136 + c4) = make_uint2(lw0, lw1);
    }
    __syncthreads();

    const int wid = t >> 5, lane = t & 31;
    const int wm = wid & 1, wn = wid >> 1;
    const uint32_t xhiB = smem_u32(sXhi), xloB = smem_u32(sXlo);
    const uint32_t whiB = smem_u32(sWp),  wloB = whiB + 9216;

    float acc[2][4][4];
    #pragma unroll
    for (int i = 0; i < 2; i++)
        #pragma unroll
        for (int j = 0; j < 4; j++)
            #pragma unroll
            for (int q = 0; q < 4; q++) acc[i][j][q] = 0.f;

    const int lr = lane & 15, lh = lane >> 4;
    #pragma unroll
    for (int ks = 0; ks < 4; ks++) {
        uint32_t ahi[2][4], alo[2][4];
        #pragma unroll
        for (int mt = 0; mt < 2; mt++) {
            unsigned off = (unsigned)(wm * 32 + mt * 16 + lr) * 144 + (unsigned)(ks * 16 + lh * 8) * 2;
            ldsm4(ahi[mt], whiB + off);
            ldsm4(alo[mt], wloB + off);
        }
        uint32_t bhi[2][4], blo[2][4];
        #pragma unroll
        for (int ng = 0; ng < 2; ng++) {
            unsigned off = (unsigned)(ks * 16 + lr) * 272 + (unsigned)(wn * 32 + ng * 16 + lh * 8) * 2;
            ldsm4t(bhi[ng], xhiB + off);
            ldsm4t(blo[ng], xloB + off);
        }
        #pragma unroll
        for (int mt = 0; mt < 2; mt++)
            #pragma unroll
            for (int ng = 0; ng < 2; ng++) {
                mma16816(acc[mt][2*ng],   ahi[mt], bhi[ng][0], bhi[ng][1]);
                mma16816(acc[mt][2*ng+1], ahi[mt], bhi[ng][2], bhi[ng][3]);
                mma16816(acc[mt][2*ng],   ahi[mt], blo[ng][0], blo[ng][1]);
                mma16816(acc[mt][2*ng+1], ahi[mt], blo[ng][2], blo[ng][3]);
                mma16816(acc[mt][2*ng],   alo[mt], bhi[ng][0], bhi[ng][1]);
                mma16816(acc[mt][2*ng+1], alo[mt], bhi[ng][2], bhi[ng][3]);
            }
    }

    const int qr = lane >> 2, qc = lane & 3;
    float* ob = out + (size_t)bb * 64 * ldRow + j0;
    const float* sb = S + (size_t)bb * 64 * ldRow + j0;
    #pragma unroll
    for (int mt = 0; mt < 2; mt++)
        #pragma unroll
        for (int half = 0; half < 2; half++) {
            const int i = wm * 32 + mt * 16 + qr + half * 8;
            #pragma unroll
            for (int ng = 0; ng < 4; ng++) {
                const int j = wn * 32 + ng * 8 + qc * 2;
                float v0 = acc[mt][ng][half * 2 + 0];
                float v1 = acc[mt][ng][half * 2 + 1];
                if (MOD) {
                    float2 s2 = *(const float2*)(sb + (size_t)i * ldRow + j);
                    v0 *= s2.x; v1 *= s2.y;
                }
                *(float2*)(ob + (size_t)i * ldRow + j) = make_float2(v0, v1);
            }
        }
}

// ================================================================ fused IDCT(w) + LayerNorm + silu-gate + bf16 split
#define DL_SMEM ((4096 + 2*64*392) * 4)
__global__ void __launch_bounds__(256) dct_ln_k(
    const float* __restrict__ X, const float* __restrict__ z,
    const float* __restrict__ gam, const float* __restrict__ bet,
    __nv_bfloat16* __restrict__ dst)
{
    extern __shared__ float s[];
    float* Ws = s;
    float* Xs = s + 4096;
    float* Os = s + 4096 + 64*392;
    const int t = threadIdx.x;
    const int bb = blockIdx.x;

    for (int idx = t; idx < 4096; idx += 256) Ws[idx] = g_W[idx];
    const float* Xb = X + (size_t)bb * 24576;
    for (int f = t; f < 6144; f += 256) {
        int row = f / 96, col = (f - row * 96) * 4;
        *(float4*)&Xs[row * 392 + col] = *(const float4*)(Xb + (size_t)row * 384 + col);
    }
    __syncthreads();

    const int wpair = t >> 3;
    const int cg = t & 7;
    const int w0 = wpair * 2;
    #pragma unroll
    for (int jb = 0; jb < 4; jb++) {
        float a0[12], a1[12];
        #pragma unroll
        for (int j = 0; j < 12; j++) { a0[j] = 0.f; a1[j] = 0.f; }
        #pragma unroll 4
        for (int m = 0; m < 64; m++) {
            float wv0 = Ws[m * 64 + w0];
            float wv1 = Ws[m * 64 + w0 + 1];
            const float* xr = &Xs[m * 392 + cg + 8 * (jb * 12)];
            #pragma unroll
            for (int j = 0; j < 12; j++) {
                float xv = xr[8 * j];
                a0[j] = fmaf(wv0, xv, a0[j]);
                a1[j] = fmaf(wv1, xv, a1[j]);
            }
        }
        #pragma unroll
        for (int j = 0; j < 12; j++) {
            int c = cg + 8 * (jb * 12 + j);
            Os[w0 * 392 + c]       = a0[j];
            Os[(w0 + 1) * 392 + c] = a1[j];
        }
    }
    __syncthreads();

    const int warp = t >> 5, lane = t & 31;
    float gv[12], bv[12];
    #pragma unroll
    for (int k = 0; k < 12; k++) { gv[k] = gam[lane + 32*k]; bv[k] = bet[lane + 32*k]; }
    for (int w = warp; w < 64; w += 8) {
        float vals[12], sum = 0.f;
        #pragma unroll
        for (int k = 0; k < 12; k++) { vals[k] = Os[w * 392 + lane + 32*k]; sum += vals[k]; }
        #pragma unroll
        for (int o = 16; o; o >>= 1) sum += __shfl_xor_sync(0xffffffffu, sum, o);
        float mu = sum * (1.0f / 384.0f);
        float q = 0.f;
        #pragma unroll
        for (int k = 0; k < 12; k++) { float d = vals[k] - mu; q = fmaf(d, d, q); }
        #pragma unroll
        for (int o = 16; o; o >>= 1) q += __shfl_xor_sync(0xffffffffu, q, o);
        float inv = rsqrtf(q * (1.0f / 384.0f) + 1e-5f);
        const size_t pixel = (size_t)bb * 64 + w;
        const float* zr = z + pixel * 384;
        __nv_bfloat16* dr = dst + pixel * 768;
        #pragma unroll
        for (int k = 0; k < 12; k++) {
            int c = lane + 32*k;
            float o = ((vals[k] - mu) * inv * gv[k] + bv[k]) * zr[c];
            __nv_bfloat16 hi, lo; split2(o, hi, lo);
            dr[c] = hi; dr[384 + c] = lo;
        }
    }
}

// ================================================================ launcher
#define TG_SMEM 81920

extern "C" void kernel_launch(void* const* d_in, const int* in_sizes, int n_in,
                              void* d_out, int out_size)
{
    const float* x     = (const float*)d_in[0];
    const float* freq  = (const float*)d_in[1];
    const float* dw_w  = (const float*)d_in[2];
    const float* dw_b  = (const float*)d_in[3];
    const float* lin_w = (const float*)d_in[4];
    const float* lin_b = (const float*)d_in[5];
    const float* tok_w = (const float*)d_in[6];
    const float* tok_b = (const float*)d_in[7];
    const float* ln_g  = (const float*)d_in[8];
    const float* ln_b  = (const float*)d_in[9];
    const float* out_w = (const float*)d_in[10];
    const float* out_b = (const float*)d_in[11];
    const float* cp    = (const float*)d_in[12];
    const float* ap    = (const float*)d_in[13];
    float* out = (float*)d_out;

    float *pxs, *pz, *ps, *pf1;
    __nv_bfloat16 *pxd, *pfq, *pf2, *pwl, *pwt, *pwo;
    cudaGetSymbolAddress((void**)&pxs, g_xs);
    cudaGetSymbolAddress((void**)&pz,  g_z);
    cudaGetSymbolAddress((void**)&ps,  g_s);
    cudaGetSymbolAddress((void**)&pf1, g_f1);
    cudaGetSymbolAddress((void**)&pxd, g_xd);
    cudaGetSymbolAddress((void**)&pfq, g_fq);
    cudaGetSymbolAddress((void**)&pf2, g_f2);
    cudaGetSymbolAddress((void**)&pwl, g_wl);
    cudaGetSymbolAddress((void**)&pwt, g_wt);
    cudaGetSymbolAddress((void**)&pwo, g_wo);

    cudaFuncSetAttribute((const void*)tgemm_k<0>, cudaFuncAttributeMaxDynamicSharedMemorySize, TG_SMEM);
    cudaFuncSetAttribute((const void*)tgemm_k<1>, cudaFuncAttributeMaxDynamicSharedMemorySize, TG_SMEM);
    cudaFuncSetAttribute((const void*)tgemm_k<2>, cudaFuncAttributeMaxDynamicSharedMemorySize, TG_SMEM);
    cudaFuncSetAttribute((const void*)(dctT_k<true,  false>), cudaFuncAttributeMaxDynamicSharedMemorySize, DT_SMEM);
    cudaFuncSetAttribute((const void*)(dctT_k<true,  true >), cudaFuncAttributeMaxDynamicSharedMemorySize, DT_SMEM);
    cudaFuncSetAttribute((const void*)(dctT_k<false, false>), cudaFuncAttributeMaxDynamicSharedMemorySize, DT_SMEM);
    cudaFuncSetAttribute((const void*)dct_ln_k,   cudaFuncAttributeMaxDynamicSharedMemorySize, DL_SMEM);

    build_w_k<<<16, 256>>>();
    split_k<<<(768*96 + 255)/256, 256>>>(lin_w, pwl, 768*96);
    split_k<<<(384*96 + 255)/256, 256>>>(tok_w, pwt, 384*96);
    split_k<<<(384*96 + 255)/256, 256>>>(out_w, pwo, 384*96);
    split_k<<<(65536*96 + 255)/256, 256>>>(freq, pfq, 65536*96);
    dwconv_k<<<1024, 384>>>(x, dw_w, dw_b, pxd);
    // xz = xd @ lin_w^T : xs + silu(z)
    tgemm_k<0><<<dim3(4, 512), 384, TG_SMEM>>>(pxd, pwl, lin_b, pxs, pz, nullptr, nullptr);
    // s = modulation(gelu(freq @ tok_w^T))
    tgemm_k<1><<<dim3(2, 512), 384, TG_SMEM>>>(pfq, pwt, tok_b, ps, nullptr, cp, ap);
    // DCT over h (tensorized)
    dctT_k<true,  false><<<dim3(192, 16),   256, DT_SMEM>>>(pf1, pxs, pf1, 24576);
    // DCT over w + modulate by s (tensorized)
    dctT_k<true,  true ><<<dim3(3,  1024),  256, DT_SMEM>>>((float*)pf2, pf1, ps, 384);
    // IDCT over n (tensorized)
    dctT_k<false, false><<<dim3(192, 16),   256, DT_SMEM>>>(pf1, (float*)pf2, pf1, 24576);
    // fused IDCT over m + LayerNorm + silu-gate -> split bf16
    dct_ln_k<<<1024, 256, DL_SMEM>>>(pf1, pz, ln_g, ln_b, pf2);
    // out = xo @ out_w^T + out_b
    tgemm_k<2><<<dim3(2, 512), 384, TG_SMEM>>>(pf2, pwo, out_b, out, nullptr, nullptr, nullptr);
}

// round 8
// speedup vs baseline: 1.1354x; 1.1354x over previous
#include <cuda_runtime.h>
#include <cuda_bf16.h>
#include <math.h>
#include <stdint.h>

#define KDIM 384
#define NEL 25165824   // 16*64*64*384

// fp32 buffers
static __device__ float g_xs[NEL];      // xs (pre-DCT)
static __device__ float g_z [NEL];      // silu(z)
static __device__ float g_s [NEL];      // modulation scalar
static __device__ float g_f1[NEL];
static __device__ float g_W[4096];      // 64x64 DCT-II matrix (fp32, for dct_ln)
// bf16 split W planes: [orient][plane hi/lo][64][72]
static __device__ __nv_bfloat16 g_Wsp[2][2][64][72];
// bf16 split buffers ([row][768]: hi 384 | lo 384)
static __device__ float g_xd[NEL];      // split conv output
static __device__ float g_fq[NEL];      // split freq_embed
static __device__ float g_f2[NEL];      // split LN output / fp32 scratch
static __device__ float g_wl[294912];   // split lin_w  (768 rows)
static __device__ float g_wt[147456];   // split tok_w  (384 rows)
static __device__ float g_wo[147456];   // split out_w  (384 rows)

// ================================================================ helpers
__device__ __forceinline__ uint32_t smem_u32(const void* p) {
    uint32_t a;
    asm("{ .reg .u64 t; cvta.to.shared.u64 t, %1; cvt.u32.u64 %0, t; }" : "=r"(a) : "l"(p));
    return a;
}
__device__ __forceinline__ void ldsm4(uint32_t (&r)[4], uint32_t addr) {
    asm volatile("ldmatrix.sync.aligned.m8n8.x4.shared.b16 {%0,%1,%2,%3}, [%4];"
                 : "=r"(r[0]), "=r"(r[1]), "=r"(r[2]), "=r"(r[3]) : "r"(addr));
}
__device__ __forceinline__ void ldsm4t(uint32_t (&r)[4], uint32_t addr) {
    asm volatile("ldmatrix.sync.aligned.m8n8.x4.trans.shared.b16 {%0,%1,%2,%3}, [%4];"
                 : "=r"(r[0]), "=r"(r[1]), "=r"(r[2]), "=r"(r[3]) : "r"(addr));
}
__device__ __forceinline__ void mma16816(float (&d)[4], const uint32_t (&a)[4],
                                         uint32_t b0, uint32_t b1) {
    asm volatile(
        "mma.sync.aligned.m16n8k16.row.col.f32.bf16.bf16.f32 "
        "{%0,%1,%2,%3}, {%4,%5,%6,%7}, {%8,%9}, {%0,%1,%2,%3};"
        : "+f"(d[0]), "+f"(d[1]), "+f"(d[2]), "+f"(d[3])
        : "r"(a[0]), "r"(a[1]), "r"(a[2]), "r"(a[3]), "r"(b0), "r"(b1));
}
__device__ __forceinline__ unsigned swz(unsigned off) {
    return off ^ ((off >> 3) & 0x70);
}
__device__ __forceinline__ void cp16(uint32_t dst, const void* src) {
    asm volatile("cp.async.cg.shared.global [%0], [%1], 16;" :: "r"(dst), "l"(src) : "memory");
}
__device__ __forceinline__ void cp_commit() {
    asm volatile("cp.async.commit_group;" ::: "memory");
}
template<int N> __device__ __forceinline__ void cp_wait() {
    asm volatile("cp.async.wait_group %0;" :: "n"(N) : "memory");
}
__device__ __forceinline__ void split2(float v, __nv_bfloat16& h, __nv_bfloat16& l) {
    h = __float2bfloat16(v);
    l = __float2bfloat16(v - __bfloat162float(h));
}

// ================================================================ build W
__global__ void build_w_k() {
    int i = blockIdx.x * 256 + threadIdx.x;
    int n = i >> 6, h = i & 63;
    float v = cosf((float)n * (((float)h + 0.5f) * (3.14159265358979323846f / 64.0f)))
            * 0.17677669529663687f;
    if (n == 0) v *= 0.70710678118654752f;
    g_W[i] = v;
    __nv_bfloat16 hi, lo; split2(v, hi, lo);
    g_Wsp[0][0][n][h] = hi;
    g_Wsp[0][1][n][h] = lo;
    g_Wsp[1][0][h][n] = hi;
    g_Wsp[1][1][h][n] = lo;
}

// ================================================================ split fp32 [rows][384] -> bf16 [rows][768]
__global__ void split_k(const float* __restrict__ src, __nv_bfloat16* __restrict__ dst, int n4) {
    int i = blockIdx.x * 256 + threadIdx.x;
    if (i >= n4) return;
    int row = i / 96;
    int col = (i - row * 96) * 4;
    float4 v = *(const float4*)(src + (size_t)row * 384 + col);
    __nv_bfloat16 h0,h1,h2,h3,l0,l1,l2,l3;
    split2(v.x,h0,l0); split2(v.y,h1,l1); split2(v.z,h2,l2); split2(v.w,h3,l3);
    __nv_bfloat16* d = dst + (size_t)row * 768 + col;
    d[0]=h0; d[1]=h1; d[2]=h2; d[3]=h3;
    d[384]=l0; d[385]=l1; d[386]=l2; d[387]=l3;
}

// ================================================================ depthwise conv 3x3, NCHW -> NHWC split bf16
__global__ void dwconv_k(const float* __restrict__ x, const float* __restrict__ w9,
                         const float* __restrict__ bias, __nv_bfloat16* __restrict__ outp)
{
    const int bh = blockIdx.x;
    const int c  = threadIdx.x;
    const int b  = bh >> 6, h = bh & 63;
    const float* xp = x + (size_t)(b * 384 + c) * 64 * 64;
    float k0 = w9[c*9+0], k1 = w9[c*9+1], k2 = w9[c*9+2];
    float k3 = w9[c*9+3], k4 = w9[c*9+4], k5 = w9[c*9+5];
    float k6 = w9[c*9+6], k7 = w9[c*9+7], k8 = w9[c*9+8];
    const float bi = bias[c];
    const float* r0 = (h > 0)  ? xp + (h-1)*64 : 0;
    const float* r1 = xp + h*64;
    const float* r2 = (h < 63) ? xp + (h+1)*64 : 0;
    float a0 = 0.f, a1 = 0.f, a2 = 0.f;
    float m0 = r0 ? r0[0] : 0.f;
    float m1 = r1[0];
    float m2 = r2 ? r2[0] : 0.f;
    __nv_bfloat16* ob = outp + (size_t)bh * 64 * 768 + c;
    #pragma unroll 4
    for (int w = 0; w < 64; w++) {
        float n0, n1, n2;
        if (w < 63) {
            n0 = r0 ? r0[w+1] : 0.f;
            n1 = r1[w+1];
            n2 = r2 ? r2[w+1] : 0.f;
        } else { n0 = n1 = n2 = 0.f; }
        float acc = bi
            + a0*k0 + m0*k1 + n0*k2
            + a1*k3 + m1*k4 + n1*k5
            + a2*k6 + m2*k7 + n2*k8;
        __nv_bfloat16 hi, lo; split2(acc, hi, lo);
        ob[(size_t)w * 768]       = hi;
        ob[(size_t)w * 768 + 384] = lo;
        a0 = m0; a1 = m1; a2 = m2;
        m0 = n0; m1 = n1; m2 = n2;
    }
}

// ================================================================ mma.sync split-bf16 GEMM (R5 structure, product-major mma order)
template<int MODE>
__global__ void __launch_bounds__(256) tgemm_k(
    const __nv_bfloat16* __restrict__ A, const __nv_bfloat16* __restrict__ Wt,
    const float* __restrict__ bias,
    float* __restrict__ o0, float* __restrict__ o1,
    const float* __restrict__ cp_, const float* __restrict__ ap)
{
    extern __shared__ char sm[];
    const int t    = threadIdx.x;
    const int wid  = t >> 5;
    const int lane = t & 31;
    const int m0 = blockIdx.y * 128;
    const int n0 = blockIdx.x * 128;
    const uint32_t smemBase = smem_u32(sm);

    const __nv_bfloat16* srcP[8];
    uint32_t dstS[8];
    #pragma unroll
    for (int r = 0; r < 8; r++) {
        int u = t + 256 * r;
        int mat = u >> 10;
        int v = u & 1023;
        int row = v >> 3;
        int s7 = v & 7;
        const __nv_bfloat16* base = mat ? (Wt + (size_t)(n0 + row) * 768)
                                        : (A  + (size_t)(m0 + row) * 768);
        int col = (s7 < 4) ? s7 * 8 : 384 + (s7 - 4) * 8;
        srcP[r] = base + col;
        dstS[r] = smemBase + mat * 32768 + swz((unsigned)(row * 128 + s7 * 16));
    }

    #pragma unroll
    for (int r = 0; r < 8; r++) cp16(dstS[r], srcP[r]);
    cp_commit();

    const int wm = wid & 3;
    const int wn = wid >> 2;
    float acc[2][8][4];
    #pragma unroll
    for (int i = 0; i < 2; i++)
        #pragma unroll
        for (int j = 0; j < 8; j++)
            #pragma unroll
            for (int q = 0; q < 4; q++) acc[i][j][q] = 0.f;

    const int lrow = lane & 15;
    const int lkc  = (lane >> 4) << 3;

    const int NCH = KDIM / 32;   // 12
    for (int ch = 0; ch < NCH; ch++) {
        const int buf = ch & 1;
        if (ch + 1 < NCH) {
            const int nb = (ch + 1) & 1;
            #pragma unroll
            for (int r = 0; r < 8; r++)
                cp16(dstS[r] + nb * 16384, srcP[r] + (ch + 1) * 32);
            cp_commit();
            cp_wait<1>();
        } else {
            cp_wait<0>();
        }
        __syncthreads();

        const uint32_t aS = smemBase + buf * 16384;
        const uint32_t bS = smemBase + 32768 + buf * 16384;
        #pragma unroll
        for (int ks = 0; ks < 2; ks++) {
            const unsigned kc2 = (unsigned)(ks * 16 + lkc) * 2;
            uint32_t ahi[2][4], alo[2][4];
            #pragma unroll
            for (int mt = 0; mt < 2; mt++) {
                unsigned off = (unsigned)(wm * 32 + mt * 16 + lrow) * 128 + kc2;
                ldsm4(ahi[mt], aS + swz(off));
                ldsm4(alo[mt], aS + swz(off + 64));
            }
            uint32_t bhi[4][4], blo[4][4];
            #pragma unroll
            for (int ng = 0; ng < 4; ng++) {
                unsigned off = (unsigned)(wn * 64 + ng * 16 + lrow) * 128 + kc2;
                ldsm4(bhi[ng], bS + swz(off));
                ldsm4(blo[ng], bS + swz(off + 64));
            }
            // product-major ordering: 16 independent mma per product,
            // RAW distance per accumulator = 16 instructions
            #pragma unroll
            for (int mt = 0; mt < 2; mt++)
                #pragma unroll
                for (int ng = 0; ng < 4; ng++) {
                    mma16816(acc[mt][2*ng],   ahi[mt], bhi[ng][0], bhi[ng][2]);
                    mma16816(acc[mt][2*ng+1], ahi[mt], bhi[ng][1], bhi[ng][3]);
                }
            #pragma unroll
            for (int mt = 0; mt < 2; mt++)
                #pragma unroll
                for (int ng = 0; ng < 4; ng++) {
                    mma16816(acc[mt][2*ng],   ahi[mt], blo[ng][0], blo[ng][2]);
                    mma16816(acc[mt][2*ng+1], ahi[mt], blo[ng][1], blo[ng][3]);
                }
            #pragma unroll
            for (int mt = 0; mt < 2; mt++)
                #pragma unroll
                for (int ng = 0; ng < 4; ng++) {
                    mma16816(acc[mt][2*ng],   alo[mt], bhi[ng][0], bhi[ng][2]);
                    mma16816(acc[mt][2*ng+1], alo[mt], bhi[ng][1], bhi[ng][3]);
                }
        }
        __syncthreads();
    }

    const int qr = lane >> 2;
    const int qc = lane & 3;
    const int mbw = m0 + wm * 32;
    const int nbw = n0 + wn * 64;

    float cc0 = 0.f, css = 0.f;
    if (MODE == 1) {
        cc0 = cp_[0];
        css = (1.0f + 0.5f * ap[0]) / (cc0 + 1e-8f);
    }

    #pragma unroll
    for (int mt = 0; mt < 2; mt++) {
        #pragma unroll
        for (int half = 0; half < 2; half++) {
            const int m = mbw + mt * 16 + qr + half * 8;
            float ee = 0.f;
            if (MODE == 1) {
                const float kp = 3.14159265358979323846f / 64.0f;
                int hh = (m >> 6) & 63, ww = m & 63;
                ee = kp * kp * (float)(hh * hh + ww * ww);
            }
            #pragma unroll
            for (int nt = 0; nt < 8; nt++) {
                const int n = nbw + nt * 8 + qc * 2;
                float v0 = acc[mt][nt][half * 2 + 0] + __ldg(bias + n);
                float v1 = acc[mt][nt][half * 2 + 1] + __ldg(bias + n + 1);
                if (MODE == 0) {
                    if (n0 >= 384) {
                        v0 *= 1.0f / (1.0f + __expf(-v0));
                        v1 *= 1.0f / (1.0f + __expf(-v1));
                        *(float2*)(o1 + (size_t)m * 384 + (n - 384)) = make_float2(v0, v1);
                    } else {
                        *(float2*)(o0 + (size_t)m * 384 + n) = make_float2(v0, v1);
                    }
                } else if (MODE == 1) {
                    float tg0 = 0.5f * v0 * (1.0f + erff(v0 * 0.70710678118654752f));
                    float tg1 = 0.5f * v1 * (1.0f + erff(v1 * 0.70710678118654752f));
                    float ct0 = cc0 * tg0, ct1 = cc0 * tg1;
                    float r0 = (__cosf(ct0) + __sinf(ct0) * css) * __expf(-ee * tg0);
                    float r1 = (__cosf(ct1) + __sinf(ct1) * css) * __expf(-ee * tg1);
                    *(float2*)(o0 + (size_t)m * 384 + n) = make_float2(r0, r1);
                } else {
                    *(float2*)(o0 + (size_t)m * 384 + n) = make_float2(v0, v1);
                }
            }
        }
    }
}

// ================================================================ tensorized 64-pt cosine transform (split bf16)
#define DT_SMEM (17408*2 + 9216*2)
template<bool FWD, bool MOD>
__global__ void __launch_bounds__(256) dctT_k(
    float* __restrict__ out, const float* __restrict__ X,
    const float* __restrict__ S, int ldRow)
{
    extern __shared__ char ds[];
    __nv_bfloat16* sXhi = (__nv_bfloat16*)ds;
    __nv_bfloat16* sXlo = (__nv_bfloat16*)(ds + 17408);
    __nv_bfloat16* sWp  = (__nv_bfloat16*)(ds + 34816);
    const int t = threadIdx.x;
    const int bb = blockIdx.y;
    const int j0 = blockIdx.x << 7;

    {
        const uint4* src = (const uint4*)&g_Wsp[FWD ? 0 : 1][0][0][0];
        uint4* dst = (uint4*)sWp;
        for (int u = t; u < 1152; u += 256) dst[u] = src[u];
    }
    const float* Xb = X + (size_t)bb * 64 * ldRow + j0;
    #pragma unroll
    for (int it = 0; it < 8; it++) {
        int idx = t + 256 * it;
        int row = idx >> 5, c4 = (idx & 31) << 2;
        float4 v = *(const float4*)(Xb + (size_t)row * ldRow + c4);
        __nv_bfloat16 h0,h1,h2,h3,l0,l1,l2,l3;
        split2(v.x,h0,l0); split2(v.y,h1,l1); split2(v.z,h2,l2); split2(v.w,h3,l3);
        unsigned hw0 = ((unsigned)__bfloat16_as_ushort(h1) << 16) | __bfloat16_as_ushort(h0);
        unsigned hw1 = ((unsigned)__bfloat16_as_ushort(h3) << 16) | __bfloat16_as_ushort(h2);
        unsigned lw0 = ((unsigned)__bfloat16_as_ushort(l1) << 16) | __bfloat16_as_ushort(l0);
        unsigned lw1 = ((unsigned)__bfloat16_as_ushort(l3) << 16) | __bfloat16_as_ushort(l2);
        *(uint2*)(sXhi + row * 136 + c4) = make_uint2(hw0, hw1);
        *(uint2*)(sXlo + row * 136 + c4) = make_uint2(lw0, lw1);
    }
    __syncthreads();

    const int wid = t >> 5, lane = t & 31;
    const int wm = wid & 1, wn = wid >> 1;
    const uint32_t xhiB = smem_u32(sXhi), xloB = smem_u32(sXlo);
    const uint32_t whiB = smem_u32(sWp),  wloB = whiB + 9216;

    float acc[2][4][4];
    #pragma unroll
    for (int i = 0; i < 2; i++)
        #pragma unroll
        for (int j = 0; j < 4; j++)
            #pragma unroll
            for (int q = 0; q < 4; q++) acc[i][j][q] = 0.f;

    const int lr = lane & 15, lh = lane >> 4;
    #pragma unroll
    for (int ks = 0; ks < 4; ks++) {
        uint32_t ahi[2][4], alo[2][4];
        #pragma unroll
        for (int mt = 0; mt < 2; mt++) {
            unsigned off = (unsigned)(wm * 32 + mt * 16 + lr) * 144 + (unsigned)(ks * 16 + lh * 8) * 2;
            ldsm4(ahi[mt], whiB + off);
            ldsm4(alo[mt], wloB + off);
        }
        uint32_t bhi[2][4], blo[2][4];
        #pragma unroll
        for (int ng = 0; ng < 2; ng++) {
            unsigned off = (unsigned)(ks * 16 + lr) * 272 + (unsigned)(wn * 32 + ng * 16 + lh * 8) * 2;
            ldsm4t(bhi[ng], xhiB + off);
            ldsm4t(blo[ng], xloB + off);
        }
        // product-major ordering (RAW distance 8)
        #pragma unroll
        for (int mt = 0; mt < 2; mt++)
            #pragma unroll
            for (int ng = 0; ng < 2; ng++) {
                mma16816(acc[mt][2*ng],   ahi[mt], bhi[ng][0], bhi[ng][1]);
                mma16816(acc[mt][2*ng+1], ahi[mt], bhi[ng][2], bhi[ng][3]);
            }
        #pragma unroll
        for (int mt = 0; mt < 2; mt++)
            #pragma unroll
            for (int ng = 0; ng < 2; ng++) {
                mma16816(acc[mt][2*ng],   ahi[mt], blo[ng][0], blo[ng][1]);
                mma16816(acc[mt][2*ng+1], ahi[mt], blo[ng][2], blo[ng][3]);
            }
        #pragma unroll
        for (int mt = 0; mt < 2; mt++)
            #pragma unroll
            for (int ng = 0; ng < 2; ng++) {
                mma16816(acc[mt][2*ng],   alo[mt], bhi[ng][0], bhi[ng][1]);
                mma16816(acc[mt][2*ng+1], alo[mt], bhi[ng][2], bhi[ng][3]);
            }
    }

    const int qr = lane >> 2, qc = lane & 3;
    float* ob = out + (size_t)bb * 64 * ldRow + j0;
    const float* sb = S + (size_t)bb * 64 * ldRow + j0;
    #pragma unroll
    for (int mt = 0; mt < 2; mt++)
        #pragma unroll
        for (int half = 0; half < 2; half++) {
            const int i = wm * 32 + mt * 16 + qr + half * 8;
            #pragma unroll
            for (int ng = 0; ng < 4; ng++) {
                const int j = wn * 32 + ng * 8 + qc * 2;
                float v0 = acc[mt][ng][half * 2 + 0];
                float v1 = acc[mt][ng][half * 2 + 1];
                if (MOD) {
                    float2 s2 = *(const float2*)(sb + (size_t)i * ldRow + j);
                    v0 *= s2.x; v1 *= s2.y;
                }
                *(float2*)(ob + (size_t)i * ldRow + j) = make_float2(v0, v1);
            }
        }
}

// ================================================================ fused IDCT(w) + LayerNorm + silu-gate + bf16 split
#define DL_SMEM ((4096 + 2*64*392) * 4)
__global__ void __launch_bounds__(256) dct_ln_k(
    const float* __restrict__ X, const float* __restrict__ z,
    const float* __restrict__ gam, const float* __restrict__ bet,
    __nv_bfloat16* __restrict__ dst)
{
    extern __shared__ float s[];
    float* Ws = s;
    float* Xs = s + 4096;
    float* Os = s + 4096 + 64*392;
    const int t = threadIdx.x;
    const int bb = blockIdx.x;

    for (int idx = t; idx < 4096; idx += 256) Ws[idx] = g_W[idx];
    const float* Xb = X + (size_t)bb * 24576;
    for (int f = t; f < 6144; f += 256) {
        int row = f / 96, col = (f - row * 96) * 4;
        *(float4*)&Xs[row * 392 + col] = *(const float4*)(Xb + (size_t)row * 384 + col);
    }
    __syncthreads();

    const int wpair = t >> 3;
    const int cg = t & 7;
    const int w0 = wpair * 2;
    #pragma unroll
    for (int jb = 0; jb < 4; jb++) {
        float a0[12], a1[12];
        #pragma unroll
        for (int j = 0; j < 12; j++) { a0[j] = 0.f; a1[j] = 0.f; }
        #pragma unroll 4
        for (int m = 0; m < 64; m++) {
            float wv0 = Ws[m * 64 + w0];
            float wv1 = Ws[m * 64 + w0 + 1];
            const float* xr = &Xs[m * 392 + cg + 8 * (jb * 12)];
            #pragma unroll
            for (int j = 0; j < 12; j++) {
                float xv = xr[8 * j];
                a0[j] = fmaf(wv0, xv, a0[j]);
                a1[j] = fmaf(wv1, xv, a1[j]);
            }
        }
        #pragma unroll
        for (int j = 0; j < 12; j++) {
            int c = cg + 8 * (jb * 12 + j);
            Os[w0 * 392 + c]       = a0[j];
            Os[(w0 + 1) * 392 + c] = a1[j];
        }
    }
    __syncthreads();

    const int warp = t >> 5, lane = t & 31;
    float gv[12], bv[12];
    #pragma unroll
    for (int k = 0; k < 12; k++) { gv[k] = gam[lane + 32*k]; bv[k] = bet[lane + 32*k]; }
    for (int w = warp; w < 64; w += 8) {
        float vals[12], sum = 0.f;
        #pragma unroll
        for (int k = 0; k < 12; k++) { vals[k] = Os[w * 392 + lane + 32*k]; sum += vals[k]; }
        #pragma unroll
        for (int o = 16; o; o >>= 1) sum += __shfl_xor_sync(0xffffffffu, sum, o);
        float mu = sum * (1.0f / 384.0f);
        float q = 0.f;
        #pragma unroll
        for (int k = 0; k < 12; k++) { float d = vals[k] - mu; q = fmaf(d, d, q); }
        #pragma unroll
        for (int o = 16; o; o >>= 1) q += __shfl_xor_sync(0xffffffffu, q, o);
        float inv = rsqrtf(q * (1.0f / 384.0f) + 1e-5f);
        const size_t pixel = (size_t)bb * 64 + w;
        const float* zr = z + pixel * 384;
        __nv_bfloat16* dr = dst + pixel * 768;
        #pragma unroll
        for (int k = 0; k < 12; k++) {
            int c = lane + 32*k;
            float o = ((vals[k] - mu) * inv * gv[k] + bv[k]) * zr[c];
            __nv_bfloat16 hi, lo; split2(o, hi, lo);
            dr[c] = hi; dr[384 + c] = lo;
        }
    }
}

// ================================================================ launcher
#define TG_SMEM 65536

extern "C" void kernel_launch(void* const* d_in, const int* in_sizes, int n_in,
                              void* d_out, int out_size)
{
    const float* x     = (const float*)d_in[0];
    const float* freq  = (const float*)d_in[1];
    const float* dw_w  = (const float*)d_in[2];
    const float* dw_b  = (const float*)d_in[3];
    const float* lin_w = (const float*)d_in[4];
    const float* lin_b = (const float*)d_in[5];
    const float* tok_w = (const float*)d_in[6];
    const float* tok_b = (const float*)d_in[7];
    const float* ln_g  = (const float*)d_in[8];
    const float* ln_b  = (const float*)d_in[9];
    const float* out_w = (const float*)d_in[10];
    const float* out_b = (const float*)d_in[11];
    const float* cp    = (const float*)d_in[12];
    const float* ap    = (const float*)d_in[13];
    float* out = (float*)d_out;

    float *pxs, *pz, *ps, *pf1;
    __nv_bfloat16 *pxd, *pfq, *pf2, *pwl, *pwt, *pwo;
    cudaGetSymbolAddress((void**)&pxs, g_xs);
    cudaGetSymbolAddress((void**)&pz,  g_z);
    cudaGetSymbolAddress((void**)&ps,  g_s);
    cudaGetSymbolAddress((void**)&pf1, g_f1);
    cudaGetSymbolAddress((void**)&pxd, g_xd);
    cudaGetSymbolAddress((void**)&pfq, g_fq);
    cudaGetSymbolAddress((void**)&pf2, g_f2);
    cudaGetSymbolAddress((void**)&pwl, g_wl);
    cudaGetSymbolAddress((void**)&pwt, g_wt);
    cudaGetSymbolAddress((void**)&pwo, g_wo);

    cudaFuncSetAttribute((const void*)tgemm_k<0>, cudaFuncAttributeMaxDynamicSharedMemorySize, TG_SMEM);
    cudaFuncSetAttribute((const void*)tgemm_k<1>, cudaFuncAttributeMaxDynamicSharedMemorySize, TG_SMEM);
    cudaFuncSetAttribute((const void*)tgemm_k<2>, cudaFuncAttributeMaxDynamicSharedMemorySize, TG_SMEM);
    cudaFuncSetAttribute((const void*)(dctT_k<true,  false>), cudaFuncAttributeMaxDynamicSharedMemorySize, DT_SMEM);
    cudaFuncSetAttribute((const void*)(dctT_k<true,  true >), cudaFuncAttributeMaxDynamicSharedMemorySize, DT_SMEM);
    cudaFuncSetAttribute((const void*)(dctT_k<false, false>), cudaFuncAttributeMaxDynamicSharedMemorySize, DT_SMEM);
    cudaFuncSetAttribute((const void*)dct_ln_k,   cudaFuncAttributeMaxDynamicSharedMemorySize, DL_SMEM);

    build_w_k<<<16, 256>>>();
    split_k<<<(768*96 + 255)/256, 256>>>(lin_w, pwl, 768*96);
    split_k<<<(384*96 + 255)/256, 256>>>(tok_w, pwt, 384*96);
    split_k<<<(384*96 + 255)/256, 256>>>(out_w, pwo, 384*96);
    split_k<<<(65536*96 + 255)/256, 256>>>(freq, pfq, 65536*96);
    dwconv_k<<<1024, 384>>>(x, dw_w, dw_b, pxd);
    // xz = xd @ lin_w^T : xs + silu(z)
    tgemm_k<0><<<dim3(6, 512), 256, TG_SMEM>>>(pxd, pwl, lin_b, pxs, pz, nullptr, nullptr);
    // s = modulation(gelu(freq @ tok_w^T))
    tgemm_k<1><<<dim3(3, 512), 256, TG_SMEM>>>(pfq, pwt, tok_b, ps, nullptr, cp, ap);
    // DCT over h (tensorized)
    dctT_k<true,  false><<<dim3(192, 16),   256, DT_SMEM>>>(pf1, pxs, pf1, 24576);
    // DCT over w + modulate by s (tensorized)
    dctT_k<true,  true ><<<dim3(3,  1024),  256, DT_SMEM>>>((float*)pf2, pf1, ps, 384);
    // IDCT over n (tensorized)
    dctT_k<false, false><<<dim3(192, 16),   256, DT_SMEM>>>(pf1, (float*)pf2, pf1, 24576);
    // fused IDCT over m + LayerNorm + silu-gate -> split bf16
    dct_ln_k<<<1024, 256, DL_SMEM>>>(pf1, pz, ln_g, ln_b, pf2);
    // out = xo @ out_w^T + out_b
    tgemm_k<2><<<dim3(3, 512), 256, TG_SMEM>>>(pf2, pwo, out_b, out, nullptr, nullptr, nullptr);
}

// round 9
// speedup vs baseline: 1.1435x; 1.0071x over previous
#include <cuda_runtime.h>
#include <cuda_bf16.h>
#include <math.h>
#include <stdint.h>

#define KDIM 384
#define NEL 25165824   // 16*64*64*384

// fp32 buffers
static __device__ float g_xs[NEL];      // xs (pre-DCT)
static __device__ float g_z [NEL];      // silu(z)
static __device__ float g_s [NEL];      // modulation scalar
static __device__ float g_f1[NEL];
static __device__ float g_W[4096];      // 64x64 DCT-II matrix (fp32, for dct_ln)
// bf16 split W planes: [orient][plane hi/lo][64][72]
static __device__ __nv_bfloat16 g_Wsp[2][2][64][72];
// bf16 split buffers ([row][768]: hi 384 | lo 384)
static __device__ float g_xd[NEL];      // split conv output
static __device__ float g_fq[NEL];      // split freq_embed
static __device__ float g_f2[NEL];      // split LN output / fp32 scratch
static __device__ float g_wl[294912];   // split lin_w  (768 rows)
static __device__ float g_wt[147456];   // split tok_w  (384 rows)
static __device__ float g_wo[147456];   // split out_w  (384 rows)

// ================================================================ helpers
__device__ __forceinline__ uint32_t smem_u32(const void* p) {
    uint32_t a;
    asm("{ .reg .u64 t; cvta.to.shared.u64 t, %1; cvt.u32.u64 %0, t; }" : "=r"(a) : "l"(p));
    return a;
}
__device__ __forceinline__ void ldsm4(uint32_t (&r)[4], uint32_t addr) {
    asm volatile("ldmatrix.sync.aligned.m8n8.x4.shared.b16 {%0,%1,%2,%3}, [%4];"
                 : "=r"(r[0]), "=r"(r[1]), "=r"(r[2]), "=r"(r[3]) : "r"(addr));
}
__device__ __forceinline__ void ldsm4t(uint32_t (&r)[4], uint32_t addr) {
    asm volatile("ldmatrix.sync.aligned.m8n8.x4.trans.shared.b16 {%0,%1,%2,%3}, [%4];"
                 : "=r"(r[0]), "=r"(r[1]), "=r"(r[2]), "=r"(r[3]) : "r"(addr));
}
__device__ __forceinline__ void mma16816(float (&d)[4], const uint32_t (&a)[4],
                                         uint32_t b0, uint32_t b1) {
    asm volatile(
        "mma.sync.aligned.m16n8k16.row.col.f32.bf16.bf16.f32 "
        "{%0,%1,%2,%3}, {%4,%5,%6,%7}, {%8,%9}, {%0,%1,%2,%3};"
        : "+f"(d[0]), "+f"(d[1]), "+f"(d[2]), "+f"(d[3])
        : "r"(a[0]), "r"(a[1]), "r"(a[2]), "r"(a[3]), "r"(b0), "r"(b1));
}
__device__ __forceinline__ unsigned swz(unsigned off) {
    return off ^ ((off >> 3) & 0x70);
}
__device__ __forceinline__ void cp16(uint32_t dst, const void* src) {
    asm volatile("cp.async.cg.shared.global [%0], [%1], 16;" :: "r"(dst), "l"(src) : "memory");
}
__device__ __forceinline__ void cp_commit() {
    asm volatile("cp.async.commit_group;" ::: "memory");
}
template<int N> __device__ __forceinline__ void cp_wait() {
    asm volatile("cp.async.wait_group %0;" :: "n"(N) : "memory");
}
__device__ __forceinline__ void split2(float v, __nv_bfloat16& h, __nv_bfloat16& l) {
    h = __float2bfloat16(v);
    l = __float2bfloat16(v - __bfloat162float(h));
}

// ================================================================ build W
__global__ void build_w_k() {
    int i = blockIdx.x * 256 + threadIdx.x;
    int n = i >> 6, h = i & 63;
    float v = cosf((float)n * (((float)h + 0.5f) * (3.14159265358979323846f / 64.0f)))
            * 0.17677669529663687f;
    if (n == 0) v *= 0.70710678118654752f;
    g_W[i] = v;
    __nv_bfloat16 hi, lo; split2(v, hi, lo);
    g_Wsp[0][0][n][h] = hi;
    g_Wsp[0][1][n][h] = lo;
    g_Wsp[1][0][h][n] = hi;
    g_Wsp[1][1][h][n] = lo;
}

// ================================================================ split fp32 [rows][384] -> bf16 [rows][768]
__global__ void split_k(const float* __restrict__ src, __nv_bfloat16* __restrict__ dst, int n4) {
    int i = blockIdx.x * 256 + threadIdx.x;
    if (i >= n4) return;
    int row = i / 96;
    int col = (i - row * 96) * 4;
    float4 v = *(const float4*)(src + (size_t)row * 384 + col);
    __nv_bfloat16 h0,h1,h2,h3,l0,l1,l2,l3;
    split2(v.x,h0,l0); split2(v.y,h1,l1); split2(v.z,h2,l2); split2(v.w,h3,l3);
    __nv_bfloat16* d = dst + (size_t)row * 768 + col;
    d[0]=h0; d[1]=h1; d[2]=h2; d[3]=h3;
    d[384]=l0; d[385]=l1; d[386]=l2; d[387]=l3;
}

// ================================================================ depthwise conv 3x3, NCHW -> NHWC split bf16
__global__ void dwconv_k(const float* __restrict__ x, const float* __restrict__ w9,
                         const float* __restrict__ bias, __nv_bfloat16* __restrict__ outp)
{
    const int bh = blockIdx.x;
    const int c  = threadIdx.x;
    const int b  = bh >> 6, h = bh & 63;
    const float* xp = x + (size_t)(b * 384 + c) * 64 * 64;
    float k0 = w9[c*9+0], k1 = w9[c*9+1], k2 = w9[c*9+2];
    float k3 = w9[c*9+3], k4 = w9[c*9+4], k5 = w9[c*9+5];
    float k6 = w9[c*9+6], k7 = w9[c*9+7], k8 = w9[c*9+8];
    const float bi = bias[c];
    const float* r0 = (h > 0)  ? xp + (h-1)*64 : 0;
    const float* r1 = xp + h*64;
    const float* r2 = (h < 63) ? xp + (h+1)*64 : 0;
    float a0 = 0.f, a1 = 0.f, a2 = 0.f;
    float m0 = r0 ? r0[0] : 0.f;
    float m1 = r1[0];
    float m2 = r2 ? r2[0] : 0.f;
    __nv_bfloat16* ob = outp + (size_t)bh * 64 * 768 + c;
    #pragma unroll 4
    for (int w = 0; w < 64; w++) {
        float n0, n1, n2;
        if (w < 63) {
            n0 = r0 ? r0[w+1] : 0.f;
            n1 = r1[w+1];
            n2 = r2 ? r2[w+1] : 0.f;
        } else { n0 = n1 = n2 = 0.f; }
        float acc = bi
            + a0*k0 + m0*k1 + n0*k2
            + a1*k3 + m1*k4 + n1*k5
            + a2*k6 + m2*k7 + n2*k8;
        __nv_bfloat16 hi, lo; split2(acc, hi, lo);
        ob[(size_t)w * 768]       = hi;
        ob[(size_t)w * 768 + 384] = lo;
        a0 = m0; a1 = m1; a2 = m2;
        m0 = n0; m1 = n1; m2 = n2;
    }
}

// ================================================================ mma.sync split-bf16 GEMM
// 128x128 tile, 512 threads (16 warps: 4 m-slices x 4 n-slices, warp tile 32x32)
// smem layout and pipeline identical to R5; only warp parallelism changed.
template<int MODE>
__global__ void __launch_bounds__(512) tgemm_k(
    const __nv_bfloat16* __restrict__ A, const __nv_bfloat16* __restrict__ Wt,
    const float* __restrict__ bias,
    float* __restrict__ o0, float* __restrict__ o1,
    const float* __restrict__ cp_, const float* __restrict__ ap)
{
    extern __shared__ char sm[];
    const int t    = threadIdx.x;
    const int wid  = t >> 5;
    const int lane = t & 31;
    const int m0 = blockIdx.y * 128;
    const int n0 = blockIdx.x * 128;
    const uint32_t smemBase = smem_u32(sm);

    // ---- loader: 2048 16B units/chunk, 4 per thread
    const __nv_bfloat16* srcP[4];
    uint32_t dstS[4];
    #pragma unroll
    for (int r = 0; r < 4; r++) {
        int u = t + 512 * r;
        int mat = u >> 10;
        int v = u & 1023;
        int row = v >> 3;
        int s7 = v & 7;
        const __nv_bfloat16* base = mat ? (Wt + (size_t)(n0 + row) * 768)
                                        : (A  + (size_t)(m0 + row) * 768);
        int col = (s7 < 4) ? s7 * 8 : 384 + (s7 - 4) * 8;
        srcP[r] = base + col;
        dstS[r] = smemBase + mat * 32768 + swz((unsigned)(row * 128 + s7 * 16));
    }

    #pragma unroll
    for (int r = 0; r < 4; r++) cp16(dstS[r], srcP[r]);
    cp_commit();

    const int wm = wid & 3;        // 32-row slice
    const int wn = wid >> 2;       // 32-col slice
    float acc[2][4][4];
    #pragma unroll
    for (int i = 0; i < 2; i++)
        #pragma unroll
        for (int j = 0; j < 4; j++)
            #pragma unroll
            for (int q = 0; q < 4; q++) acc[i][j][q] = 0.f;

    const int lrow = lane & 15;
    const int lkc  = (lane >> 4) << 3;

    const int NCH = KDIM / 32;   // 12
    for (int ch = 0; ch < NCH; ch++) {
        const int buf = ch & 1;
        if (ch + 1 < NCH) {
            const int nb = (ch + 1) & 1;
            #pragma unroll
            for (int r = 0; r < 4; r++)
                cp16(dstS[r] + nb * 16384, srcP[r] + (ch + 1) * 32);
            cp_commit();
            cp_wait<1>();
        } else {
            cp_wait<0>();
        }
        __syncthreads();

        const uint32_t aS = smemBase + buf * 16384;
        const uint32_t bS = smemBase + 32768 + buf * 16384;
        #pragma unroll
        for (int ks = 0; ks < 2; ks++) {
            const unsigned kc2 = (unsigned)(ks * 16 + lkc) * 2;
            uint32_t ahi[2][4], alo[2][4];
            #pragma unroll
            for (int mt = 0; mt < 2; mt++) {
                unsigned off = (unsigned)(wm * 32 + mt * 16 + lrow) * 128 + kc2;
                ldsm4(ahi[mt], aS + swz(off));
                ldsm4(alo[mt], aS + swz(off + 64));
            }
            uint32_t bhi[2][4], blo[2][4];
            #pragma unroll
            for (int ng = 0; ng < 2; ng++) {
                unsigned off = (unsigned)(wn * 32 + ng * 16 + lrow) * 128 + kc2;
                ldsm4(bhi[ng], bS + swz(off));
                ldsm4(blo[ng], bS + swz(off + 64));
            }
            #pragma unroll
            for (int mt = 0; mt < 2; mt++)
                #pragma unroll
                for (int ng = 0; ng < 2; ng++) {
                    mma16816(acc[mt][2*ng],   ahi[mt], bhi[ng][0], bhi[ng][2]);
                    mma16816(acc[mt][2*ng+1], ahi[mt], bhi[ng][1], bhi[ng][3]);
                }
            #pragma unroll
            for (int mt = 0; mt < 2; mt++)
                #pragma unroll
                for (int ng = 0; ng < 2; ng++) {
                    mma16816(acc[mt][2*ng],   ahi[mt], blo[ng][0], blo[ng][2]);
                    mma16816(acc[mt][2*ng+1], ahi[mt], blo[ng][1], blo[ng][3]);
                }
            #pragma unroll
            for (int mt = 0; mt < 2; mt++)
                #pragma unroll
                for (int ng = 0; ng < 2; ng++) {
                    mma16816(acc[mt][2*ng],   alo[mt], bhi[ng][0], bhi[ng][2]);
                    mma16816(acc[mt][2*ng+1], alo[mt], bhi[ng][1], bhi[ng][3]);
                }
        }
        __syncthreads();
    }

    // ---- epilogue: warp tile 32x32
    const int qr = lane >> 2;
    const int qc = lane & 3;
    const int mbw = m0 + wm * 32;
    const int nbw = n0 + wn * 32;

    float cc0 = 0.f, css = 0.f;
    if (MODE == 1) {
        cc0 = cp_[0];
        css = (1.0f + 0.5f * ap[0]) / (cc0 + 1e-8f);
    }

    #pragma unroll
    for (int mt = 0; mt < 2; mt++) {
        #pragma unroll
        for (int half = 0; half < 2; half++) {
            const int m = mbw + mt * 16 + qr + half * 8;
            float ee = 0.f;
            if (MODE == 1) {
                const float kp = 3.14159265358979323846f / 64.0f;
                int hh = (m >> 6) & 63, ww = m & 63;
                ee = kp * kp * (float)(hh * hh + ww * ww);
            }
            #pragma unroll
            for (int nt = 0; nt < 4; nt++) {
                const int n = nbw + nt * 8 + qc * 2;
                float v0 = acc[mt][nt][half * 2 + 0] + __ldg(bias + n);
                float v1 = acc[mt][nt][half * 2 + 1] + __ldg(bias + n + 1);
                if (MODE == 0) {
                    if (n0 >= 384) {
                        v0 *= 1.0f / (1.0f + __expf(-v0));
                        v1 *= 1.0f / (1.0f + __expf(-v1));
                        *(float2*)(o1 + (size_t)m * 384 + (n - 384)) = make_float2(v0, v1);
                    } else {
                        *(float2*)(o0 + (size_t)m * 384 + n) = make_float2(v0, v1);
                    }
                } else if (MODE == 1) {
                    float tg0 = 0.5f * v0 * (1.0f + erff(v0 * 0.70710678118654752f));
                    float tg1 = 0.5f * v1 * (1.0f + erff(v1 * 0.70710678118654752f));
                    float ct0 = cc0 * tg0, ct1 = cc0 * tg1;
                    float r0 = (__cosf(ct0) + __sinf(ct0) * css) * __expf(-ee * tg0);
                    float r1 = (__cosf(ct1) + __sinf(ct1) * css) * __expf(-ee * tg1);
                    *(float2*)(o0 + (size_t)m * 384 + n) = make_float2(r0, r1);
                } else {
                    *(float2*)(o0 + (size_t)m * 384 + n) = make_float2(v0, v1);
                }
            }
        }
    }
}

// ================================================================ tensorized 64-pt cosine transform (split bf16)
#define DT_SMEM (17408*2 + 9216*2)
template<bool FWD, bool MOD>
__global__ void __launch_bounds__(256) dctT_k(
    float* __restrict__ out, const float* __restrict__ X,
    const float* __restrict__ S, int ldRow)
{
    extern __shared__ char ds[];
    __nv_bfloat16* sXhi = (__nv_bfloat16*)ds;
    __nv_bfloat16* sXlo = (__nv_bfloat16*)(ds + 17408);
    __nv_bfloat16* sWp  = (__nv_bfloat16*)(ds + 34816);
    const int t = threadIdx.x;
    const int bb = blockIdx.y;
    const int j0 = blockIdx.x << 7;

    {
        const uint4* src = (const uint4*)&g_Wsp[FWD ? 0 : 1][0][0][0];
        uint4* dst = (uint4*)sWp;
        for (int u = t; u < 1152; u += 256) dst[u] = src[u];
    }
    const float* Xb = X + (size_t)bb * 64 * ldRow + j0;
    #pragma unroll
    for (int it = 0; it < 8; it++) {
        int idx = t + 256 * it;
        int row = idx >> 5, c4 = (idx & 31) << 2;
        float4 v = *(const float4*)(Xb + (size_t)row * ldRow + c4);
        __nv_bfloat16 h0,h1,h2,h3,l0,l1,l2,l3;
        split2(v.x,h0,l0); split2(v.y,h1,l1); split2(v.z,h2,l2); split2(v.w,h3,l3);
        unsigned hw0 = ((unsigned)__bfloat16_as_ushort(h1) << 16) | __bfloat16_as_ushort(h0);
        unsigned hw1 = ((unsigned)__bfloat16_as_ushort(h3) << 16) | __bfloat16_as_ushort(h2);
        unsigned lw0 = ((unsigned)__bfloat16_as_ushort(l1) << 16) | __bfloat16_as_ushort(l0);
        unsigned lw1 = ((unsigned)__bfloat16_as_ushort(l3) << 16) | __bfloat16_as_ushort(l2);
        *(uint2*)(sXhi + row * 136 + c4) = make_uint2(hw0, hw1);
        *(uint2*)(sXlo + row * 136 + c4) = make_uint2(lw0, lw1);
    }
    __syncthreads();

    const int wid = t >> 5, lane = t & 31;
    const int wm = wid & 1, wn = wid >> 1;
    const uint32_t xhiB = smem_u32(sXhi), xloB = smem_u32(sXlo);
    const uint32_t whiB = smem_u32(sWp),  wloB = whiB + 9216;

    float acc[2][4][4];
    #pragma unroll
    for (int i = 0; i < 2; i++)
        #pragma unroll
        for (int j = 0; j < 4; j++)
            #pragma unroll
            for (int q = 0; q < 4; q++) acc[i][j][q] = 0.f;

    const int lr = lane & 15, lh = lane >> 4;
    #pragma unroll
    for (int ks = 0; ks < 4; ks++) {
        uint32_t ahi[2][4], alo[2][4];
        #pragma unroll
        for (int mt = 0; mt < 2; mt++) {
            unsigned off = (unsigned)(wm * 32 + mt * 16 + lr) * 144 + (unsigned)(ks * 16 + lh * 8) * 2;
            ldsm4(ahi[mt], whiB + off);
            ldsm4(alo[mt], wloB + off);
        }
        uint32_t bhi[2][4], blo[2][4];
        #pragma unroll
        for (int ng = 0; ng < 2; ng++) {
            unsigned off = (unsigned)(ks * 16 + lr) * 272 + (unsigned)(wn * 32 + ng * 16 + lh * 8) * 2;
            ldsm4t(bhi[ng], xhiB + off);
            ldsm4t(blo[ng], xloB + off);
        }
        #pragma unroll
        for (int mt = 0; mt < 2; mt++)
            #pragma unroll
            for (int ng = 0; ng < 2; ng++) {
                mma16816(acc[mt][2*ng],   ahi[mt], bhi[ng][0], bhi[ng][1]);
                mma16816(acc[mt][2*ng+1], ahi[mt], bhi[ng][2], bhi[ng][3]);
            }
        #pragma unroll
        for (int mt = 0; mt < 2; mt++)
            #pragma unroll
            for (int ng = 0; ng < 2; ng++) {
                mma16816(acc[mt][2*ng],   ahi[mt], blo[ng][0], blo[ng][1]);
                mma16816(acc[mt][2*ng+1], ahi[mt], blo[ng][2], blo[ng][3]);
            }
        #pragma unroll
        for (int mt = 0; mt < 2; mt++)
            #pragma unroll
            for (int ng = 0; ng < 2; ng++) {
                mma16816(acc[mt][2*ng],   alo[mt], bhi[ng][0], bhi[ng][1]);
                mma16816(acc[mt][2*ng+1], alo[mt], bhi[ng][2], bhi[ng][3]);
            }
    }

    const int qr = lane >> 2, qc = lane & 3;
    float* ob = out + (size_t)bb * 64 * ldRow + j0;
    const float* sb = S + (size_t)bb * 64 * ldRow + j0;
    #pragma unroll
    for (int mt = 0; mt < 2; mt++)
        #pragma unroll
        for (int half = 0; half < 2; half++) {
            const int i = wm * 32 + mt * 16 + qr + half * 8;
            #pragma unroll
            for (int ng = 0; ng < 4; ng++) {
                const int j = wn * 32 + ng * 8 + qc * 2;
                float v0 = acc[mt][ng][half * 2 + 0];
                float v1 = acc[mt][ng][half * 2 + 1];
                if (MOD) {
                    float2 s2 = *(const float2*)(sb + (size_t)i * ldRow + j);
                    v0 *= s2.x; v1 *= s2.y;
                }
                *(float2*)(ob + (size_t)i * ldRow + j) = make_float2(v0, v1);
            }
        }
}

// ================================================================ fused IDCT(w) + LayerNorm + silu-gate + bf16 split
#define DL_SMEM ((4096 + 2*64*392) * 4)
__global__ void __launch_bounds__(256) dct_ln_k(
    const float* __restrict__ X, const float* __restrict__ z,
    const float* __restrict__ gam, const float* __restrict__ bet,
    __nv_bfloat16* __restrict__ dst)
{
    extern __shared__ float s[];
    float* Ws = s;
    float* Xs = s + 4096;
    float* Os = s + 4096 + 64*392;
    const int t = threadIdx.x;
    const int bb = blockIdx.x;

    for (int idx = t; idx < 4096; idx += 256) Ws[idx] = g_W[idx];
    const float* Xb = X + (size_t)bb * 24576;
    for (int f = t; f < 6144; f += 256) {
        int row = f / 96, col = (f - row * 96) * 4;
        *(float4*)&Xs[row * 392 + col] = *(const float4*)(Xb + (size_t)row * 384 + col);
    }
    __syncthreads();

    const int wpair = t >> 3;
    const int cg = t & 7;
    const int w0 = wpair * 2;
    #pragma unroll
    for (int jb = 0; jb < 4; jb++) {
        float a0[12], a1[12];
        #pragma unroll
        for (int j = 0; j < 12; j++) { a0[j] = 0.f; a1[j] = 0.f; }
        #pragma unroll 4
        for (int m = 0; m < 64; m++) {
            float wv0 = Ws[m * 64 + w0];
            float wv1 = Ws[m * 64 + w0 + 1];
            const float* xr = &Xs[m * 392 + cg + 8 * (jb * 12)];
            #pragma unroll
            for (int j = 0; j < 12; j++) {
                float xv = xr[8 * j];
                a0[j] = fmaf(wv0, xv, a0[j]);
                a1[j] = fmaf(wv1, xv, a1[j]);
            }
        }
        #pragma unroll
        for (int j = 0; j < 12; j++) {
            int c = cg + 8 * (jb * 12 + j);
            Os[w0 * 392 + c]       = a0[j];
            Os[(w0 + 1) * 392 + c] = a1[j];
        }
    }
    __syncthreads();

    const int warp = t >> 5, lane = t & 31;
    float gv[12], bv[12];
    #pragma unroll
    for (int k = 0; k < 12; k++) { gv[k] = gam[lane + 32*k]; bv[k] = bet[lane + 32*k]; }
    for (int w = warp; w < 64; w += 8) {
        float vals[12], sum = 0.f;
        #pragma unroll
        for (int k = 0; k < 12; k++) { vals[k] = Os[w * 392 + lane + 32*k]; sum += vals[k]; }
        #pragma unroll
        for (int o = 16; o; o >>= 1) sum += __shfl_xor_sync(0xffffffffu, sum, o);
        float mu = sum * (1.0f / 384.0f);
        float q = 0.f;
        #pragma unroll
        for (int k = 0; k < 12; k++) { float d = vals[k] - mu; q = fmaf(d, d, q); }
        #pragma unroll
        for (int o = 16; o; o >>= 1) q += __shfl_xor_sync(0xffffffffu, q, o);
        float inv = rsqrtf(q * (1.0f / 384.0f) + 1e-5f);
        const size_t pixel = (size_t)bb * 64 + w;
        const float* zr = z + pixel * 384;
        __nv_bfloat16* dr = dst + pixel * 768;
        #pragma unroll
        for (int k = 0; k < 12; k++) {
            int c = lane + 32*k;
            float o = ((vals[k] - mu) * inv * gv[k] + bv[k]) * zr[c];
            __nv_bfloat16 hi, lo; split2(o, hi, lo);
            dr[c] = hi; dr[384 + c] = lo;
        }
    }
}

// ================================================================ launcher
#define TG_SMEM 65536

extern "C" void kernel_launch(void* const* d_in, const int* in_sizes, int n_in,
                              void* d_out, int out_size)
{
    const float* x     = (const float*)d_in[0];
    const float* freq  = (const float*)d_in[1];
    const float* dw_w  = (const float*)d_in[2];
    const float* dw_b  = (const float*)d_in[3];
    const float* lin_w = (const float*)d_in[4];
    const float* lin_b = (const float*)d_in[5];
    const float* tok_w = (const float*)d_in[6];
    const float* tok_b = (const float*)d_in[7];
    const float* ln_g  = (const float*)d_in[8];
    const float* ln_b  = (const float*)d_in[9];
    const float* out_w = (const float*)d_in[10];
    const float* out_b = (const float*)d_in[11];
    const float* cp    = (const float*)d_in[12];
    const float* ap    = (const float*)d_in[13];
    float* out = (float*)d_out;

    float *pxs, *pz, *ps, *pf1;
    __nv_bfloat16 *pxd, *pfq, *pf2, *pwl, *pwt, *pwo;
    cudaGetSymbolAddress((void**)&pxs, g_xs);
    cudaGetSymbolAddress((void**)&pz,  g_z);
    cudaGetSymbolAddress((void**)&ps,  g_s);
    cudaGetSymbolAddress((void**)&pf1, g_f1);
    cudaGetSymbolAddress((void**)&pxd, g_xd);
    cudaGetSymbolAddress((void**)&pfq, g_fq);
    cudaGetSymbolAddress((void**)&pf2, g_f2);
    cudaGetSymbolAddress((void**)&pwl, g_wl);
    cudaGetSymbolAddress((void**)&pwt, g_wt);
    cudaGetSymbolAddress((void**)&pwo, g_wo);

    cudaFuncSetAttribute((const void*)tgemm_k<0>, cudaFuncAttributeMaxDynamicSharedMemorySize, TG_SMEM);
    cudaFuncSetAttribute((const void*)tgemm_k<1>, cudaFuncAttributeMaxDynamicSharedMemorySize, TG_SMEM);
    cudaFuncSetAttribute((const void*)tgemm_k<2>, cudaFuncAttributeMaxDynamicSharedMemorySize, TG_SMEM);
    cudaFuncSetAttribute((const void*)(dctT_k<true,  false>), cudaFuncAttributeMaxDynamicSharedMemorySize, DT_SMEM);
    cudaFuncSetAttribute((const void*)(dctT_k<true,  true >), cudaFuncAttributeMaxDynamicSharedMemorySize, DT_SMEM);
    cudaFuncSetAttribute((const void*)(dctT_k<false, false>), cudaFuncAttributeMaxDynamicSharedMemorySize, DT_SMEM);
    cudaFuncSetAttribute((const void*)dct_ln_k,   cudaFuncAttributeMaxDynamicSharedMemorySize, DL_SMEM);

    build_w_k<<<16, 256>>>();
    split_k<<<(768*96 + 255)/256, 256>>>(lin_w, pwl, 768*96);
    split_k<<<(384*96 + 255)/256, 256>>>(tok_w, pwt, 384*96);
    split_k<<<(384*96 + 255)/256, 256>>>(out_w, pwo, 384*96);
    split_k<<<(65536*96 + 255)/256, 256>>>(freq, pfq, 65536*96);
    dwconv_k<<<1024, 384>>>(x, dw_w, dw_b, pxd);
    // xz = xd @ lin_w^T : xs + silu(z)
    tgemm_k<0><<<dim3(6, 512), 512, TG_SMEM>>>(pxd, pwl, lin_b, pxs, pz, nullptr, nullptr);
    // s = modulation(gelu(freq @ tok_w^T))
    tgemm_k<1><<<dim3(3, 512), 512, TG_SMEM>>>(pfq, pwt, tok_b, ps, nullptr, cp, ap);
    // DCT over h (tensorized)
    dctT_k<true,  false><<<dim3(192, 16),   256, DT_SMEM>>>(pf1, pxs, pf1, 24576);
    // DCT over w + modulate by s (tensorized)
    dctT_k<true,  true ><<<dim3(3,  1024),  256, DT_SMEM>>>((float*)pf2, pf1, ps, 384);
    // IDCT over n (tensorized)
    dctT_k<false, false><<<dim3(192, 16),   256, DT_SMEM>>>(pf1, (float*)pf2, pf1, 24576);
    // fused IDCT over m + LayerNorm + silu-gate -> split bf16
    dct_ln_k<<<1024, 256, DL_SMEM>>>(pf1, pz, ln_g, ln_b, pf2);
    // out = xo @ out_w^T + out_b
    tgemm_k<2><<<dim3(3, 512), 512, TG_SMEM>>>(pf2, pwo, out_b, out, nullptr, nullptr, nullptr);
}

// round 10
// speedup vs baseline: 1.2023x; 1.0514x over previous
#include <cuda_runtime.h>
#include <cuda_bf16.h>
#include <cuda_fp16.h>
#include <math.h>
#include <stdint.h>

#define KDIM 384
#define NEL 25165824   // 16*64*64*384

// fp32 buffers
static __device__ float g_xs[NEL];      // xs (pre-DCT)
static __device__ float g_z [NEL];      // silu(z)
static __device__ float g_s [NEL];      // modulation scalar
static __device__ float g_f1[NEL];
static __device__ float g_W[4096];      // 64x64 DCT-II matrix (fp32, for dct_ln)
// bf16 split W planes for DCT: [orient][plane hi/lo][64][72]
static __device__ __nv_bfloat16 g_Wsp[2][2][64][72];
// fp16 split buffers ([row][768]: hi 384 | lo 384)
static __device__ float g_xd[NEL];      // split conv output
static __device__ float g_fq[NEL];      // split freq_embed
static __device__ float g_f2[NEL];      // split LN output / fp32 scratch
static __device__ float g_wl[294912];   // split lin_w  (768 rows)
static __device__ float g_wt[147456];   // split tok_w  (384 rows)
static __device__ float g_wo[147456];   // split out_w  (384 rows)

// ================================================================ helpers
__device__ __forceinline__ uint32_t smem_u32(const void* p) {
    uint32_t a;
    asm("{ .reg .u64 t; cvta.to.shared.u64 t, %1; cvt.u32.u64 %0, t; }" : "=r"(a) : "l"(p));
    return a;
}
__device__ __forceinline__ void ldsm4(uint32_t (&r)[4], uint32_t addr) {
    asm volatile("ldmatrix.sync.aligned.m8n8.x4.shared.b16 {%0,%1,%2,%3}, [%4];"
                 : "=r"(r[0]), "=r"(r[1]), "=r"(r[2]), "=r"(r[3]) : "r"(addr));
}
__device__ __forceinline__ void ldsm4t(uint32_t (&r)[4], uint32_t addr) {
    asm volatile("ldmatrix.sync.aligned.m8n8.x4.trans.shared.b16 {%0,%1,%2,%3}, [%4];"
                 : "=r"(r[0]), "=r"(r[1]), "=r"(r[2]), "=r"(r[3]) : "r"(addr));
}
// bf16 mma (DCT chain)
__device__ __forceinline__ void mma16816(float (&d)[4], const uint32_t (&a)[4],
                                         uint32_t b0, uint32_t b1) {
    asm volatile(
        "mma.sync.aligned.m16n8k16.row.col.f32.bf16.bf16.f32 "
        "{%0,%1,%2,%3}, {%4,%5,%6,%7}, {%8,%9}, {%0,%1,%2,%3};"
        : "+f"(d[0]), "+f"(d[1]), "+f"(d[2]), "+f"(d[3])
        : "r"(a[0]), "r"(a[1]), "r"(a[2]), "r"(a[3]), "r"(b0), "r"(b1));
}
// fp16 mma (GEMMs)
__device__ __forceinline__ void mma16816h(float (&d)[4], const uint32_t (&a)[4],
                                          uint32_t b0, uint32_t b1) {
    asm volatile(
        "mma.sync.aligned.m16n8k16.row.col.f32.f16.f16.f32 "
        "{%0,%1,%2,%3}, {%4,%5,%6,%7}, {%8,%9}, {%0,%1,%2,%3};"
        : "+f"(d[0]), "+f"(d[1]), "+f"(d[2]), "+f"(d[3])
        : "r"(a[0]), "r"(a[1]), "r"(a[2]), "r"(a[3]), "r"(b0), "r"(b1));
}
__device__ __forceinline__ unsigned swz(unsigned off) {
    return off ^ ((off >> 3) & 0x70);
}
__device__ __forceinline__ void cp16(uint32_t dst, const void* src) {
    asm volatile("cp.async.cg.shared.global [%0], [%1], 16;" :: "r"(dst), "l"(src) : "memory");
}
__device__ __forceinline__ void cp_commit() {
    asm volatile("cp.async.commit_group;" ::: "memory");
}
template<int N> __device__ __forceinline__ void cp_wait() {
    asm volatile("cp.async.wait_group %0;" :: "n"(N) : "memory");
}
__device__ __forceinline__ void split2(float v, __nv_bfloat16& h, __nv_bfloat16& l) {
    h = __float2bfloat16(v);
    l = __float2bfloat16(v - __bfloat162float(h));
}
__device__ __forceinline__ void split2h(float v, __half& h, __half& l) {
    h = __float2half_rn(v);
    l = __float2half_rn(v - __half2float(h));
}

// ================================================================ build W
__global__ void build_w_k() {
    int i = blockIdx.x * 256 + threadIdx.x;
    int n = i >> 6, h = i & 63;
    float v = cosf((float)n * (((float)h + 0.5f) * (3.14159265358979323846f / 64.0f)))
            * 0.17677669529663687f;
    if (n == 0) v *= 0.70710678118654752f;
    g_W[i] = v;
    __nv_bfloat16 hi, lo; split2(v, hi, lo);
    g_Wsp[0][0][n][h] = hi;
    g_Wsp[0][1][n][h] = lo;
    g_Wsp[1][0][h][n] = hi;
    g_Wsp[1][1][h][n] = lo;
}

// ================================================================ split fp32 [rows][384] -> fp16 [rows][768] (hi|lo)
__global__ void split_k(const float* __restrict__ src, __half* __restrict__ dst, int n4) {
    int i = blockIdx.x * 256 + threadIdx.x;
    if (i >= n4) return;
    int row = i / 96;
    int col = (i - row * 96) * 4;
    float4 v = *(const float4*)(src + (size_t)row * 384 + col);
    __half h0,h1,h2,h3,l0,l1,l2,l3;
    split2h(v.x,h0,l0); split2h(v.y,h1,l1); split2h(v.z,h2,l2); split2h(v.w,h3,l3);
    __half* d = dst + (size_t)row * 768 + col;
    d[0]=h0; d[1]=h1; d[2]=h2; d[3]=h3;
    d[384]=l0; d[385]=l1; d[386]=l2; d[387]=l3;
}

// ================================================================ depthwise conv 3x3, NCHW -> NHWC split fp16
__global__ void dwconv_k(const float* __restrict__ x, const float* __restrict__ w9,
                         const float* __restrict__ bias, __half* __restrict__ outp)
{
    const int bh = blockIdx.x;
    const int c  = threadIdx.x;
    const int b  = bh >> 6, h = bh & 63;
    const float* xp = x + (size_t)(b * 384 + c) * 64 * 64;
    float k0 = w9[c*9+0], k1 = w9[c*9+1], k2 = w9[c*9+2];
    float k3 = w9[c*9+3], k4 = w9[c*9+4], k5 = w9[c*9+5];
    float k6 = w9[c*9+6], k7 = w9[c*9+7], k8 = w9[c*9+8];
    const float bi = bias[c];
    const float* r0 = (h > 0)  ? xp + (h-1)*64 : 0;
    const float* r1 = xp + h*64;
    const float* r2 = (h < 63) ? xp + (h+1)*64 : 0;
    float a0 = 0.f, a1 = 0.f, a2 = 0.f;
    float m0 = r0 ? r0[0] : 0.f;
    float m1 = r1[0];
    float m2 = r2 ? r2[0] : 0.f;
    __half* ob = outp + (size_t)bh * 64 * 768 + c;
    #pragma unroll 4
    for (int w = 0; w < 64; w++) {
        float n0, n1, n2;
        if (w < 63) {
            n0 = r0 ? r0[w+1] : 0.f;
            n1 = r1[w+1];
            n2 = r2 ? r2[w+1] : 0.f;
        } else { n0 = n1 = n2 = 0.f; }
        float acc = bi
            + a0*k0 + m0*k1 + n0*k2
            + a1*k3 + m1*k4 + n1*k5
            + a2*k6 + m2*k7 + n2*k8;
        __half hi, lo; split2h(acc, hi, lo);
        ob[(size_t)w * 768]       = hi;
        ob[(size_t)w * 768 + 384] = lo;
        a0 = m0; a1 = m1; a2 = m2;
        m0 = n0; m1 = n1; m2 = n2;
    }
}

// ================================================================ mma.sync split-fp16 GEMM
// 128x128 tile, 512 threads (16 warps, warp tile 32x32)
// PROD==2: out = Ahi*Bhi + Alo*Bhi   (B rounded to fp16 hi only)
// PROD==3: out = Ahi*Bhi + Ahi*Blo + Alo*Bhi (for the exp-amplified tok GEMM)
template<int MODE, int PROD>
__global__ void __launch_bounds__(512) tgemm_k(
    const __half* __restrict__ A, const __half* __restrict__ Wt,
    const float* __restrict__ bias,
    float* __restrict__ o0, float* __restrict__ o1,
    const float* __restrict__ cp_, const float* __restrict__ ap)
{
    extern __shared__ char sm[];
    const int t    = threadIdx.x;
    const int wid  = t >> 5;
    const int lane = t & 31;
    const int m0 = blockIdx.y * 128;
    const int n0 = blockIdx.x * 128;
    const uint32_t smemBase = smem_u32(sm);

    // ---- loader: 2048 16B units/chunk, 4 per thread (skip B-lo units when PROD==2)
    const __half* srcP[4];
    uint32_t dstS[4];
    bool act[4];
    #pragma unroll
    for (int r = 0; r < 4; r++) {
        int u = t + 512 * r;
        int mat = u >> 10;
        int v = u & 1023;
        int row = v >> 3;
        int s7 = v & 7;
        act[r] = (PROD == 3) || (mat == 0) || (s7 < 4);
        const __half* base = mat ? (Wt + (size_t)(n0 + row) * 768)
                                 : (A  + (size_t)(m0 + row) * 768);
        int col = (s7 < 4) ? s7 * 8 : 384 + (s7 - 4) * 8;
        srcP[r] = base + col;
        dstS[r] = smemBase + mat * 32768 + swz((unsigned)(row * 128 + s7 * 16));
    }

    #pragma unroll
    for (int r = 0; r < 4; r++) if (act[r]) cp16(dstS[r], srcP[r]);
    cp_commit();

    const int wm = wid & 3;
    const int wn = wid >> 2;
    float acc[2][4][4];
    #pragma unroll
    for (int i = 0; i < 2; i++)
        #pragma unroll
        for (int j = 0; j < 4; j++)
            #pragma unroll
            for (int q = 0; q < 4; q++) acc[i][j][q] = 0.f;

    const int lrow = lane & 15;
    const int lkc  = (lane >> 4) << 3;

    const int NCH = KDIM / 32;   // 12
    for (int ch = 0; ch < NCH; ch++) {
        const int buf = ch & 1;
        if (ch + 1 < NCH) {
            const int nb = (ch + 1) & 1;
            #pragma unroll
            for (int r = 0; r < 4; r++)
                if (act[r]) cp16(dstS[r] + nb * 16384, srcP[r] + (ch + 1) * 32);
            cp_commit();
            cp_wait<1>();
        } else {
            cp_wait<0>();
        }
        __syncthreads();

        const uint32_t aS = smemBase + buf * 16384;
        const uint32_t bS = smemBase + 32768 + buf * 16384;
        #pragma unroll
        for (int ks = 0; ks < 2; ks++) {
            const unsigned kc2 = (unsigned)(ks * 16 + lkc) * 2;
            uint32_t ahi[2][4], alo[2][4];
            #pragma unroll
            for (int mt = 0; mt < 2; mt++) {
                unsigned off = (unsigned)(wm * 32 + mt * 16 + lrow) * 128 + kc2;
                ldsm4(ahi[mt], aS + swz(off));
                ldsm4(alo[mt], aS + swz(off + 64));
            }
            uint32_t bhi[2][4];
            #pragma unroll
            for (int ng = 0; ng < 2; ng++) {
                unsigned off = (unsigned)(wn * 32 + ng * 16 + lrow) * 128 + kc2;
                ldsm4(bhi[ng], bS + swz(off));
            }
            #pragma unroll
            for (int mt = 0; mt < 2; mt++)
                #pragma unroll
                for (int ng = 0; ng < 2; ng++) {
                    mma16816h(acc[mt][2*ng],   ahi[mt], bhi[ng][0], bhi[ng][2]);
                    mma16816h(acc[mt][2*ng+1], ahi[mt], bhi[ng][1], bhi[ng][3]);
                }
            #pragma unroll
            for (int mt = 0; mt < 2; mt++)
                #pragma unroll
                for (int ng = 0; ng < 2; ng++) {
                    mma16816h(acc[mt][2*ng],   alo[mt], bhi[ng][0], bhi[ng][2]);
                    mma16816h(acc[mt][2*ng+1], alo[mt], bhi[ng][1], bhi[ng][3]);
                }
            if (PROD == 3) {
                uint32_t blo[2][4];
                #pragma unroll
                for (int ng = 0; ng < 2; ng++) {
                    unsigned off = (unsigned)(wn * 32 + ng * 16 + lrow) * 128 + kc2;
                    ldsm4(blo[ng], bS + swz(off + 64));
                }
                #pragma unroll
                for (int mt = 0; mt < 2; mt++)
                    #pragma unroll
                    for (int ng = 0; ng < 2; ng++) {
                        mma16816h(acc[mt][2*ng],   ahi[mt], blo[ng][0], blo[ng][2]);
                        mma16816h(acc[mt][2*ng+1], ahi[mt], blo[ng][1], blo[ng][3]);
                    }
            }
        }
        __syncthreads();
    }

    // ---- epilogue: warp tile 32x32
    const int qr = lane >> 2;
    const int qc = lane & 3;
    const int mbw = m0 + wm * 32;
    const int nbw = n0 + wn * 32;

    float cc0 = 0.f, css = 0.f;
    if (MODE == 1) {
        cc0 = cp_[0];
        css = (1.0f + 0.5f * ap[0]) / (cc0 + 1e-8f);
    }

    #pragma unroll
    for (int mt = 0; mt < 2; mt++) {
        #pragma unroll
        for (int half = 0; half < 2; half++) {
            const int m = mbw + mt * 16 + qr + half * 8;
            float ee = 0.f;
            if (MODE == 1) {
                const float kp = 3.14159265358979323846f / 64.0f;
                int hh = (m >> 6) & 63, ww = m & 63;
                ee = kp * kp * (float)(hh * hh + ww * ww);
            }
            #pragma unroll
            for (int nt = 0; nt < 4; nt++) {
                const int n = nbw + nt * 8 + qc * 2;
                float v0 = acc[mt][nt][half * 2 + 0] + __ldg(bias + n);
                float v1 = acc[mt][nt][half * 2 + 1] + __ldg(bias + n + 1);
                if (MODE == 0) {
                    if (n0 >= 384) {
                        v0 *= 1.0f / (1.0f + __expf(-v0));
                        v1 *= 1.0f / (1.0f + __expf(-v1));
                        *(float2*)(o1 + (size_t)m * 384 + (n - 384)) = make_float2(v0, v1);
                    } else {
                        *(float2*)(o0 + (size_t)m * 384 + n) = make_float2(v0, v1);
                    }
                } else if (MODE == 1) {
                    float tg0 = 0.5f * v0 * (1.0f + erff(v0 * 0.70710678118654752f));
                    float tg1 = 0.5f * v1 * (1.0f + erff(v1 * 0.70710678118654752f));
                    float ct0 = cc0 * tg0, ct1 = cc0 * tg1;
                    float r0 = (__cosf(ct0) + __sinf(ct0) * css) * __expf(-ee * tg0);
                    float r1 = (__cosf(ct1) + __sinf(ct1) * css) * __expf(-ee * tg1);
                    *(float2*)(o0 + (size_t)m * 384 + n) = make_float2(r0, r1);
                } else {
                    *(float2*)(o0 + (size_t)m * 384 + n) = make_float2(v0, v1);
                }
            }
        }
    }
}

// ================================================================ tensorized 64-pt cosine transform (split bf16)
#define DT_SMEM (17408*2 + 9216*2)
template<bool FWD, bool MOD>
__global__ void __launch_bounds__(256) dctT_k(
    float* __restrict__ out, const float* __restrict__ X,
    const float* __restrict__ S, int ldRow)
{
    extern __shared__ char ds[];
    __nv_bfloat16* sXhi = (__nv_bfloat16*)ds;
    __nv_bfloat16* sXlo = (__nv_bfloat16*)(ds + 17408);
    __nv_bfloat16* sWp  = (__nv_bfloat16*)(ds + 34816);
    const int t = threadIdx.x;
    const int bb = blockIdx.y;
    const int j0 = blockIdx.x << 7;

    {
        const uint4* src = (const uint4*)&g_Wsp[FWD ? 0 : 1][0][0][0];
        uint4* dst = (uint4*)sWp;
        for (int u = t; u < 1152; u += 256) dst[u] = src[u];
    }
    const float* Xb = X + (size_t)bb * 64 * ldRow + j0;
    #pragma unroll
    for (int it = 0; it < 8; it++) {
        int idx = t + 256 * it;
        int row = idx >> 5, c4 = (idx & 31) << 2;
        float4 v = *(const float4*)(Xb + (size_t)row * ldRow + c4);
        __nv_bfloat16 h0,h1,h2,h3,l0,l1,l2,l3;
        split2(v.x,h0,l0); split2(v.y,h1,l1); split2(v.z,h2,l2); split2(v.w,h3,l3);
        unsigned hw0 = ((unsigned)__bfloat16_as_ushort(h1) << 16) | __bfloat16_as_ushort(h0);
        unsigned hw1 = ((unsigned)__bfloat16_as_ushort(h3) << 16) | __bfloat16_as_ushort(h2);
        unsigned lw0 = ((unsigned)__bfloat16_as_ushort(l1) << 16) | __bfloat16_as_ushort(l0);
        unsigned lw1 = ((unsigned)__bfloat16_as_ushort(l3) << 16) | __bfloat16_as_ushort(l2);
        *(uint2*)(sXhi + row * 136 + c4) = make_uint2(hw0, hw1);
        *(uint2*)(sXlo + row * 136 + c4) = make_uint2(lw0, lw1);
    }
    __syncthreads();

    const int wid = t >> 5, lane = t & 31;
    const int wm = wid & 1, wn = wid >> 1;
    const uint32_t xhiB = smem_u32(sXhi), xloB = smem_u32(sXlo);
    const uint32_t whiB = smem_u32(sWp),  wloB = whiB + 9216;

    float acc[2][4][4];
    #pragma unroll
    for (int i = 0; i < 2; i++)
        #pragma unroll
        for (int j = 0; j < 4; j++)
            #pragma unroll
            for (int q = 0; q < 4; q++) acc[i][j][q] = 0.f;

    const int lr = lane & 15, lh = lane >> 4;
    #pragma unroll
    for (int ks = 0; ks < 4; ks++) {
        uint32_t ahi[2][4], alo[2][4];
        #pragma unroll
        for (int mt = 0; mt < 2; mt++) {
            unsigned off = (unsigned)(wm * 32 + mt * 16 + lr) * 144 + (unsigned)(ks * 16 + lh * 8) * 2;
            ldsm4(ahi[mt], whiB + off);
            ldsm4(alo[mt], wloB + off);
        }
        uint32_t bhi[2][4], blo[2][4];
        #pragma unroll
        for (int ng = 0; ng < 2; ng++) {
            unsigned off = (unsigned)(ks * 16 + lr) * 272 + (unsigned)(wn * 32 + ng * 16 + lh * 8) * 2;
            ldsm4t(bhi[ng], xhiB + off);
            ldsm4t(blo[ng], xloB + off);
        }
        #pragma unroll
        for (int mt = 0; mt < 2; mt++)
            #pragma unroll
            for (int ng = 0; ng < 2; ng++) {
                mma16816(acc[mt][2*ng],   ahi[mt], bhi[ng][0], bhi[ng][1]);
                mma16816(acc[mt][2*ng+1], ahi[mt], bhi[ng][2], bhi[ng][3]);
            }
        #pragma unroll
        for (int mt = 0; mt < 2; mt++)
            #pragma unroll
            for (int ng = 0; ng < 2; ng++) {
                mma16816(acc[mt][2*ng],   ahi[mt], blo[ng][0], blo[ng][1]);
                mma16816(acc[mt][2*ng+1], ahi[mt], blo[ng][2], blo[ng][3]);
            }
        #pragma unroll
        for (int mt = 0; mt < 2; mt++)
            #pragma unroll
            for (int ng = 0; ng < 2; ng++) {
                mma16816(acc[mt][2*ng],   alo[mt], bhi[ng][0], bhi[ng][1]);
                mma16816(acc[mt][2*ng+1], alo[mt], bhi[ng][2], bhi[ng][3]);
            }
    }

    const int qr = lane >> 2, qc = lane & 3;
    float* ob = out + (size_t)bb * 64 * ldRow + j0;
    const float* sb = S + (size_t)bb * 64 * ldRow + j0;
    #pragma unroll
    for (int mt = 0; mt < 2; mt++)
        #pragma unroll
        for (int half = 0; half < 2; half++) {
            const int i = wm * 32 + mt * 16 + qr + half * 8;
            #pragma unroll
            for (int ng = 0; ng < 4; ng++) {
                const int j = wn * 32 + ng * 8 + qc * 2;
                float v0 = acc[mt][ng][half * 2 + 0];
                float v1 = acc[mt][ng][half * 2 + 1];
                if (MOD) {
                    float2 s2 = *(const float2*)(sb + (size_t)i * ldRow + j);
                    v0 *= s2.x; v1 *= s2.y;
                }
                *(float2*)(ob + (size_t)i * ldRow + j) = make_float2(v0, v1);
            }
        }
}

// ================================================================ fused IDCT(w) + LayerNorm + silu-gate + fp16 split
#define DL_SMEM ((4096 + 2*64*392) * 4)
__global__ void __launch_bounds__(256) dct_ln_k(
    const float* __restrict__ X, const float* __restrict__ z,
    const float* __restrict__ gam, const float* __restrict__ bet,
    __half* __restrict__ dst)
{
    extern __shared__ float s[];
    float* Ws = s;
    float* Xs = s + 4096;
    float* Os = s + 4096 + 64*392;
    const int t = threadIdx.x;
    const int bb = blockIdx.x;

    for (int idx = t; idx < 4096; idx += 256) Ws[idx] = g_W[idx];
    const float* Xb = X + (size_t)bb * 24576;
    for (int f = t; f < 6144; f += 256) {
        int row = f / 96, col = (f - row * 96) * 4;
        *(float4*)&Xs[row * 392 + col] = *(const float4*)(Xb + (size_t)row * 384 + col);
    }
    __syncthreads();

    const int wpair = t >> 3;
    const int cg = t & 7;
    const int w0 = wpair * 2;
    #pragma unroll
    for (int jb = 0; jb < 4; jb++) {
        float a0[12], a1[12];
        #pragma unroll
        for (int j = 0; j < 12; j++) { a0[j] = 0.f; a1[j] = 0.f; }
        #pragma unroll 4
        for (int m = 0; m < 64; m++) {
            float wv0 = Ws[m * 64 + w0];
            float wv1 = Ws[m * 64 + w0 + 1];
            const float* xr = &Xs[m * 392 + cg + 8 * (jb * 12)];
            #pragma unroll
            for (int j = 0; j < 12; j++) {
                float xv = xr[8 * j];
                a0[j] = fmaf(wv0, xv, a0[j]);
                a1[j] = fmaf(wv1, xv, a1[j]);
            }
        }
        #pragma unroll
        for (int j = 0; j < 12; j++) {
            int c = cg + 8 * (jb * 12 + j);
            Os[w0 * 392 + c]       = a0[j];
            Os[(w0 + 1) * 392 + c] = a1[j];
        }
    }
    __syncthreads();

    const int warp = t >> 5, lane = t & 31;
    float gv[12], bv[12];
    #pragma unroll
    for (int k = 0; k < 12; k++) { gv[k] = gam[lane + 32*k]; bv[k] = bet[lane + 32*k]; }
    for (int w = warp; w < 64; w += 8) {
        float vals[12], sum = 0.f;
        #pragma unroll
        for (int k = 0; k < 12; k++) { vals[k] = Os[w * 392 + lane + 32*k]; sum += vals[k]; }
        #pragma unroll
        for (int o = 16; o; o >>= 1) sum += __shfl_xor_sync(0xffffffffu, sum, o);
        float mu = sum * (1.0f / 384.0f);
        float q = 0.f;
        #pragma unroll
        for (int k = 0; k < 12; k++) { float d = vals[k] - mu; q = fmaf(d, d, q); }
        #pragma unroll
        for (int o = 16; o; o >>= 1) q += __shfl_xor_sync(0xffffffffu, q, o);
        float inv = rsqrtf(q * (1.0f / 384.0f) + 1e-5f);
        const size_t pixel = (size_t)bb * 64 + w;
        const float* zr = z + pixel * 384;
        __half* dr = dst + pixel * 768;
        #pragma unroll
        for (int k = 0; k < 12; k++) {
            int c = lane + 32*k;
            float o = ((vals[k] - mu) * inv * gv[k] + bv[k]) * zr[c];
            __half hi, lo; split2h(o, hi, lo);
            dr[c] = hi; dr[384 + c] = lo;
        }
    }
}

// ================================================================ launcher
#define TG_SMEM 65536

extern "C" void kernel_launch(void* const* d_in, const int* in_sizes, int n_in,
                              void* d_out, int out_size)
{
    const float* x     = (const float*)d_in[0];
    const float* freq  = (const float*)d_in[1];
    const float* dw_w  = (const float*)d_in[2];
    const float* dw_b  = (const float*)d_in[3];
    const float* lin_w = (const float*)d_in[4];
    const float* lin_b = (const float*)d_in[5];
    const float* tok_w = (const float*)d_in[6];
    const float* tok_b = (const float*)d_in[7];
    const float* ln_g  = (const float*)d_in[8];
    const float* ln_b  = (const float*)d_in[9];
    const float* out_w = (const float*)d_in[10];
    const float* out_b = (const float*)d_in[11];
    const float* cp    = (const float*)d_in[12];
    const float* ap    = (const float*)d_in[13];
    float* out = (float*)d_out;

    float *pxs, *pz, *ps, *pf1;
    __half *pxd, *pfq, *pf2, *pwl, *pwt, *pwo;
    cudaGetSymbolAddress((void**)&pxs, g_xs);
    cudaGetSymbolAddress((void**)&pz,  g_z);
    cudaGetSymbolAddress((void**)&ps,  g_s);
    cudaGetSymbolAddress((void**)&pf1, g_f1);
    cudaGetSymbolAddress((void**)&pxd, g_xd);
    cudaGetSymbolAddress((void**)&pfq, g_fq);
    cudaGetSymbolAddress((void**)&pf2, g_f2);
    cudaGetSymbolAddress((void**)&pwl, g_wl);
    cudaGetSymbolAddress((void**)&pwt, g_wt);
    cudaGetSymbolAddress((void**)&pwo, g_wo);

    cudaFuncSetAttribute((const void*)(tgemm_k<0,2>), cudaFuncAttributeMaxDynamicSharedMemorySize, TG_SMEM);
    cudaFuncSetAttribute((const void*)(tgemm_k<1,3>), cudaFuncAttributeMaxDynamicSharedMemorySize, TG_SMEM);
    cudaFuncSetAttribute((const void*)(tgemm_k<2,2>), cudaFuncAttributeMaxDynamicSharedMemorySize, TG_SMEM);
    cudaFuncSetAttribute((const void*)(dctT_k<true,  false>), cudaFuncAttributeMaxDynamicSharedMemorySize, DT_SMEM);
    cudaFuncSetAttribute((const void*)(dctT_k<true,  true >), cudaFuncAttributeMaxDynamicSharedMemorySize, DT_SMEM);
    cudaFuncSetAttribute((const void*)(dctT_k<false, false>), cudaFuncAttributeMaxDynamicSharedMemorySize, DT_SMEM);
    cudaFuncSetAttribute((const void*)dct_ln_k,   cudaFuncAttributeMaxDynamicSharedMemorySize, DL_SMEM);

    build_w_k<<<16, 256>>>();
    split_k<<<(768*96 + 255)/256, 256>>>(lin_w, pwl, 768*96);
    split_k<<<(384*96 + 255)/256, 256>>>(tok_w, pwt, 384*96);
    split_k<<<(384*96 + 255)/256, 256>>>(out_w, pwo, 384*96);
    split_k<<<(65536*96 + 255)/256, 256>>>(freq, pfq, 65536*96);
    dwconv_k<<<1024, 384>>>(x, dw_w, dw_b, pxd);
    // xz = xd @ lin_w^T : xs + silu(z)   (2-product fp16)
    tgemm_k<0,2><<<dim3(6, 512), 512, TG_SMEM>>>(pxd, pwl, lin_b, pxs, pz, nullptr, nullptr);
    // s = modulation(gelu(freq @ tok_w^T))  (3-product fp16 — exp-amplified path)
    tgemm_k<1,3><<<dim3(3, 512), 512, TG_SMEM>>>(pfq, pwt, tok_b, ps, nullptr, cp, ap);
    // DCT over h (tensorized bf16 3-product)
    dctT_k<true,  false><<<dim3(192, 16),   256, DT_SMEM>>>(pf1, pxs, pf1, 24576);
    // DCT over w + modulate by s
    dctT_k<true,  true ><<<dim3(3,  1024),  256, DT_SMEM>>>((float*)pf2, pf1, ps, 384);
    // IDCT over n
    dctT_k<false, false><<<dim3(192, 16),   256, DT_SMEM>>>(pf1, (float*)pf2, pf1, 24576);
    // fused IDCT over m + LayerNorm + silu-gate -> split fp16
    dct_ln_k<<<1024, 256, DL_SMEM>>>(pf1, pz, ln_g, ln_b, pf2);
    // out = xo @ out_w^T + out_b  (2-product fp16)
    tgemm_k<2,2><<<dim3(3, 512), 512, TG_SMEM>>>(pf2, pwo, out_b, out, nullptr, nullptr, nullptr);
}

// round 11
// speedup vs baseline: 1.2297x; 1.0228x over previous
#include <cuda_runtime.h>
#include <cuda_bf16.h>
#include <cuda_fp16.h>
#include <math.h>
#include <stdint.h>

#define KDIM 384
#define NEL 25165824   // 16*64*64*384

// fp32 buffers
static __device__ float g_xs[NEL];      // xs (pre-DCT)
static __device__ float g_z [NEL];      // silu(z)
static __device__ float g_s [NEL];      // modulation scalar
static __device__ float g_f1[NEL];
static __device__ float g_W[4096];      // 64x64 DCT-II matrix (fp32, for dct_ln)
// bf16 split W planes for DCT: [orient][plane hi/lo][64][72]
static __device__ __nv_bfloat16 g_Wsp[2][2][64][72];
// fp16 split buffers ([row][768]: hi 384 | lo 384)
static __device__ float g_xd[NEL];      // split conv output
static __device__ float g_fq[NEL];      // split freq_embed
static __device__ float g_f2[NEL];      // split LN output / fp32 scratch
static __device__ float g_wl[294912];   // split lin_w  (768 rows)
static __device__ float g_wt[147456];   // split tok_w  (384 rows)
static __device__ float g_wo[147456];   // split out_w  (384 rows)

// ================================================================ helpers
__device__ __forceinline__ uint32_t smem_u32(const void* p) {
    uint32_t a;
    asm("{ .reg .u64 t; cvta.to.shared.u64 t, %1; cvt.u32.u64 %0, t; }" : "=r"(a) : "l"(p));
    return a;
}
__device__ __forceinline__ void ldsm4(uint32_t (&r)[4], uint32_t addr) {
    asm volatile("ldmatrix.sync.aligned.m8n8.x4.shared.b16 {%0,%1,%2,%3}, [%4];"
                 : "=r"(r[0]), "=r"(r[1]), "=r"(r[2]), "=r"(r[3]) : "r"(addr));
}
__device__ __forceinline__ void ldsm4t(uint32_t (&r)[4], uint32_t addr) {
    asm volatile("ldmatrix.sync.aligned.m8n8.x4.trans.shared.b16 {%0,%1,%2,%3}, [%4];"
                 : "=r"(r[0]), "=r"(r[1]), "=r"(r[2]), "=r"(r[3]) : "r"(addr));
}
// bf16 mma (DCT chain)
__device__ __forceinline__ void mma16816(float (&d)[4], const uint32_t (&a)[4],
                                         uint32_t b0, uint32_t b1) {
    asm volatile(
        "mma.sync.aligned.m16n8k16.row.col.f32.bf16.bf16.f32 "
        "{%0,%1,%2,%3}, {%4,%5,%6,%7}, {%8,%9}, {%0,%1,%2,%3};"
        : "+f"(d[0]), "+f"(d[1]), "+f"(d[2]), "+f"(d[3])
        : "r"(a[0]), "r"(a[1]), "r"(a[2]), "r"(a[3]), "r"(b0), "r"(b1));
}
// fp16 mma (GEMMs)
__device__ __forceinline__ void mma16816h(float (&d)[4], const uint32_t (&a)[4],
                                          uint32_t b0, uint32_t b1) {
    asm volatile(
        "mma.sync.aligned.m16n8k16.row.col.f32.f16.f16.f32 "
        "{%0,%1,%2,%3}, {%4,%5,%6,%7}, {%8,%9}, {%0,%1,%2,%3};"
        : "+f"(d[0]), "+f"(d[1]), "+f"(d[2]), "+f"(d[3])
        : "r"(a[0]), "r"(a[1]), "r"(a[2]), "r"(a[3]), "r"(b0), "r"(b1));
}
__device__ __forceinline__ unsigned swz(unsigned off) {
    return off ^ ((off >> 3) & 0x70);
}
__device__ __forceinline__ void cp16(uint32_t dst, const void* src) {
    asm volatile("cp.async.cg.shared.global [%0], [%1], 16;" :: "r"(dst), "l"(src) : "memory");
}
__device__ __forceinline__ void cp_commit() {
    asm volatile("cp.async.commit_group;" ::: "memory");
}
template<int N> __device__ __forceinline__ void cp_wait() {
    asm volatile("cp.async.wait_group %0;" :: "n"(N) : "memory");
}
__device__ __forceinline__ void split2(float v, __nv_bfloat16& h, __nv_bfloat16& l) {
    h = __float2bfloat16(v);
    l = __float2bfloat16(v - __bfloat162float(h));
}
__device__ __forceinline__ void split2h(float v, __half& h, __half& l) {
    h = __float2half_rn(v);
    l = __float2half_rn(v - __half2float(h));
}

// ================================================================ build W
__global__ void build_w_k() {
    int i = blockIdx.x * 256 + threadIdx.x;
    int n = i >> 6, h = i & 63;
    float v = cosf((float)n * (((float)h + 0.5f) * (3.14159265358979323846f / 64.0f)))
            * 0.17677669529663687f;
    if (n == 0) v *= 0.70710678118654752f;
    g_W[i] = v;
    __nv_bfloat16 hi, lo; split2(v, hi, lo);
    g_Wsp[0][0][n][h] = hi;
    g_Wsp[0][1][n][h] = lo;
    g_Wsp[1][0][h][n] = hi;
    g_Wsp[1][1][h][n] = lo;
}

// ================================================================ split fp32 [rows][384] -> fp16 [rows][768] (hi|lo)
__global__ void split_k(const float* __restrict__ src, __half* __restrict__ dst, int n4) {
    int i = blockIdx.x * 256 + threadIdx.x;
    if (i >= n4) return;
    int row = i / 96;
    int col = (i - row * 96) * 4;
    float4 v = *(const float4*)(src + (size_t)row * 384 + col);
    __half h0,h1,h2,h3,l0,l1,l2,l3;
    split2h(v.x,h0,l0); split2h(v.y,h1,l1); split2h(v.z,h2,l2); split2h(v.w,h3,l3);
    __half* d = dst + (size_t)row * 768 + col;
    d[0]=h0; d[1]=h1; d[2]=h2; d[3]=h3;
    d[384]=l0; d[385]=l1; d[386]=l2; d[387]=l3;
}

// ================================================================ depthwise conv 3x3, NCHW -> NHWC split fp16
__global__ void dwconv_k(const float* __restrict__ x, const float* __restrict__ w9,
                         const float* __restrict__ bias, __half* __restrict__ outp)
{
    const int bh = blockIdx.x;
    const int c  = threadIdx.x;
    const int b  = bh >> 6, h = bh & 63;
    const float* xp = x + (size_t)(b * 384 + c) * 64 * 64;
    float k0 = w9[c*9+0], k1 = w9[c*9+1], k2 = w9[c*9+2];
    float k3 = w9[c*9+3], k4 = w9[c*9+4], k5 = w9[c*9+5];
    float k6 = w9[c*9+6], k7 = w9[c*9+7], k8 = w9[c*9+8];
    const float bi = bias[c];
    const float* r0 = (h > 0)  ? xp + (h-1)*64 : 0;
    const float* r1 = xp + h*64;
    const float* r2 = (h < 63) ? xp + (h+1)*64 : 0;
    float a0 = 0.f, a1 = 0.f, a2 = 0.f;
    float m0 = r0 ? r0[0] : 0.f;
    float m1 = r1[0];
    float m2 = r2 ? r2[0] : 0.f;
    __half* ob = outp + (size_t)bh * 64 * 768 + c;
    #pragma unroll 4
    for (int w = 0; w < 64; w++) {
        float n0, n1, n2;
        if (w < 63) {
            n0 = r0 ? r0[w+1] : 0.f;
            n1 = r1[w+1];
            n2 = r2 ? r2[w+1] : 0.f;
        } else { n0 = n1 = n2 = 0.f; }
        float acc = bi
            + a0*k0 + m0*k1 + n0*k2
            + a1*k3 + m1*k4 + n1*k5
            + a2*k6 + m2*k7 + n2*k8;
        __half hi, lo; split2h(acc, hi, lo);
        ob[(size_t)w * 768]       = hi;
        ob[(size_t)w * 768 + 384] = lo;
        a0 = m0; a1 = m1; a2 = m2;
        m0 = n0; m1 = n1; m2 = n2;
    }
}

// ================================================================ mma.sync split-fp16 GEMM, 3-stage cp.async pipeline
// 128x128 tile, 512 threads (16 warps, warp tile 32x32)
// smem: 3 stages x (A 16KB | B 16KB) = 96KB
// PROD==2: out = Ahi*Bhi + Alo*Bhi
// PROD==3: out = Ahi*Bhi + Ahi*Blo + Alo*Bhi
template<int MODE, int PROD>
__global__ void __launch_bounds__(512) tgemm_k(
    const __half* __restrict__ A, const __half* __restrict__ Wt,
    const float* __restrict__ bias,
    float* __restrict__ o0, float* __restrict__ o1,
    const float* __restrict__ cp_, const float* __restrict__ ap)
{
    extern __shared__ char sm[];
    const int t    = threadIdx.x;
    const int wid  = t >> 5;
    const int lane = t & 31;
    const int m0 = blockIdx.y * 128;
    const int n0 = blockIdx.x * 128;
    const uint32_t smemBase = smem_u32(sm);

    // ---- loader: 2048 16B units/chunk, 4 per thread (skip B-lo when PROD==2)
    const __half* srcP[4];
    uint32_t dstS[4];
    bool act[4];
    #pragma unroll
    for (int r = 0; r < 4; r++) {
        int u = t + 512 * r;
        int mat = u >> 10;
        int v = u & 1023;
        int row = v >> 3;
        int s7 = v & 7;
        act[r] = (PROD == 3) || (mat == 0) || (s7 < 4);
        const __half* base = mat ? (Wt + (size_t)(n0 + row) * 768)
                                 : (A  + (size_t)(m0 + row) * 768);
        int col = (s7 < 4) ? s7 * 8 : 384 + (s7 - 4) * 8;
        srcP[r] = base + col;
        dstS[r] = smemBase + mat * 16384 + swz((unsigned)(row * 128 + s7 * 16));
    }

    #define TG_ISSUE(CH, STG) do {                                         \
        const unsigned so_ = (unsigned)(STG) * 32768u;                     \
        _Pragma("unroll")                                                  \
        for (int r_ = 0; r_ < 4; r_++)                                     \
            if (act[r_]) cp16(dstS[r_] + so_, srcP[r_] + (CH) * 32);       \
        cp_commit();                                                       \
    } while (0)

    TG_ISSUE(0, 0);
    TG_ISSUE(1, 1);

    const int wm = wid & 3;
    const int wn = wid >> 2;
    float acc[2][4][4];
    #pragma unroll
    for (int i = 0; i < 2; i++)
        #pragma unroll
        for (int j = 0; j < 4; j++)
            #pragma unroll
            for (int q = 0; q < 4; q++) acc[i][j][q] = 0.f;

    const int lrow = lane & 15;
    const int lkc  = (lane >> 4) << 3;

    const int NCH = KDIM / 32;   // 12
    int stg = 0;                 // ch % 3
    int istg = 2;                // (ch+2) % 3
    for (int ch = 0; ch < NCH; ch++) {
        if (ch < NCH - 1) cp_wait<1>(); else cp_wait<0>();
        __syncthreads();
        if (ch + 2 < NCH) TG_ISSUE(ch + 2, istg);

        const uint32_t aS = smemBase + (unsigned)stg * 32768u;
        const uint32_t bS = aS + 16384u;
        #pragma unroll
        for (int ks = 0; ks < 2; ks++) {
            const unsigned kc2 = (unsigned)(ks * 16 + lkc) * 2;
            uint32_t ahi[2][4], alo[2][4];
            #pragma unroll
            for (int mt = 0; mt < 2; mt++) {
                unsigned off = (unsigned)(wm * 32 + mt * 16 + lrow) * 128 + kc2;
                ldsm4(ahi[mt], aS + swz(off));
                ldsm4(alo[mt], aS + swz(off + 64));
            }
            uint32_t bhi[2][4];
            #pragma unroll
            for (int ng = 0; ng < 2; ng++) {
                unsigned off = (unsigned)(wn * 32 + ng * 16 + lrow) * 128 + kc2;
                ldsm4(bhi[ng], bS + swz(off));
            }
            #pragma unroll
            for (int mt = 0; mt < 2; mt++)
                #pragma unroll
                for (int ng = 0; ng < 2; ng++) {
                    mma16816h(acc[mt][2*ng],   ahi[mt], bhi[ng][0], bhi[ng][2]);
                    mma16816h(acc[mt][2*ng+1], ahi[mt], bhi[ng][1], bhi[ng][3]);
                }
            #pragma unroll
            for (int mt = 0; mt < 2; mt++)
                #pragma unroll
                for (int ng = 0; ng < 2; ng++) {
                    mma16816h(acc[mt][2*ng],   alo[mt], bhi[ng][0], bhi[ng][2]);
                    mma16816h(acc[mt][2*ng+1], alo[mt], bhi[ng][1], bhi[ng][3]);
                }
            if (PROD == 3) {
                uint32_t blo[2][4];
                #pragma unroll
                for (int ng = 0; ng < 2; ng++) {
                    unsigned off = (unsigned)(wn * 32 + ng * 16 + lrow) * 128 + kc2;
                    ldsm4(blo[ng], bS + swz(off + 64));
                }
                #pragma unroll
                for (int mt = 0; mt < 2; mt++)
                    #pragma unroll
                    for (int ng = 0; ng < 2; ng++) {
                        mma16816h(acc[mt][2*ng],   ahi[mt], blo[ng][0], blo[ng][2]);
                        mma16816h(acc[mt][2*ng+1], ahi[mt], blo[ng][1], blo[ng][3]);
                    }
            }
        }
        stg  = (stg  == 2) ? 0 : stg  + 1;
        istg = (istg == 2) ? 0 : istg + 1;
    }
    #undef TG_ISSUE

    // ---- epilogue: warp tile 32x32
    const int qr = lane >> 2;
    const int qc = lane & 3;
    const int mbw = m0 + wm * 32;
    const int nbw = n0 + wn * 32;

    float cc0 = 0.f, css = 0.f;
    if (MODE == 1) {
        cc0 = cp_[0];
        css = (1.0f + 0.5f * ap[0]) / (cc0 + 1e-8f);
    }

    #pragma unroll
    for (int mt = 0; mt < 2; mt++) {
        #pragma unroll
        for (int half = 0; half < 2; half++) {
            const int m = mbw + mt * 16 + qr + half * 8;
            float ee = 0.f;
            if (MODE == 1) {
                const float kp = 3.14159265358979323846f / 64.0f;
                int hh = (m >> 6) & 63, ww = m & 63;
                ee = kp * kp * (float)(hh * hh + ww * ww);
            }
            #pragma unroll
            for (int nt = 0; nt < 4; nt++) {
                const int n = nbw + nt * 8 + qc * 2;
                float v0 = acc[mt][nt][half * 2 + 0] + __ldg(bias + n);
                float v1 = acc[mt][nt][half * 2 + 1] + __ldg(bias + n + 1);
                if (MODE == 0) {
                    if (n0 >= 384) {
                        v0 *= 1.0f / (1.0f + __expf(-v0));
                        v1 *= 1.0f / (1.0f + __expf(-v1));
                        *(float2*)(o1 + (size_t)m * 384 + (n - 384)) = make_float2(v0, v1);
                    } else {
                        *(float2*)(o0 + (size_t)m * 384 + n) = make_float2(v0, v1);
                    }
                } else if (MODE == 1) {
                    float tg0 = 0.5f * v0 * (1.0f + erff(v0 * 0.70710678118654752f));
                    float tg1 = 0.5f * v1 * (1.0f + erff(v1 * 0.70710678118654752f));
                    float ct0 = cc0 * tg0, ct1 = cc0 * tg1;
                    float r0 = (__cosf(ct0) + __sinf(ct0) * css) * __expf(-ee * tg0);
                    float r1 = (__cosf(ct1) + __sinf(ct1) * css) * __expf(-ee * tg1);
                    *(float2*)(o0 + (size_t)m * 384 + n) = make_float2(r0, r1);
                } else {
                    *(float2*)(o0 + (size_t)m * 384 + n) = make_float2(v0, v1);
                }
            }
        }
    }
}

// ================================================================ tensorized 64-pt cosine transform (split bf16)
#define DT_SMEM (17408*2 + 9216*2)
template<bool FWD, bool MOD>
__global__ void __launch_bounds__(256) dctT_k(
    float* __restrict__ out, const float* __restrict__ X,
    const float* __restrict__ S, int ldRow)
{
    extern __shared__ char ds[];
    __nv_bfloat16* sXhi = (__nv_bfloat16*)ds;
    __nv_bfloat16* sXlo = (__nv_bfloat16*)(ds + 17408);
    __nv_bfloat16* sWp  = (__nv_bfloat16*)(ds + 34816);
    const int t = threadIdx.x;
    const int bb = blockIdx.y;
    const int j0 = blockIdx.x << 7;

    {
        const uint4* src = (const uint4*)&g_Wsp[FWD ? 0 : 1][0][0][0];
        uint4* dst = (uint4*)sWp;
        for (int u = t; u < 1152; u += 256) dst[u] = src[u];
    }
    const float* Xb = X + (size_t)bb * 64 * ldRow + j0;
    #pragma unroll
    for (int it = 0; it < 8; it++) {
        int idx = t + 256 * it;
        int row = idx >> 5, c4 = (idx & 31) << 2;
        float4 v = *(const float4*)(Xb + (size_t)row * ldRow + c4);
        __nv_bfloat16 h0,h1,h2,h3,l0,l1,l2,l3;
        split2(v.x,h0,l0); split2(v.y,h1,l1); split2(v.z,h2,l2); split2(v.w,h3,l3);
        unsigned hw0 = ((unsigned)__bfloat16_as_ushort(h1) << 16) | __bfloat16_as_ushort(h0);
        unsigned hw1 = ((unsigned)__bfloat16_as_ushort(h3) << 16) | __bfloat16_as_ushort(h2);
        unsigned lw0 = ((unsigned)__bfloat16_as_ushort(l1) << 16) | __bfloat16_as_ushort(l0);
        unsigned lw1 = ((unsigned)__bfloat16_as_ushort(l3) << 16) | __bfloat16_as_ushort(l2);
        *(uint2*)(sXhi + row * 136 + c4) = make_uint2(hw0, hw1);
        *(uint2*)(sXlo + row * 136 + c4) = make_uint2(lw0, lw1);
    }
    __syncthreads();

    const int wid = t >> 5, lane = t & 31;
    const int wm = wid & 1, wn = wid >> 1;
    const uint32_t xhiB = smem_u32(sXhi), xloB = smem_u32(sXlo);
    const uint32_t whiB = smem_u32(sWp),  wloB = whiB + 9216;

    float acc[2][4][4];
    #pragma unroll
    for (int i = 0; i < 2; i++)
        #pragma unroll
        for (int j = 0; j < 4; j++)
            #pragma unroll
            for (int q = 0; q < 4; q++) acc[i][j][q] = 0.f;

    const int lr = lane & 15, lh = lane >> 4;
    #pragma unroll
    for (int ks = 0; ks < 4; ks++) {
        uint32_t ahi[2][4], alo[2][4];
        #pragma unroll
        for (int mt = 0; mt < 2; mt++) {
            unsigned off = (unsigned)(wm * 32 + mt * 16 + lr) * 144 + (unsigned)(ks * 16 + lh * 8) * 2;
            ldsm4(ahi[mt], whiB + off);
            ldsm4(alo[mt], wloB + off);
        }
        uint32_t bhi[2][4], blo[2][4];
        #pragma unroll
        for (int ng = 0; ng < 2; ng++) {
            unsigned off = (unsigned)(ks * 16 + lr) * 272 + (unsigned)(wn * 32 + ng * 16 + lh * 8) * 2;
            ldsm4t(bhi[ng], xhiB + off);
            ldsm4t(blo[ng], xloB + off);
        }
        #pragma unroll
        for (int mt = 0; mt < 2; mt++)
            #pragma unroll
            for (int ng = 0; ng < 2; ng++) {
                mma16816(acc[mt][2*ng],   ahi[mt], bhi[ng][0], bhi[ng][1]);
                mma16816(acc[mt][2*ng+1], ahi[mt], bhi[ng][2], bhi[ng][3]);
            }
        #pragma unroll
        for (int mt = 0; mt < 2; mt++)
            #pragma unroll
            for (int ng = 0; ng < 2; ng++) {
                mma16816(acc[mt][2*ng],   ahi[mt], blo[ng][0], blo[ng][1]);
                mma16816(acc[mt][2*ng+1], ahi[mt], blo[ng][2], blo[ng][3]);
            }
        #pragma unroll
        for (int mt = 0; mt < 2; mt++)
            #pragma unroll
            for (int ng = 0; ng < 2; ng++) {
                mma16816(acc[mt][2*ng],   alo[mt], bhi[ng][0], bhi[ng][1]);
                mma16816(acc[mt][2*ng+1], alo[mt], bhi[ng][2], bhi[ng][3]);
            }
    }

    const int qr = lane >> 2, qc = lane & 3;
    float* ob = out + (size_t)bb * 64 * ldRow + j0;
    const float* sb = S + (size_t)bb * 64 * ldRow + j0;
    #pragma unroll
    for (int mt = 0; mt < 2; mt++)
        #pragma unroll
        for (int half = 0; half < 2; half++) {
            const int i = wm * 32 + mt * 16 + qr + half * 8;
            #pragma unroll
            for (int ng = 0; ng < 4; ng++) {
                const int j = wn * 32 + ng * 8 + qc * 2;
                float v0 = acc[mt][ng][half * 2 + 0];
                float v1 = acc[mt][ng][half * 2 + 1];
                if (MOD) {
                    float2 s2 = *(const float2*)(sb + (size_t)i * ldRow + j);
                    v0 *= s2.x; v1 *= s2.y;
                }
                *(float2*)(ob + (size_t)i * ldRow + j) = make_float2(v0, v1);
            }
        }
}

// ================================================================ fused IDCT(w) + LayerNorm + silu-gate + fp16 split
#define DL_SMEM ((4096 + 2*64*392) * 4)
__global__ void __launch_bounds__(256) dct_ln_k(
    const float* __restrict__ X, const float* __restrict__ z,
    const float* __restrict__ gam, const float* __restrict__ bet,
    __half* __restrict__ dst)
{
    extern __shared__ float s[];
    float* Ws = s;
    float* Xs = s + 4096;
    float* Os = s + 4096 + 64*392;
    const int t = threadIdx.x;
    const int bb = blockIdx.x;

    for (int idx = t; idx < 4096; idx += 256) Ws[idx] = g_W[idx];
    const float* Xb = X + (size_t)bb * 24576;
    for (int f = t; f < 6144; f += 256) {
        int row = f / 96, col = (f - row * 96) * 4;
        *(float4*)&Xs[row * 392 + col] = *(const float4*)(Xb + (size_t)row * 384 + col);
    }
    __syncthreads();

    const int wpair = t >> 3;
    const int cg = t & 7;
    const int w0 = wpair * 2;
    #pragma unroll
    for (int jb = 0; jb < 4; jb++) {
        float a0[12], a1[12];
        #pragma unroll
        for (int j = 0; j < 12; j++) { a0[j] = 0.f; a1[j] = 0.f; }
        #pragma unroll 4
        for (int m = 0; m < 64; m++) {
            float wv0 = Ws[m * 64 + w0];
            float wv1 = Ws[m * 64 + w0 + 1];
            const float* xr = &Xs[m * 392 + cg + 8 * (jb * 12)];
            #pragma unroll
            for (int j = 0; j < 12; j++) {
                float xv = xr[8 * j];
                a0[j] = fmaf(wv0, xv, a0[j]);
                a1[j] = fmaf(wv1, xv, a1[j]);
            }
        }
        #pragma unroll
        for (int j = 0; j < 12; j++) {
            int c = cg + 8 * (jb * 12 + j);
            Os[w0 * 392 + c]       = a0[j];
            Os[(w0 + 1) * 392 + c] = a1[j];
        }
    }
    __syncthreads();

    const int warp = t >> 5, lane = t & 31;
    float gv[12], bv[12];
    #pragma unroll
    for (int k = 0; k < 12; k++) { gv[k] = gam[lane + 32*k]; bv[k] = bet[lane + 32*k]; }
    for (int w = warp; w < 64; w += 8) {
        float vals[12], sum = 0.f;
        #pragma unroll
        for (int k = 0; k < 12; k++) { vals[k] = Os[w * 392 + lane + 32*k]; sum += vals[k]; }
        #pragma unroll
        for (int o = 16; o; o >>= 1) sum += __shfl_xor_sync(0xffffffffu, sum, o);
        float mu = sum * (1.0f / 384.0f);
        float q = 0.f;
        #pragma unroll
        for (int k = 0; k < 12; k++) { float d = vals[k] - mu; q = fmaf(d, d, q); }
        #pragma unroll
        for (int o = 16; o; o >>= 1) q += __shfl_xor_sync(0xffffffffu, q, o);
        float inv = rsqrtf(q * (1.0f / 384.0f) + 1e-5f);
        const size_t pixel = (size_t)bb * 64 + w;
        const float* zr = z + pixel * 384;
        __half* dr = dst + pixel * 768;
        #pragma unroll
        for (int k = 0; k < 12; k++) {
            int c = lane + 32*k;
            float o = ((vals[k] - mu) * inv * gv[k] + bv[k]) * zr[c];
            __half hi, lo; split2h(o, hi, lo);
            dr[c] = hi; dr[384 + c] = lo;
        }
    }
}

// ================================================================ launcher
#define TG_SMEM 98304

extern "C" void kernel_launch(void* const* d_in, const int* in_sizes, int n_in,
                              void* d_out, int out_size)
{
    const float* x     = (const float*)d_in[0];
    const float* freq  = (const float*)d_in[1];
    const float* dw_w  = (const float*)d_in[2];
    const float* dw_b  = (const float*)d_in[3];
    const float* lin_w = (const float*)d_in[4];
    const float* lin_b = (const float*)d_in[5];
    const float* tok_w = (const float*)d_in[6];
    const float* tok_b = (const float*)d_in[7];
    const float* ln_g  = (const float*)d_in[8];
    const float* ln_b  = (const float*)d_in[9];
    const float* out_w = (const float*)d_in[10];
    const float* out_b = (const float*)d_in[11];
    const float* cp    = (const float*)d_in[12];
    const float* ap    = (const float*)d_in[13];
    float* out = (float*)d_out;

    float *pxs, *pz, *ps, *pf1;
    __half *pxd, *pfq, *pf2, *pwl, *pwt, *pwo;
    cudaGetSymbolAddress((void**)&pxs, g_xs);
    cudaGetSymbolAddress((void**)&pz,  g_z);
    cudaGetSymbolAddress((void**)&ps,  g_s);
    cudaGetSymbolAddress((void**)&pf1, g_f1);
    cudaGetSymbolAddress((void**)&pxd, g_xd);
    cudaGetSymbolAddress((void**)&pfq, g_fq);
    cudaGetSymbolAddress((void**)&pf2, g_f2);
    cudaGetSymbolAddress((void**)&pwl, g_wl);
    cudaGetSymbolAddress((void**)&pwt, g_wt);
    cudaGetSymbolAddress((void**)&pwo, g_wo);

    cudaFuncSetAttribute((const void*)(tgemm_k<0,2>), cudaFuncAttributeMaxDynamicSharedMemorySize, TG_SMEM);
    cudaFuncSetAttribute((const void*)(tgemm_k<1,3>), cudaFuncAttributeMaxDynamicSharedMemorySize, TG_SMEM);
    cudaFuncSetAttribute((const void*)(tgemm_k<2,2>), cudaFuncAttributeMaxDynamicSharedMemorySize, TG_SMEM);
    cudaFuncSetAttribute((const void*)(dctT_k<true,  false>), cudaFuncAttributeMaxDynamicSharedMemorySize, DT_SMEM);
    cudaFuncSetAttribute((const void*)(dctT_k<true,  true >), cudaFuncAttributeMaxDynamicSharedMemorySize, DT_SMEM);
    cudaFuncSetAttribute((const void*)(dctT_k<false, false>), cudaFuncAttributeMaxDynamicSharedMemorySize, DT_SMEM);
    cudaFuncSetAttribute((const void*)dct_ln_k,   cudaFuncAttributeMaxDynamicSharedMemorySize, DL_SMEM);

    // (launch order arranged so the profiler's captured launch is tgemm_k<0>)
    build_w_k<<<16, 256>>>();                                               // 1
    split_k<<<(768*96 + 255)/256, 256>>>(lin_w, pwl, 768*96);               // 2
    dwconv_k<<<1024, 384>>>(x, dw_w, dw_b, pxd);                            // 3
    split_k<<<(384*96 + 255)/256, 256>>>(tok_w, pwt, 384*96);               // 4
    // xz = xd @ lin_w^T : xs + silu(z)   (2-product fp16)                  // 5 <- profiled
    tgemm_k<0,2><<<dim3(6, 512), 512, TG_SMEM>>>(pxd, pwl, lin_b, pxs, pz, nullptr, nullptr);
    split_k<<<(65536*96 + 255)/256, 256>>>(freq, pfq, 65536*96);            // 6
    split_k<<<(384*96 + 255)/256, 256>>>(out_w, pwo, 384*96);               // 7
    // s = modulation(gelu(freq @ tok_w^T))  (3-product fp16)
    tgemm_k<1,3><<<dim3(3, 512), 512, TG_SMEM>>>(pfq, pwt, tok_b, ps, nullptr, cp, ap);
    // DCT over h (tensorized bf16 3-product)
    dctT_k<true,  false><<<dim3(192, 16),   256, DT_SMEM>>>(pf1, pxs, pf1, 24576);
    // DCT over w + modulate by s
    dctT_k<true,  true ><<<dim3(3,  1024),  256, DT_SMEM>>>((float*)pf2, pf1, ps, 384);
    // IDCT over n
    dctT_k<false, false><<<dim3(192, 16),   256, DT_SMEM>>>(pf1, (float*)pf2, pf1, 24576);
    // fused IDCT over m + LayerNorm + silu-gate -> split fp16
    dct_ln_k<<<1024, 256, DL_SMEM>>>(pf1, pz, ln_g, ln_b, pf2);
    // out = xo @ out_w^T + out_b  (2-product fp16)
    tgemm_k<2,2><<<dim3(3, 512), 512, TG_SMEM>>>(pf2, pwo, out_b, out, nullptr, nullptr, nullptr);
}

// round 12
// speedup vs baseline: 1.2632x; 1.0272x over previous
#include <cuda_runtime.h>
#include <cuda_bf16.h>
#include <cuda_fp16.h>
#include <math.h>
#include <stdint.h>

#define KDIM 384
#define NEL 25165824   // 16*64*64*384

// fp32 buffers
static __device__ float g_xs[NEL];      // xs (pre-DCT)
static __device__ float g_z [NEL];      // silu(z)
static __device__ float g_s [NEL];      // modulation scalar
static __device__ float g_f1[NEL];
static __device__ float g_W[4096];      // 64x64 DCT-II matrix (fp32, for dct_ln)
// bf16 split W planes for DCT: [orient][plane hi/lo][64][72]
static __device__ __nv_bfloat16 g_Wsp[2][2][64][72];
// fp16 split buffers ([row][768]: hi 384 | lo 384)
static __device__ float g_xd[NEL];      // split conv output
static __device__ float g_fq[NEL];      // split freq_embed
static __device__ float g_f2[NEL];      // split LN output / fp32 scratch
static __device__ float g_wl[294912];   // split lin_w  (768 rows)
static __device__ float g_wt[147456];   // split tok_w  (384 rows)
static __device__ float g_wo[147456];   // split out_w  (384 rows)

// ================================================================ helpers
__device__ __forceinline__ uint32_t smem_u32(const void* p) {
    uint32_t a;
    asm("{ .reg .u64 t; cvta.to.shared.u64 t, %1; cvt.u32.u64 %0, t; }" : "=r"(a) : "l"(p));
    return a;
}
__device__ __forceinline__ void ldsm4(uint32_t (&r)[4], uint32_t addr) {
    asm volatile("ldmatrix.sync.aligned.m8n8.x4.shared.b16 {%0,%1,%2,%3}, [%4];"
                 : "=r"(r[0]), "=r"(r[1]), "=r"(r[2]), "=r"(r[3]) : "r"(addr));
}
__device__ __forceinline__ void ldsm4t(uint32_t (&r)[4], uint32_t addr) {
    asm volatile("ldmatrix.sync.aligned.m8n8.x4.trans.shared.b16 {%0,%1,%2,%3}, [%4];"
                 : "=r"(r[0]), "=r"(r[1]), "=r"(r[2]), "=r"(r[3]) : "r"(addr));
}
// bf16 mma (DCT chain)
__device__ __forceinline__ void mma16816(float (&d)[4], const uint32_t (&a)[4],
                                         uint32_t b0, uint32_t b1) {
    asm volatile(
        "mma.sync.aligned.m16n8k16.row.col.f32.bf16.bf16.f32 "
        "{%0,%1,%2,%3}, {%4,%5,%6,%7}, {%8,%9}, {%0,%1,%2,%3};"
        : "+f"(d[0]), "+f"(d[1]), "+f"(d[2]), "+f"(d[3])
        : "r"(a[0]), "r"(a[1]), "r"(a[2]), "r"(a[3]), "r"(b0), "r"(b1));
}
// fp16 mma (GEMMs)
__device__ __forceinline__ void mma16816h(float (&d)[4], const uint32_t (&a)[4],
                                          uint32_t b0, uint32_t b1) {
    asm volatile(
        "mma.sync.aligned.m16n8k16.row.col.f32.f16.f16.f32 "
        "{%0,%1,%2,%3}, {%4,%5,%6,%7}, {%8,%9}, {%0,%1,%2,%3};"
        : "+f"(d[0]), "+f"(d[1]), "+f"(d[2]), "+f"(d[3])
        : "r"(a[0]), "r"(a[1]), "r"(a[2]), "r"(a[3]), "r"(b0), "r"(b1));
}
__device__ __forceinline__ unsigned swz(unsigned off) {
    return off ^ ((off >> 3) & 0x70);
}
__device__ __forceinline__ void cp16(uint32_t dst, const void* src) {
    asm volatile("cp.async.cg.shared.global [%0], [%1], 16;" :: "r"(dst), "l"(src) : "memory");
}
__device__ __forceinline__ void cp_commit() {
    asm volatile("cp.async.commit_group;" ::: "memory");
}
template<int N> __device__ __forceinline__ void cp_wait() {
    asm volatile("cp.async.wait_group %0;" :: "n"(N) : "memory");
}
__device__ __forceinline__ void split2(float v, __nv_bfloat16& h, __nv_bfloat16& l) {
    h = __float2bfloat16(v);
    l = __float2bfloat16(v - __bfloat162float(h));
}
__device__ __forceinline__ void split2h(float v, __half& h, __half& l) {
    h = __float2half_rn(v);
    l = __float2half_rn(v - __half2float(h));
}

// ================================================================ build W
__global__ void build_w_k() {
    int i = blockIdx.x * 256 + threadIdx.x;
    int n = i >> 6, h = i & 63;
    float v = cosf((float)n * (((float)h + 0.5f) * (3.14159265358979323846f / 64.0f)))
            * 0.17677669529663687f;
    if (n == 0) v *= 0.70710678118654752f;
    g_W[i] = v;
    __nv_bfloat16 hi, lo; split2(v, hi, lo);
    g_Wsp[0][0][n][h] = hi;
    g_Wsp[0][1][n][h] = lo;
    g_Wsp[1][0][h][n] = hi;
    g_Wsp[1][1][h][n] = lo;
}

// ================================================================ split fp32 [rows][384] -> fp16 [rows][768] (hi|lo)
__global__ void split_k(const float* __restrict__ src, __half* __restrict__ dst, int n4) {
    int i = blockIdx.x * 256 + threadIdx.x;
    if (i >= n4) return;
    int row = i / 96;
    int col = (i - row * 96) * 4;
    float4 v = *(const float4*)(src + (size_t)row * 384 + col);
    __half h0,h1,h2,h3,l0,l1,l2,l3;
    split2h(v.x,h0,l0); split2h(v.y,h1,l1); split2h(v.z,h2,l2); split2h(v.w,h3,l3);
    __half* d = dst + (size_t)row * 768 + col;
    d[0]=h0; d[1]=h1; d[2]=h2; d[3]=h3;
    d[384]=l0; d[385]=l1; d[386]=l2; d[387]=l3;
}

// ================================================================ depthwise conv 3x3, NCHW -> NHWC split fp16
__global__ void dwconv_k(const float* __restrict__ x, const float* __restrict__ w9,
                         const float* __restrict__ bias, __half* __restrict__ outp)
{
    const int bh = blockIdx.x;
    const int c  = threadIdx.x;
    const int b  = bh >> 6, h = bh & 63;
    const float* xp = x + (size_t)(b * 384 + c) * 64 * 64;
    float k0 = w9[c*9+0], k1 = w9[c*9+1], k2 = w9[c*9+2];
    float k3 = w9[c*9+3], k4 = w9[c*9+4], k5 = w9[c*9+5];
    float k6 = w9[c*9+6], k7 = w9[c*9+7], k8 = w9[c*9+8];
    const float bi = bias[c];
    const float* r0 = (h > 0)  ? xp + (h-1)*64 : 0;
    const float* r1 = xp + h*64;
    const float* r2 = (h < 63) ? xp + (h+1)*64 : 0;
    float a0 = 0.f, a1 = 0.f, a2 = 0.f;
    float m0 = r0 ? r0[0] : 0.f;
    float m1 = r1[0];
    float m2 = r2 ? r2[0] : 0.f;
    __half* ob = outp + (size_t)bh * 64 * 768 + c;
    #pragma unroll 4
    for (int w = 0; w < 64; w++) {
        float n0, n1, n2;
        if (w < 63) {
            n0 = r0 ? r0[w+1] : 0.f;
            n1 = r1[w+1];
            n2 = r2 ? r2[w+1] : 0.f;
        } else { n0 = n1 = n2 = 0.f; }
        float acc = bi
            + a0*k0 + m0*k1 + n0*k2
            + a1*k3 + m1*k4 + n1*k5
            + a2*k6 + m2*k7 + n2*k8;
        __half hi, lo; split2h(acc, hi, lo);
        ob[(size_t)w * 768]       = hi;
        ob[(size_t)w * 768 + 384] = lo;
        a0 = m0; a1 = m1; a2 = m2;
        m0 = n0; m1 = n1; m2 = n2;
    }
}

// ================================================================ mma.sync split-fp16 GEMM, BK=64, 3-stage cp.async pipeline
// 128x128 tile, 512 threads (16 warps, warp tile 32x32)
// stage = [A sub0 16K][A sub1 16K][B sub0 16K][B sub1 16K] = 64KB; 3 stages = 192KB
// PROD==2: out = Ahi*Bhi + Alo*Bhi
// PROD==3: out = Ahi*Bhi + Ahi*Blo + Alo*Bhi
template<int MODE, int PROD>
__global__ void __launch_bounds__(512) tgemm_k(
    const __half* __restrict__ A, const __half* __restrict__ Wt,
    const float* __restrict__ bias,
    float* __restrict__ o0, float* __restrict__ o1,
    const float* __restrict__ cp_, const float* __restrict__ ap)
{
    extern __shared__ char sm[];
    const int t    = threadIdx.x;
    const int wid  = t >> 5;
    const int lane = t & 31;
    const int m0 = blockIdx.y * 128;
    const int n0 = blockIdx.x * 128;
    const uint32_t smemBase = smem_u32(sm);

    // ---- loader: per 32-K sub-chunk 2048 16B units, 4 per thread (skip B-lo when PROD==2)
    const __half* srcP[4];
    uint32_t dstS[4];
    bool act[4];
    #pragma unroll
    for (int r = 0; r < 4; r++) {
        int u = t + 512 * r;
        int mat = u >> 10;
        int v = u & 1023;
        int row = v >> 3;
        int s7 = v & 7;
        act[r] = (PROD == 3) || (mat == 0) || (s7 < 4);
        const __half* base = mat ? (Wt + (size_t)(n0 + row) * 768)
                                 : (A  + (size_t)(m0 + row) * 768);
        int col = (s7 < 4) ? s7 * 8 : 384 + (s7 - 4) * 8;
        srcP[r] = base + col;
        dstS[r] = smemBase + mat * 32768 + swz((unsigned)(row * 128 + s7 * 16));
    }

    // issue one 64-K chunk (two 32-K sub-chunks) into stage STG
    #define TG_ISSUE(CH, STG) do {                                               \
        const unsigned so_ = (unsigned)(STG) * 65536u;                           \
        _Pragma("unroll")                                                        \
        for (int r_ = 0; r_ < 4; r_++)                                           \
            if (act[r_]) {                                                       \
                cp16(dstS[r_] + so_,          srcP[r_] + (CH) * 64);             \
                cp16(dstS[r_] + so_ + 16384u, srcP[r_] + (CH) * 64 + 32);        \
            }                                                                    \
        cp_commit();                                                             \
    } while (0)

    TG_ISSUE(0, 0);
    TG_ISSUE(1, 1);

    const int wm = wid & 3;
    const int wn = wid >> 2;
    float acc[2][4][4];
    #pragma unroll
    for (int i = 0; i < 2; i++)
        #pragma unroll
        for (int j = 0; j < 4; j++)
            #pragma unroll
            for (int q = 0; q < 4; q++) acc[i][j][q] = 0.f;

    const int lrow = lane & 15;
    const int lkc  = (lane >> 4) << 3;

    const int NCH = KDIM / 64;   // 6
    int stg = 0;                 // ch % 3
    int istg = 2;                // (ch+2) % 3
    for (int ch = 0; ch < NCH; ch++) {
        if (ch < NCH - 1) cp_wait<1>(); else cp_wait<0>();
        __syncthreads();
        if (ch + 2 < NCH) TG_ISSUE(ch + 2, istg);

        #pragma unroll
        for (int sub = 0; sub < 2; sub++) {
            const uint32_t aS = smemBase + (unsigned)stg * 65536u + (unsigned)sub * 16384u;
            const uint32_t bS = aS + 32768u;
            #pragma unroll
            for (int ks = 0; ks < 2; ks++) {
                const unsigned kc2 = (unsigned)(ks * 16 + lkc) * 2;
                uint32_t ahi[2][4], alo[2][4];
                #pragma unroll
                for (int mt = 0; mt < 2; mt++) {
                    unsigned off = (unsigned)(wm * 32 + mt * 16 + lrow) * 128 + kc2;
                    ldsm4(ahi[mt], aS + swz(off));
                    ldsm4(alo[mt], aS + swz(off + 64));
                }
                uint32_t bhi[2][4];
                #pragma unroll
                for (int ng = 0; ng < 2; ng++) {
                    unsigned off = (unsigned)(wn * 32 + ng * 16 + lrow) * 128 + kc2;
                    ldsm4(bhi[ng], bS + swz(off));
                }
                #pragma unroll
                for (int mt = 0; mt < 2; mt++)
                    #pragma unroll
                    for (int ng = 0; ng < 2; ng++) {
                        mma16816h(acc[mt][2*ng],   ahi[mt], bhi[ng][0], bhi[ng][2]);
                        mma16816h(acc[mt][2*ng+1], ahi[mt], bhi[ng][1], bhi[ng][3]);
                    }
                #pragma unroll
                for (int mt = 0; mt < 2; mt++)
                    #pragma unroll
                    for (int ng = 0; ng < 2; ng++) {
                        mma16816h(acc[mt][2*ng],   alo[mt], bhi[ng][0], bhi[ng][2]);
                        mma16816h(acc[mt][2*ng+1], alo[mt], bhi[ng][1], bhi[ng][3]);
                    }
                if (PROD == 3) {
                    uint32_t blo[2][4];
                    #pragma unroll
                    for (int ng = 0; ng < 2; ng++) {
                        unsigned off = (unsigned)(wn * 32 + ng * 16 + lrow) * 128 + kc2;
                        ldsm4(blo[ng], bS + swz(off + 64));
                    }
                    #pragma unroll
                    for (int mt = 0; mt < 2; mt++)
                        #pragma unroll
                        for (int ng = 0; ng < 2; ng++) {
                            mma16816h(acc[mt][2*ng],   ahi[mt], blo[ng][0], blo[ng][2]);
                            mma16816h(acc[mt][2*ng+1], ahi[mt], blo[ng][1], blo[ng][3]);
                        }
                }
            }
        }
        stg  = (stg  == 2) ? 0 : stg  + 1;
        istg = (istg == 2) ? 0 : istg + 1;
    }
    #undef TG_ISSUE

    // ---- epilogue: warp tile 32x32
    const int qr = lane >> 2;
    const int qc = lane & 3;
    const int mbw = m0 + wm * 32;
    const int nbw = n0 + wn * 32;

    float cc0 = 0.f, css = 0.f;
    if (MODE == 1) {
        cc0 = cp_[0];
        css = (1.0f + 0.5f * ap[0]) / (cc0 + 1e-8f);
    }

    #pragma unroll
    for (int mt = 0; mt < 2; mt++) {
        #pragma unroll
        for (int half = 0; half < 2; half++) {
            const int m = mbw + mt * 16 + qr + half * 8;
            float ee = 0.f;
            if (MODE == 1) {
                const float kp = 3.14159265358979323846f / 64.0f;
                int hh = (m >> 6) & 63, ww = m & 63;
                ee = kp * kp * (float)(hh * hh + ww * ww);
            }
            #pragma unroll
            for (int nt = 0; nt < 4; nt++) {
                const int n = nbw + nt * 8 + qc * 2;
                float v0 = acc[mt][nt][half * 2 + 0] + __ldg(bias + n);
                float v1 = acc[mt][nt][half * 2 + 1] + __ldg(bias + n + 1);
                if (MODE == 0) {
                    if (n0 >= 384) {
                        v0 *= 1.0f / (1.0f + __expf(-v0));
                        v1 *= 1.0f / (1.0f + __expf(-v1));
                        *(float2*)(o1 + (size_t)m * 384 + (n - 384)) = make_float2(v0, v1);
                    } else {
                        *(float2*)(o0 + (size_t)m * 384 + n) = make_float2(v0, v1);
                    }
                } else if (MODE == 1) {
                    float tg0 = 0.5f * v0 * (1.0f + erff(v0 * 0.70710678118654752f));
                    float tg1 = 0.5f * v1 * (1.0f + erff(v1 * 0.70710678118654752f));
                    float ct0 = cc0 * tg0, ct1 = cc0 * tg1;
                    float r0 = (__cosf(ct0) + __sinf(ct0) * css) * __expf(-ee * tg0);
                    float r1 = (__cosf(ct1) + __sinf(ct1) * css) * __expf(-ee * tg1);
                    *(float2*)(o0 + (size_t)m * 384 + n) = make_float2(r0, r1);
                } else {
                    *(float2*)(o0 + (size_t)m * 384 + n) = make_float2(v0, v1);
                }
            }
        }
    }
}

// ================================================================ tensorized 64-pt cosine transform (split bf16)
#define DT_SMEM (17408*2 + 9216*2)
template<bool FWD, bool MOD>
__global__ void __launch_bounds__(256) dctT_k(
    float* __restrict__ out, const float* __restrict__ X,
    const float* __restrict__ S, int ldRow)
{
    extern __shared__ char ds[];
    __nv_bfloat16* sXhi = (__nv_bfloat16*)ds;
    __nv_bfloat16* sXlo = (__nv_bfloat16*)(ds + 17408);
    __nv_bfloat16* sWp  = (__nv_bfloat16*)(ds + 34816);
    const int t = threadIdx.x;
    const int bb = blockIdx.y;
    const int j0 = blockIdx.x << 7;

    {
        const uint4* src = (const uint4*)&g_Wsp[FWD ? 0 : 1][0][0][0];
        uint4* dst = (uint4*)sWp;
        for (int u = t; u < 1152; u += 256) dst[u] = src[u];
    }
    const float* Xb = X + (size_t)bb * 64 * ldRow + j0;
    #pragma unroll
    for (int it = 0; it < 8; it++) {
        int idx = t + 256 * it;
        int row = idx >> 5, c4 = (idx & 31) << 2;
        float4 v = *(const float4*)(Xb + (size_t)row * ldRow + c4);
        __nv_bfloat16 h0,h1,h2,h3,l0,l1,l2,l3;
        split2(v.x,h0,l0); split2(v.y,h1,l1); split2(v.z,h2,l2); split2(v.w,h3,l3);
        unsigned hw0 = ((unsigned)__bfloat16_as_ushort(h1) << 16) | __bfloat16_as_ushort(h0);
        unsigned hw1 = ((unsigned)__bfloat16_as_ushort(h3) << 16) | __bfloat16_as_ushort(h2);
        unsigned lw0 = ((unsigned)__bfloat16_as_ushort(l1) << 16) | __bfloat16_as_ushort(l0);
        unsigned lw1 = ((unsigned)__bfloat16_as_ushort(l3) << 16) | __bfloat16_as_ushort(l2);
        *(uint2*)(sXhi + row * 136 + c4) = make_uint2(hw0, hw1);
        *(uint2*)(sXlo + row * 136 + c4) = make_uint2(lw0, lw1);
    }
    __syncthreads();

    const int wid = t >> 5, lane = t & 31;
    const int wm = wid & 1, wn = wid >> 1;
    const uint32_t xhiB = smem_u32(sXhi), xloB = smem_u32(sXlo);
    const uint32_t whiB = smem_u32(sWp),  wloB = whiB + 9216;

    float acc[2][4][4];
    #pragma unroll
    for (int i = 0; i < 2; i++)
        #pragma unroll
        for (int j = 0; j < 4; j++)
            #pragma unroll
            for (int q = 0; q < 4; q++) acc[i][j][q] = 0.f;

    const int lr = lane & 15, lh = lane >> 4;
    #pragma unroll
    for (int ks = 0; ks < 4; ks++) {
        uint32_t ahi[2][4], alo[2][4];
        #pragma unroll
        for (int mt = 0; mt < 2; mt++) {
            unsigned off = (unsigned)(wm * 32 + mt * 16 + lr) * 144 + (unsigned)(ks * 16 + lh * 8) * 2;
            ldsm4(ahi[mt], whiB + off);
            ldsm4(alo[mt], wloB + off);
        }
        uint32_t bhi[2][4], blo[2][4];
        #pragma unroll
        for (int ng = 0; ng < 2; ng++) {
            unsigned off = (unsigned)(ks * 16 + lr) * 272 + (unsigned)(wn * 32 + ng * 16 + lh * 8) * 2;
            ldsm4t(bhi[ng], xhiB + off);
            ldsm4t(blo[ng], xloB + off);
        }
        #pragma unroll
        for (int mt = 0; mt < 2; mt++)
            #pragma unroll
            for (int ng = 0; ng < 2; ng++) {
                mma16816(acc[mt][2*ng],   ahi[mt], bhi[ng][0], bhi[ng][1]);
                mma16816(acc[mt][2*ng+1], ahi[mt], bhi[ng][2], bhi[ng][3]);
            }
        #pragma unroll
        for (int mt = 0; mt < 2; mt++)
            #pragma unroll
            for (int ng = 0; ng < 2; ng++) {
                mma16816(acc[mt][2*ng],   ahi[mt], blo[ng][0], blo[ng][1]);
                mma16816(acc[mt][2*ng+1], ahi[mt], blo[ng][2], blo[ng][3]);
            }
        #pragma unroll
        for (int mt = 0; mt < 2; mt++)
            #pragma unroll
            for (int ng = 0; ng < 2; ng++) {
                mma16816(acc[mt][2*ng],   alo[mt], bhi[ng][0], bhi[ng][1]);
                mma16816(acc[mt][2*ng+1], alo[mt], bhi[ng][2], bhi[ng][3]);
            }
    }

    const int qr = lane >> 2, qc = lane & 3;
    float* ob = out + (size_t)bb * 64 * ldRow + j0;
    const float* sb = S + (size_t)bb * 64 * ldRow + j0;
    #pragma unroll
    for (int mt = 0; mt < 2; mt++)
        #pragma unroll
        for (int half = 0; half < 2; half++) {
            const int i = wm * 32 + mt * 16 + qr + half * 8;
            #pragma unroll
            for (int ng = 0; ng < 4; ng++) {
                const int j = wn * 32 + ng * 8 + qc * 2;
                float v0 = acc[mt][ng][half * 2 + 0];
                float v1 = acc[mt][ng][half * 2 + 1];
                if (MOD) {
                    float2 s2 = *(const float2*)(sb + (size_t)i * ldRow + j);
                    v0 *= s2.x; v1 *= s2.y;
                }
                *(float2*)(ob + (size_t)i * ldRow + j) = make_float2(v0, v1);
            }
        }
}

// ================================================================ fused IDCT(w) + LayerNorm + silu-gate + fp16 split
#define DL_SMEM ((4096 + 2*64*392) * 4)
__global__ void __launch_bounds__(256) dct_ln_k(
    const float* __restrict__ X, const float* __restrict__ z,
    const float* __restrict__ gam, const float* __restrict__ bet,
    __half* __restrict__ dst)
{
    extern __shared__ float s[];
    float* Ws = s;
    float* Xs = s + 4096;
    float* Os = s + 4096 + 64*392;
    const int t = threadIdx.x;
    const int bb = blockIdx.x;

    for (int idx = t; idx < 4096; idx += 256) Ws[idx] = g_W[idx];
    const float* Xb = X + (size_t)bb * 24576;
    for (int f = t; f < 6144; f += 256) {
        int row = f / 96, col = (f - row * 96) * 4;
        *(float4*)&Xs[row * 392 + col] = *(const float4*)(Xb + (size_t)row * 384 + col);
    }
    __syncthreads();

    const int wpair = t >> 3;
    const int cg = t & 7;
    const int w0 = wpair * 2;
    #pragma unroll
    for (int jb = 0; jb < 4; jb++) {
        float a0[12], a1[12];
        #pragma unroll
        for (int j = 0; j < 12; j++) { a0[j] = 0.f; a1[j] = 0.f; }
        #pragma unroll 4
        for (int m = 0; m < 64; m++) {
            float wv0 = Ws[m * 64 + w0];
            float wv1 = Ws[m * 64 + w0 + 1];
            const float* xr = &Xs[m * 392 + cg + 8 * (jb * 12)];
            #pragma unroll
            for (int j = 0; j < 12; j++) {
                float xv = xr[8 * j];
                a0[j] = fmaf(wv0, xv, a0[j]);
                a1[j] = fmaf(wv1, xv, a1[j]);
            }
        }
        #pragma unroll
        for (int j = 0; j < 12; j++) {
            int c = cg + 8 * (jb * 12 + j);
            Os[w0 * 392 + c]       = a0[j];
            Os[(w0 + 1) * 392 + c] = a1[j];
        }
    }
    __syncthreads();

    const int warp = t >> 5, lane = t & 31;
    float gv[12], bv[12];
    #pragma unroll
    for (int k = 0; k < 12; k++) { gv[k] = gam[lane + 32*k]; bv[k] = bet[lane + 32*k]; }
    for (int w = warp; w < 64; w += 8) {
        float vals[12], sum = 0.f;
        #pragma unroll
        for (int k = 0; k < 12; k++) { vals[k] = Os[w * 392 + lane + 32*k]; sum += vals[k]; }
        #pragma unroll
        for (int o = 16; o; o >>= 1) sum += __shfl_xor_sync(0xffffffffu, sum, o);
        float mu = sum * (1.0f / 384.0f);
        float q = 0.f;
        #pragma unroll
        for (int k = 0; k < 12; k++) { float d = vals[k] - mu; q = fmaf(d, d, q); }
        #pragma unroll
        for (int o = 16; o; o >>= 1) q += __shfl_xor_sync(0xffffffffu, q, o);
        float inv = rsqrtf(q * (1.0f / 384.0f) + 1e-5f);
        const size_t pixel = (size_t)bb * 64 + w;
        const float* zr = z + pixel * 384;
        __half* dr = dst + pixel * 768;
        #pragma unroll
        for (int k = 0; k < 12; k++) {
            int c = lane + 32*k;
            float o = ((vals[k] - mu) * inv * gv[k] + bv[k]) * zr[c];
            __half hi, lo; split2h(o, hi, lo);
            dr[c] = hi; dr[384 + c] = lo;
        }
    }
}

// ================================================================ launcher
#define TG_SMEM 196608

extern "C" void kernel_launch(void* const* d_in, const int* in_sizes, int n_in,
                              void* d_out, int out_size)
{
    const float* x     = (const float*)d_in[0];
    const float* freq  = (const float*)d_in[1];
    const float* dw_w  = (const float*)d_in[2];
    const float* dw_b  = (const float*)d_in[3];
    const float* lin_w = (const float*)d_in[4];
    const float* lin_b = (const float*)d_in[5];
    const float* tok_w = (const float*)d_in[6];
    const float* tok_b = (const float*)d_in[7];
    const float* ln_g  = (const float*)d_in[8];
    const float* ln_b  = (const float*)d_in[9];
    const float* out_w = (const float*)d_in[10];
    const float* out_b = (const float*)d_in[11];
    const float* cp    = (const float*)d_in[12];
    const float* ap    = (const float*)d_in[13];
    float* out = (float*)d_out;

    float *pxs, *pz, *ps, *pf1;
    __half *pxd, *pfq, *pf2, *pwl, *pwt, *pwo;
    cudaGetSymbolAddress((void**)&pxs, g_xs);
    cudaGetSymbolAddress((void**)&pz,  g_z);
    cudaGetSymbolAddress((void**)&ps,  g_s);
    cudaGetSymbolAddress((void**)&pf1, g_f1);
    cudaGetSymbolAddress((void**)&pxd, g_xd);
    cudaGetSymbolAddress((void**)&pfq, g_fq);
    cudaGetSymbolAddress((void**)&pf2, g_f2);
    cudaGetSymbolAddress((void**)&pwl, g_wl);
    cudaGetSymbolAddress((void**)&pwt, g_wt);
    cudaGetSymbolAddress((void**)&pwo, g_wo);

    cudaFuncSetAttribute((const void*)(tgemm_k<0,2>), cudaFuncAttributeMaxDynamicSharedMemorySize, TG_SMEM);
    cudaFuncSetAttribute((const void*)(tgemm_k<1,3>), cudaFuncAttributeMaxDynamicSharedMemorySize, TG_SMEM);
    cudaFuncSetAttribute((const void*)(tgemm_k<2,2>), cudaFuncAttributeMaxDynamicSharedMemorySize, TG_SMEM);
    cudaFuncSetAttribute((const void*)(dctT_k<true,  false>), cudaFuncAttributeMaxDynamicSharedMemorySize, DT_SMEM);
    cudaFuncSetAttribute((const void*)(dctT_k<true,  true >), cudaFuncAttributeMaxDynamicSharedMemorySize, DT_SMEM);
    cudaFuncSetAttribute((const void*)(dctT_k<false, false>), cudaFuncAttributeMaxDynamicSharedMemorySize, DT_SMEM);
    cudaFuncSetAttribute((const void*)dct_ln_k,   cudaFuncAttributeMaxDynamicSharedMemorySize, DL_SMEM);

    // launch order: tgemm_k<0> is the 6th launch (ncu -s 5 -c 1 captures it)
    build_w_k<<<16, 256>>>();                                               // 1
    split_k<<<(768*96 + 255)/256, 256>>>(lin_w, pwl, 768*96);               // 2
    dwconv_k<<<1024, 384>>>(x, dw_w, dw_b, pxd);                            // 3
    split_k<<<(384*96 + 255)/256, 256>>>(tok_w, pwt, 384*96);               // 4
    split_k<<<(65536*96 + 255)/256, 256>>>(freq, pfq, 65536*96);            // 5
    // xz = xd @ lin_w^T : xs + silu(z)   (2-product fp16)                  // 6 <- profiled
    tgemm_k<0,2><<<dim3(6, 512), 512, TG_SMEM>>>(pxd, pwl, lin_b, pxs, pz, nullptr, nullptr);
    split_k<<<(384*96 + 255)/256, 256>>>(out_w, pwo, 384*96);               // 7
    // s = modulation(gelu(freq @ tok_w^T))  (3-product fp16)
    tgemm_k<1,3><<<dim3(3, 512), 512, TG_SMEM>>>(pfq, pwt, tok_b, ps, nullptr, cp, ap);
    // DCT over h (tensorized bf16 3-product)
    dctT_k<true,  false><<<dim3(192, 16),   256, DT_SMEM>>>(pf1, pxs, pf1, 24576);
    // DCT over w + modulate by s
    dctT_k<true,  true ><<<dim3(3,  1024),  256, DT_SMEM>>>((float*)pf2, pf1, ps, 384);
    // IDCT over n
    dctT_k<false, false><<<dim3(192, 16),   256, DT_SMEM>>>(pf1, (float*)pf2, pf1, 24576);
    // fused IDCT over m + LayerNorm + silu-gate -> split fp16
    dct_ln_k<<<1024, 256, DL_SMEM>>>(pf1, pz, ln_g, ln_b, pf2);
    // out = xo @ out_w^T + out_b  (2-product fp16)
    tgemm_k<2,2><<<dim3(3, 512), 512, TG_SMEM>>>(pf2, pwo, out_b, out, nullptr, nullptr, nullptr);
}

// round 13
// speedup vs baseline: 1.3887x; 1.0994x over previous
#include <cuda_runtime.h>
#include <cuda_bf16.h>
#include <cuda_fp16.h>
#include <math.h>
#include <stdint.h>

#define KDIM 384
#define NEL 25165824   // 16*64*64*384

// fp32 buffers
static __device__ float g_xs[NEL];      // xs (pre-DCT)
static __device__ float g_z [NEL];      // silu(z)
static __device__ float g_s [NEL];      // modulation scalar
static __device__ float g_f1[NEL];
static __device__ float g_W[4096];      // 64x64 DCT-II matrix (fp32, for dct_ln)
// bf16 split W planes for DCT: [orient][plane hi/lo][64][72]
static __device__ __nv_bfloat16 g_Wsp[2][2][64][72];
// fp16 split buffers ([row][768]: hi 384 | lo 384)
static __device__ float g_xd[NEL];      // split conv output
static __device__ float g_fq[NEL];      // split freq_embed
static __device__ float g_f2[NEL];      // split LN output / fp32 scratch
static __device__ float g_wl[294912];   // split lin_w  (768 rows)
static __device__ float g_wt[147456];   // split tok_w  (384 rows)
static __device__ float g_wo[147456];   // split out_w  (384 rows)

// ================================================================ helpers
__device__ __forceinline__ uint32_t smem_u32(const void* p) {
    uint32_t a;
    asm("{ .reg .u64 t; cvta.to.shared.u64 t, %1; cvt.u32.u64 %0, t; }" : "=r"(a) : "l"(p));
    return a;
}
__device__ __forceinline__ void ldsm4(uint32_t (&r)[4], uint32_t addr) {
    asm volatile("ldmatrix.sync.aligned.m8n8.x4.shared.b16 {%0,%1,%2,%3}, [%4];"
                 : "=r"(r[0]), "=r"(r[1]), "=r"(r[2]), "=r"(r[3]) : "r"(addr));
}
__device__ __forceinline__ void ldsm4t(uint32_t (&r)[4], uint32_t addr) {
    asm volatile("ldmatrix.sync.aligned.m8n8.x4.trans.shared.b16 {%0,%1,%2,%3}, [%4];"
                 : "=r"(r[0]), "=r"(r[1]), "=r"(r[2]), "=r"(r[3]) : "r"(addr));
}
// bf16 mma (DCT chain)
__device__ __forceinline__ void mma16816(float (&d)[4], const uint32_t (&a)[4],
                                         uint32_t b0, uint32_t b1) {
    asm volatile(
        "mma.sync.aligned.m16n8k16.row.col.f32.bf16.bf16.f32 "
        "{%0,%1,%2,%3}, {%4,%5,%6,%7}, {%8,%9}, {%0,%1,%2,%3};"
        : "+f"(d[0]), "+f"(d[1]), "+f"(d[2]), "+f"(d[3])
        : "r"(a[0]), "r"(a[1]), "r"(a[2]), "r"(a[3]), "r"(b0), "r"(b1));
}
// fp16 mma (GEMMs)
__device__ __forceinline__ void mma16816h(float (&d)[4], const uint32_t (&a)[4],
                                          uint32_t b0, uint32_t b1) {
    asm volatile(
        "mma.sync.aligned.m16n8k16.row.col.f32.f16.f16.f32 "
        "{%0,%1,%2,%3}, {%4,%5,%6,%7}, {%8,%9}, {%0,%1,%2,%3};"
        : "+f"(d[0]), "+f"(d[1]), "+f"(d[2]), "+f"(d[3])
        : "r"(a[0]), "r"(a[1]), "r"(a[2]), "r"(a[3]), "r"(b0), "r"(b1));
}
__device__ __forceinline__ unsigned swz(unsigned off) {
    return off ^ ((off >> 3) & 0x70);
}
__device__ __forceinline__ void cp16(uint32_t dst, const void* src) {
    asm volatile("cp.async.cg.shared.global [%0], [%1], 16;" :: "r"(dst), "l"(src) : "memory");
}
__device__ __forceinline__ void cp_commit() {
    asm volatile("cp.async.commit_group;" ::: "memory");
}
template<int N> __device__ __forceinline__ void cp_wait() {
    asm volatile("cp.async.wait_group %0;" :: "n"(N) : "memory");
}
__device__ __forceinline__ void split2(float v, __nv_bfloat16& h, __nv_bfloat16& l) {
    h = __float2bfloat16(v);
    l = __float2bfloat16(v - __bfloat162float(h));
}
__device__ __forceinline__ void split2h(float v, __half& h, __half& l) {
    h = __float2half_rn(v);
    l = __float2half_rn(v - __half2float(h));
}

// ================================================================ build W
__global__ void build_w_k() {
    int i = blockIdx.x * 256 + threadIdx.x;
    int n = i >> 6, h = i & 63;
    float v = cosf((float)n * (((float)h + 0.5f) * (3.14159265358979323846f / 64.0f)))
            * 0.17677669529663687f;
    if (n == 0) v *= 0.70710678118654752f;
    g_W[i] = v;
    __nv_bfloat16 hi, lo; split2(v, hi, lo);
    g_Wsp[0][0][n][h] = hi;
    g_Wsp[0][1][n][h] = lo;
    g_Wsp[1][0][h][n] = hi;
    g_Wsp[1][1][h][n] = lo;
}

// ================================================================ split fp32 [rows][384] -> fp16 [rows][768] (hi|lo)
__global__ void split_k(const float* __restrict__ src, __half* __restrict__ dst, int n4) {
    int i = blockIdx.x * 256 + threadIdx.x;
    if (i >= n4) return;
    int row = i / 96;
    int col = (i - row * 96) * 4;
    float4 v = *(const float4*)(src + (size_t)row * 384 + col);
    __half h0,h1,h2,h3,l0,l1,l2,l3;
    split2h(v.x,h0,l0); split2h(v.y,h1,l1); split2h(v.z,h2,l2); split2h(v.w,h3,l3);
    __half* d = dst + (size_t)row * 768 + col;
    d[0]=h0; d[1]=h1; d[2]=h2; d[3]=h3;
    d[384]=l0; d[385]=l1; d[386]=l2; d[387]=l3;
}

// ================================================================ depthwise conv 3x3, NCHW -> NHWC split fp16
__global__ void dwconv_k(const float* __restrict__ x, const float* __restrict__ w9,
                         const float* __restrict__ bias, __half* __restrict__ outp)
{
    const int bh = blockIdx.x;
    const int c  = threadIdx.x;
    const int b  = bh >> 6, h = bh & 63;
    const float* xp = x + (size_t)(b * 384 + c) * 64 * 64;
    float k0 = w9[c*9+0], k1 = w9[c*9+1], k2 = w9[c*9+2];
    float k3 = w9[c*9+3], k4 = w9[c*9+4], k5 = w9[c*9+5];
    float k6 = w9[c*9+6], k7 = w9[c*9+7], k8 = w9[c*9+8];
    const float bi = bias[c];
    const float* r0 = (h > 0)  ? xp + (h-1)*64 : 0;
    const float* r1 = xp + h*64;
    const float* r2 = (h < 63) ? xp + (h+1)*64 : 0;
    float a0 = 0.f, a1 = 0.f, a2 = 0.f;
    float m0 = r0 ? r0[0] : 0.f;
    float m1 = r1[0];
    float m2 = r2 ? r2[0] : 0.f;
    __half* ob = outp + (size_t)bh * 64 * 768 + c;
    #pragma unroll 4
    for (int w = 0; w < 64; w++) {
        float n0, n1, n2;
        if (w < 63) {
            n0 = r0 ? r0[w+1] : 0.f;
            n1 = r1[w+1];
            n2 = r2 ? r2[w+1] : 0.f;
        } else { n0 = n1 = n2 = 0.f; }
        float acc = bi
            + a0*k0 + m0*k1 + n0*k2
            + a1*k3 + m1*k4 + n1*k5
            + a2*k6 + m2*k7 + n2*k8;
        __half hi, lo; split2h(acc, hi, lo);
        ob[(size_t)w * 768]       = hi;
        ob[(size_t)w * 768 + 384] = lo;
        a0 = m0; a1 = m1; a2 = m2;
        m0 = n0; m1 = n1; m2 = n2;
    }
}

// ================================================================ mma.sync fp16 GEMM, BK=64, 3-stage cp.async pipeline
// 128x128 tile, 512 threads (16 warps, warp tile 32x32)
// stage = [A sub0 16K][A sub1 16K][B sub0 16K][B sub1 16K] = 64KB; 3 stages = 192KB
// PROD==1: out = Ahi*Bhi                      (both rounded to fp16)
// PROD==2: out = Ahi*Bhi + Alo*Bhi
// PROD==3: out = Ahi*Bhi + Ahi*Blo + Alo*Bhi
template<int MODE, int PROD>
__global__ void __launch_bounds__(512) tgemm_k(
    const __half* __restrict__ A, const __half* __restrict__ Wt,
    const float* __restrict__ bias,
    float* __restrict__ o0, float* __restrict__ o1,
    const float* __restrict__ cp_, const float* __restrict__ ap)
{
    extern __shared__ char sm[];
    const int t    = threadIdx.x;
    const int wid  = t >> 5;
    const int lane = t & 31;
    const int m0 = blockIdx.y * 128;
    const int n0 = blockIdx.x * 128;
    const uint32_t smemBase = smem_u32(sm);

    // ---- loader: per 32-K sub-chunk 2048 16B units, 4 per thread
    //      activity mask drops lo-plane lines per PROD
    const __half* srcP[4];
    uint32_t dstS[4];
    bool act[4];
    #pragma unroll
    for (int r = 0; r < 4; r++) {
        int u = t + 512 * r;
        int mat = u >> 10;
        int v = u & 1023;
        int row = v >> 3;
        int s7 = v & 7;
        act[r] = (PROD == 3) || (s7 < 4) || (PROD == 2 && mat == 0);
        const __half* base = mat ? (Wt + (size_t)(n0 + row) * 768)
                                 : (A  + (size_t)(m0 + row) * 768);
        int col = (s7 < 4) ? s7 * 8 : 384 + (s7 - 4) * 8;
        srcP[r] = base + col;
        dstS[r] = smemBase + mat * 32768 + swz((unsigned)(row * 128 + s7 * 16));
    }

    // issue one 64-K chunk (two 32-K sub-chunks) into stage STG
    #define TG_ISSUE(CH, STG) do {                                               \
        const unsigned so_ = (unsigned)(STG) * 65536u;                           \
        _Pragma("unroll")                                                        \
        for (int r_ = 0; r_ < 4; r_++)                                           \
            if (act[r_]) {                                                       \
                cp16(dstS[r_] + so_,          srcP[r_] + (CH) * 64);             \
                cp16(dstS[r_] + so_ + 16384u, srcP[r_] + (CH) * 64 + 32);        \
            }                                                                    \
        cp_commit();                                                             \
    } while (0)

    TG_ISSUE(0, 0);
    TG_ISSUE(1, 1);

    const int wm = wid & 3;
    const int wn = wid >> 2;
    float acc[2][4][4];
    #pragma unroll
    for (int i = 0; i < 2; i++)
        #pragma unroll
        for (int j = 0; j < 4; j++)
            #pragma unroll
            for (int q = 0; q < 4; q++) acc[i][j][q] = 0.f;

    const int lrow = lane & 15;
    const int lkc  = (lane >> 4) << 3;

    const int NCH = KDIM / 64;   // 6
    int stg = 0;                 // ch % 3
    int istg = 2;                // (ch+2) % 3
    for (int ch = 0; ch < NCH; ch++) {
        if (ch < NCH - 1) cp_wait<1>(); else cp_wait<0>();
        __syncthreads();
        if (ch + 2 < NCH) TG_ISSUE(ch + 2, istg);

        #pragma unroll
        for (int sub = 0; sub < 2; sub++) {
            const uint32_t aS = smemBase + (unsigned)stg * 65536u + (unsigned)sub * 16384u;
            const uint32_t bS = aS + 32768u;
            #pragma unroll
            for (int ks = 0; ks < 2; ks++) {
                const unsigned kc2 = (unsigned)(ks * 16 + lkc) * 2;
                uint32_t ahi[2][4];
                #pragma unroll
                for (int mt = 0; mt < 2; mt++) {
                    unsigned off = (unsigned)(wm * 32 + mt * 16 + lrow) * 128 + kc2;
                    ldsm4(ahi[mt], aS + swz(off));
                }
                uint32_t bhi[2][4];
                #pragma unroll
                for (int ng = 0; ng < 2; ng++) {
                    unsigned off = (unsigned)(wn * 32 + ng * 16 + lrow) * 128 + kc2;
                    ldsm4(bhi[ng], bS + swz(off));
                }
                #pragma unroll
                for (int mt = 0; mt < 2; mt++)
                    #pragma unroll
                    for (int ng = 0; ng < 2; ng++) {
                        mma16816h(acc[mt][2*ng],   ahi[mt], bhi[ng][0], bhi[ng][2]);
                        mma16816h(acc[mt][2*ng+1], ahi[mt], bhi[ng][1], bhi[ng][3]);
                    }
                if (PROD >= 2) {
                    uint32_t alo[2][4];
                    #pragma unroll
                    for (int mt = 0; mt < 2; mt++) {
                        unsigned off = (unsigned)(wm * 32 + mt * 16 + lrow) * 128 + kc2;
                        ldsm4(alo[mt], aS + swz(off + 64));
                    }
                    #pragma unroll
                    for (int mt = 0; mt < 2; mt++)
                        #pragma unroll
                        for (int ng = 0; ng < 2; ng++) {
                            mma16816h(acc[mt][2*ng],   alo[mt], bhi[ng][0], bhi[ng][2]);
                            mma16816h(acc[mt][2*ng+1], alo[mt], bhi[ng][1], bhi[ng][3]);
                        }
                }
                if (PROD == 3) {
                    uint32_t ahib[2][4];
                    #pragma unroll
                    for (int mt = 0; mt < 2; mt++) ahib[mt][0] = 0; // (unused placeholder)
                    uint32_t blo[2][4];
                    #pragma unroll
                    for (int ng = 0; ng < 2; ng++) {
                        unsigned off = (unsigned)(wn * 32 + ng * 16 + lrow) * 128 + kc2;
                        ldsm4(blo[ng], bS + swz(off + 64));
                    }
                    #pragma unroll
                    for (int mt = 0; mt < 2; mt++)
                        #pragma unroll
                        for (int ng = 0; ng < 2; ng++) {
                            mma16816h(acc[mt][2*ng],   ahi[mt], blo[ng][0], blo[ng][2]);
                            mma16816h(acc[mt][2*ng+1], ahi[mt], blo[ng][1], blo[ng][3]);
                        }
                }
            }
        }
        stg  = (stg  == 2) ? 0 : stg  + 1;
        istg = (istg == 2) ? 0 : istg + 1;
    }
    #undef TG_ISSUE

    // ---- epilogue: warp tile 32x32
    const int qr = lane >> 2;
    const int qc = lane & 3;
    const int mbw = m0 + wm * 32;
    const int nbw = n0 + wn * 32;

    float cc0 = 0.f, css = 0.f;
    if (MODE == 1) {
        cc0 = cp_[0];
        css = (1.0f + 0.5f * ap[0]) / (cc0 + 1e-8f);
    }

    #pragma unroll
    for (int mt = 0; mt < 2; mt++) {
        #pragma unroll
        for (int half = 0; half < 2; half++) {
            const int m = mbw + mt * 16 + qr + half * 8;
            float ee = 0.f;
            if (MODE == 1) {
                const float kp = 3.14159265358979323846f / 64.0f;
                int hh = (m >> 6) & 63, ww = m & 63;
                ee = kp * kp * (float)(hh * hh + ww * ww);
            }
            #pragma unroll
            for (int nt = 0; nt < 4; nt++) {
                const int n = nbw + nt * 8 + qc * 2;
                float v0 = acc[mt][nt][half * 2 + 0] + __ldg(bias + n);
                float v1 = acc[mt][nt][half * 2 + 1] + __ldg(bias + n + 1);
                if (MODE == 0) {
                    if (n0 >= 384) {
                        v0 *= 1.0f / (1.0f + __expf(-v0));
                        v1 *= 1.0f / (1.0f + __expf(-v1));
                        *(float2*)(o1 + (size_t)m * 384 + (n - 384)) = make_float2(v0, v1);
                    } else {
                        *(float2*)(o0 + (size_t)m * 384 + n) = make_float2(v0, v1);
                    }
                } else if (MODE == 1) {
                    float tg0 = 0.5f * v0 * (1.0f + erff(v0 * 0.70710678118654752f));
                    float tg1 = 0.5f * v1 * (1.0f + erff(v1 * 0.70710678118654752f));
                    float ct0 = cc0 * tg0, ct1 = cc0 * tg1;
                    float r0 = (__cosf(ct0) + __sinf(ct0) * css) * __expf(-ee * tg0);
                    float r1 = (__cosf(ct1) + __sinf(ct1) * css) * __expf(-ee * tg1);
                    *(float2*)(o0 + (size_t)m * 384 + n) = make_float2(r0, r1);
                } else {
                    *(float2*)(o0 + (size_t)m * 384 + n) = make_float2(v0, v1);
                }
            }
        }
    }
}

// ================================================================ tensorized 64-pt cosine transform (split bf16)
#define DT_SMEM (17408*2 + 9216*2)
template<bool FWD, bool MOD>
__global__ void __launch_bounds__(256) dctT_k(
    float* __restrict__ out, const float* __restrict__ X,
    const float* __restrict__ S, int ldRow)
{
    extern __shared__ char ds[];
    __nv_bfloat16* sXhi = (__nv_bfloat16*)ds;
    __nv_bfloat16* sXlo = (__nv_bfloat16*)(ds + 17408);
    __nv_bfloat16* sWp  = (__nv_bfloat16*)(ds + 34816);
    const int t = threadIdx.x;
    const int bb = blockIdx.y;
    const int j0 = blockIdx.x << 7;

    {
        const uint4* src = (const uint4*)&g_Wsp[FWD ? 0 : 1][0][0][0];
        uint4* dst = (uint4*)sWp;
        for (int u = t; u < 1152; u += 256) dst[u] = src[u];
    }
    const float* Xb = X + (size_t)bb * 64 * ldRow + j0;
    #pragma unroll
    for (int it = 0; it < 8; it++) {
        int idx = t + 256 * it;
        int row = idx >> 5, c4 = (idx & 31) << 2;
        float4 v = *(const float4*)(Xb + (size_t)row * ldRow + c4);
        __nv_bfloat16 h0,h1,h2,h3,l0,l1,l2,l3;
        split2(v.x,h0,l0); split2(v.y,h1,l1); split2(v.z,h2,l2); split2(v.w,h3,l3);
        unsigned hw0 = ((unsigned)__bfloat16_as_ushort(h1) << 16) | __bfloat16_as_ushort(h0);
        unsigned hw1 = ((unsigned)__bfloat16_as_ushort(h3) << 16) | __bfloat16_as_ushort(h2);
        unsigned lw0 = ((unsigned)__bfloat16_as_ushort(l1) << 16) | __bfloat16_as_ushort(l0);
        unsigned lw1 = ((unsigned)__bfloat16_as_ushort(l3) << 16) | __bfloat16_as_ushort(l2);
        *(uint2*)(sXhi + row * 136 + c4) = make_uint2(hw0, hw1);
        *(uint2*)(sXlo + row * 136 + c4) = make_uint2(lw0, lw1);
    }
    __syncthreads();

    const int wid = t >> 5, lane = t & 31;
    const int wm = wid & 1, wn = wid >> 1;
    const uint32_t xhiB = smem_u32(sXhi), xloB = smem_u32(sXlo);
    const uint32_t whiB = smem_u32(sWp),  wloB = whiB + 9216;

    float acc[2][4][4];
    #pragma unroll
    for (int i = 0; i < 2; i++)
        #pragma unroll
        for (int j = 0; j < 4; j++)
            #pragma unroll
            for (int q = 0; q < 4; q++) acc[i][j][q] = 0.f;

    const int lr = lane & 15, lh = lane >> 4;
    #pragma unroll
    for (int ks = 0; ks < 4; ks++) {
        uint32_t ahi[2][4], alo[2][4];
        #pragma unroll
        for (int mt = 0; mt < 2; mt++) {
            unsigned off = (unsigned)(wm * 32 + mt * 16 + lr) * 144 + (unsigned)(ks * 16 + lh * 8) * 2;
            ldsm4(ahi[mt], whiB + off);
            ldsm4(alo[mt], wloB + off);
        }
        uint32_t bhi[2][4], blo[2][4];
        #pragma unroll
        for (int ng = 0; ng < 2; ng++) {
            unsigned off = (unsigned)(ks * 16 + lr) * 272 + (unsigned)(wn * 32 + ng * 16 + lh * 8) * 2;
            ldsm4t(bhi[ng], xhiB + off);
            ldsm4t(blo[ng], xloB + off);
        }
        #pragma unroll
        for (int mt = 0; mt < 2; mt++)
            #pragma unroll
            for (int ng = 0; ng < 2; ng++) {
                mma16816(acc[mt][2*ng],   ahi[mt], bhi[ng][0], bhi[ng][1]);
                mma16816(acc[mt][2*ng+1], ahi[mt], bhi[ng][2], bhi[ng][3]);
            }
        #pragma unroll
        for (int mt = 0; mt < 2; mt++)
            #pragma unroll
            for (int ng = 0; ng < 2; ng++) {
                mma16816(acc[mt][2*ng],   ahi[mt], blo[ng][0], blo[ng][1]);
                mma16816(acc[mt][2*ng+1], ahi[mt], blo[ng][2], blo[ng][3]);
            }
        #pragma unroll
        for (int mt = 0; mt < 2; mt++)
            #pragma unroll
            for (int ng = 0; ng < 2; ng++) {
                mma16816(acc[mt][2*ng],   alo[mt], bhi[ng][0], bhi[ng][1]);
                mma16816(acc[mt][2*ng+1], alo[mt], bhi[ng][2], bhi[ng][3]);
            }
    }

    const int qr = lane >> 2, qc = lane & 3;
    float* ob = out + (size_t)bb * 64 * ldRow + j0;
    const float* sb = S + (size_t)bb * 64 * ldRow + j0;
    #pragma unroll
    for (int mt = 0; mt < 2; mt++)
        #pragma unroll
        for (int half = 0; half < 2; half++) {
            const int i = wm * 32 + mt * 16 + qr + half * 8;
            #pragma unroll
            for (int ng = 0; ng < 4; ng++) {
                const int j = wn * 32 + ng * 8 + qc * 2;
                float v0 = acc[mt][ng][half * 2 + 0];
                float v1 = acc[mt][ng][half * 2 + 1];
                if (MOD) {
                    float2 s2 = *(const float2*)(sb + (size_t)i * ldRow + j);
                    v0 *= s2.x; v1 *= s2.y;
                }
                *(float2*)(ob + (size_t)i * ldRow + j) = make_float2(v0, v1);
            }
        }
}

// ================================================================ fused IDCT(w) + LayerNorm + silu-gate + fp16 split
#define DL_SMEM ((4096 + 2*64*392) * 4)
__global__ void __launch_bounds__(256) dct_ln_k(
    const float* __restrict__ X, const float* __restrict__ z,
    const float* __restrict__ gam, const float* __restrict__ bet,
    __half* __restrict__ dst)
{
    extern __shared__ float s[];
    float* Ws = s;
    float* Xs = s + 4096;
    float* Os = s + 4096 + 64*392;
    const int t = threadIdx.x;
    const int bb = blockIdx.x;

    for (int idx = t; idx < 4096; idx += 256) Ws[idx] = g_W[idx];
    const float* Xb = X + (size_t)bb * 24576;
    for (int f = t; f < 6144; f += 256) {
        int row = f / 96, col = (f - row * 96) * 4;
        *(float4*)&Xs[row * 392 + col] = *(const float4*)(Xb + (size_t)row * 384 + col);
    }
    __syncthreads();

    const int wpair = t >> 3;
    const int cg = t & 7;
    const int w0 = wpair * 2;
    #pragma unroll
    for (int jb = 0; jb < 4; jb++) {
        float a0[12], a1[12];
        #pragma unroll
        for (int j = 0; j < 12; j++) { a0[j] = 0.f; a1[j] = 0.f; }
        #pragma unroll 4
        for (int m = 0; m < 64; m++) {
            float wv0 = Ws[m * 64 + w0];
            float wv1 = Ws[m * 64 + w0 + 1];
            const float* xr = &Xs[m * 392 + cg + 8 * (jb * 12)];
            #pragma unroll
            for (int j = 0; j < 12; j++) {
                float xv = xr[8 * j];
                a0[j] = fmaf(wv0, xv, a0[j]);
                a1[j] = fmaf(wv1, xv, a1[j]);
            }
        }
        #pragma unroll
        for (int j = 0; j < 12; j++) {
            int c = cg + 8 * (jb * 12 + j);
            Os[w0 * 392 + c]       = a0[j];
            Os[(w0 + 1) * 392 + c] = a1[j];
        }
    }
    __syncthreads();

    const int warp = t >> 5, lane = t & 31;
    float gv[12], bv[12];
    #pragma unroll
    for (int k = 0; k < 12; k++) { gv[k] = gam[lane + 32*k]; bv[k] = bet[lane + 32*k]; }
    for (int w = warp; w < 64; w += 8) {
        float vals[12], sum = 0.f;
        #pragma unroll
        for (int k = 0; k < 12; k++) { vals[k] = Os[w * 392 + lane + 32*k]; sum += vals[k]; }
        #pragma unroll
        for (int o = 16; o; o >>= 1) sum += __shfl_xor_sync(0xffffffffu, sum, o);
        float mu = sum * (1.0f / 384.0f);
        float q = 0.f;
        #pragma unroll
        for (int k = 0; k < 12; k++) { float d = vals[k] - mu; q = fmaf(d, d, q); }
        #pragma unroll
        for (int o = 16; o; o >>= 1) q += __shfl_xor_sync(0xffffffffu, q, o);
        float inv = rsqrtf(q * (1.0f / 384.0f) + 1e-5f);
        const size_t pixel = (size_t)bb * 64 + w;
        const float* zr = z + pixel * 384;
        __half* dr = dst + pixel * 768;
        #pragma unroll
        for (int k = 0; k < 12; k++) {
            int c = lane + 32*k;
            float o = ((vals[k] - mu) * inv * gv[k] + bv[k]) * zr[c];
            __half hi, lo; split2h(o, hi, lo);
            dr[c] = hi; dr[384 + c] = lo;
        }
    }
}

// ================================================================ launcher
#define TG_SMEM 196608

extern "C" void kernel_launch(void* const* d_in, const int* in_sizes, int n_in,
                              void* d_out, int out_size)
{
    const float* x     = (const float*)d_in[0];
    const float* freq  = (const float*)d_in[1];
    const float* dw_w  = (const float*)d_in[2];
    const float* dw_b  = (const float*)d_in[3];
    const float* lin_w = (const float*)d_in[4];
    const float* lin_b = (const float*)d_in[5];
    const float* tok_w = (const float*)d_in[6];
    const float* tok_b = (const float*)d_in[7];
    const float* ln_g  = (const float*)d_in[8];
    const float* ln_b  = (const float*)d_in[9];
    const float* out_w = (const float*)d_in[10];
    const float* out_b = (const float*)d_in[11];
    const float* cp    = (const float*)d_in[12];
    const float* ap    = (const float*)d_in[13];
    float* out = (float*)d_out;

    float *pxs, *pz, *ps, *pf1;
    __half *pxd, *pfq, *pf2, *pwl, *pwt, *pwo;
    cudaGetSymbolAddress((void**)&pxs, g_xs);
    cudaGetSymbolAddress((void**)&pz,  g_z);
    cudaGetSymbolAddress((void**)&ps,  g_s);
    cudaGetSymbolAddress((void**)&pf1, g_f1);
    cudaGetSymbolAddress((void**)&pxd, g_xd);
    cudaGetSymbolAddress((void**)&pfq, g_fq);
    cudaGetSymbolAddress((void**)&pf2, g_f2);
    cudaGetSymbolAddress((void**)&pwl, g_wl);
    cudaGetSymbolAddress((void**)&pwt, g_wt);
    cudaGetSymbolAddress((void**)&pwo, g_wo);

    cudaFuncSetAttribute((const void*)(tgemm_k<0,1>), cudaFuncAttributeMaxDynamicSharedMemorySize, TG_SMEM);
    cudaFuncSetAttribute((const void*)(tgemm_k<1,3>), cudaFuncAttributeMaxDynamicSharedMemorySize, TG_SMEM);
    cudaFuncSetAttribute((const void*)(tgemm_k<2,1>), cudaFuncAttributeMaxDynamicSharedMemorySize, TG_SMEM);
    cudaFuncSetAttribute((const void*)(dctT_k<true,  false>), cudaFuncAttributeMaxDynamicSharedMemorySize, DT_SMEM);
    cudaFuncSetAttribute((const void*)(dctT_k<true,  true >), cudaFuncAttributeMaxDynamicSharedMemorySize, DT_SMEM);
    cudaFuncSetAttribute((const void*)(dctT_k<false, false>), cudaFuncAttributeMaxDynamicSharedMemorySize, DT_SMEM);
    cudaFuncSetAttribute((const void*)dct_ln_k,   cudaFuncAttributeMaxDynamicSharedMemorySize, DL_SMEM);

    build_w_k<<<16, 256>>>();                                               // 1
    split_k<<<(768*96 + 255)/256, 256>>>(lin_w, pwl, 768*96);               // 2
    dwconv_k<<<1024, 384>>>(x, dw_w, dw_b, pxd);                            // 3
    split_k<<<(384*96 + 255)/256, 256>>>(tok_w, pwt, 384*96);               // 4
    split_k<<<(65536*96 + 255)/256, 256>>>(freq, pfq, 65536*96);            // 5
    // xz = xd @ lin_w^T : xs + silu(z)   (single-product fp16)
    tgemm_k<0,1><<<dim3(6, 512), 512, TG_SMEM>>>(pxd, pwl, lin_b, pxs, pz, nullptr, nullptr);
    split_k<<<(384*96 + 255)/256, 256>>>(out_w, pwo, 384*96);
    // s = modulation(gelu(freq @ tok_w^T))  (3-product fp16 — exp-amplified path)
    tgemm_k<1,3><<<dim3(3, 512), 512, TG_SMEM>>>(pfq, pwt, tok_b, ps, nullptr, cp, ap);
    // DCT over h (tensorized bf16 3-product)
    dctT_k<true,  false><<<dim3(192, 16),   256, DT_SMEM>>>(pf1, pxs, pf1, 24576);
    // DCT over w + modulate by s
    dctT_k<true,  true ><<<dim3(3,  1024),  256, DT_SMEM>>>((float*)pf2, pf1, ps, 384);
    // IDCT over n
    dctT_k<false, false><<<dim3(192, 16),   256, DT_SMEM>>>(pf1, (float*)pf2, pf1, 24576);
    // fused IDCT over m + LayerNorm + silu-gate -> split fp16
    dct_ln_k<<<1024, 256, DL_SMEM>>>(pf1, pz, ln_g, ln_b, pf2);
    // out = xo @ out_w^T + out_b  (single-product fp16)
    tgemm_k<2,1><<<dim3(3, 512), 512, TG_SMEM>>>(pf2, pwo, out_b, out, nullptr, nullptr, nullptr);
}

// round 14
// speedup vs baseline: 1.5557x; 1.1202x over previous
#include <cuda_runtime.h>
#include <cuda_bf16.h>
#include <cuda_fp16.h>
#include <math.h>
#include <stdint.h>

#define KDIM 384
#define NEL 25165824   // 16*64*64*384

// fp32 buffers
static __device__ float g_xs[NEL];      // xs (pre-DCT)
static __device__ float g_z [NEL];      // silu(z)
static __device__ float g_s [NEL];      // modulation scalar
static __device__ float g_f1[NEL];
static __device__ float g_W[4096];      // 64x64 DCT-II matrix (fp32, for dct_ln)
// fp16 split W planes for DCT: [orient][plane hi/lo][64][72]
static __device__ __half g_Wsp[2][2][64][72];
// fp16 split buffers ([row][768]: hi 384 | lo 384)
static __device__ float g_xd[NEL];      // conv output (hi plane only used)
static __device__ float g_fq[NEL];      // split freq_embed (hi+lo)
static __device__ float g_f2[NEL];      // LN output (hi only) / fp32 scratch
static __device__ float g_wl[294912];   // split lin_w  (768 rows)
static __device__ float g_wt[147456];   // split tok_w  (384 rows)
static __device__ float g_wo[147456];   // split out_w  (384 rows)

// ================================================================ helpers
__device__ __forceinline__ uint32_t smem_u32(const void* p) {
    uint32_t a;
    asm("{ .reg .u64 t; cvta.to.shared.u64 t, %1; cvt.u32.u64 %0, t; }" : "=r"(a) : "l"(p));
    return a;
}
__device__ __forceinline__ void ldsm4(uint32_t (&r)[4], uint32_t addr) {
    asm volatile("ldmatrix.sync.aligned.m8n8.x4.shared.b16 {%0,%1,%2,%3}, [%4];"
                 : "=r"(r[0]), "=r"(r[1]), "=r"(r[2]), "=r"(r[3]) : "r"(addr));
}
__device__ __forceinline__ void ldsm4t(uint32_t (&r)[4], uint32_t addr) {
    asm volatile("ldmatrix.sync.aligned.m8n8.x4.trans.shared.b16 {%0,%1,%2,%3}, [%4];"
                 : "=r"(r[0]), "=r"(r[1]), "=r"(r[2]), "=r"(r[3]) : "r"(addr));
}
// fp16 mma
__device__ __forceinline__ void mma16816h(float (&d)[4], const uint32_t (&a)[4],
                                          uint32_t b0, uint32_t b1) {
    asm volatile(
        "mma.sync.aligned.m16n8k16.row.col.f32.f16.f16.f32 "
        "{%0,%1,%2,%3}, {%4,%5,%6,%7}, {%8,%9}, {%0,%1,%2,%3};"
        : "+f"(d[0]), "+f"(d[1]), "+f"(d[2]), "+f"(d[3])
        : "r"(a[0]), "r"(a[1]), "r"(a[2]), "r"(a[3]), "r"(b0), "r"(b1));
}
__device__ __forceinline__ unsigned swz(unsigned off) {
    return off ^ ((off >> 3) & 0x70);
}
__device__ __forceinline__ void cp16(uint32_t dst, const void* src) {
    asm volatile("cp.async.cg.shared.global [%0], [%1], 16;" :: "r"(dst), "l"(src) : "memory");
}
__device__ __forceinline__ void cp_commit() {
    asm volatile("cp.async.commit_group;" ::: "memory");
}
template<int N> __device__ __forceinline__ void cp_wait() {
    asm volatile("cp.async.wait_group %0;" :: "n"(N) : "memory");
}
__device__ __forceinline__ void split2h(float v, __half& h, __half& l) {
    h = __float2half_rn(v);
    l = __float2half_rn(v - __half2float(h));
}

// ================================================================ build W
__global__ void build_w_k() {
    int i = blockIdx.x * 256 + threadIdx.x;
    int n = i >> 6, h = i & 63;
    float v = cosf((float)n * (((float)h + 0.5f) * (3.14159265358979323846f / 64.0f)))
            * 0.17677669529663687f;
    if (n == 0) v *= 0.70710678118654752f;
    g_W[i] = v;
    __half hi, lo; split2h(v, hi, lo);
    g_Wsp[0][0][n][h] = hi;
    g_Wsp[0][1][n][h] = lo;
    g_Wsp[1][0][h][n] = hi;
    g_Wsp[1][1][h][n] = lo;
}

// ================================================================ split fp32 [rows][384] -> fp16 [rows][768] (hi|lo)
__global__ void split_k(const float* __restrict__ src, __half* __restrict__ dst, int n4) {
    int i = blockIdx.x * 256 + threadIdx.x;
    if (i >= n4) return;
    int row = i / 96;
    int col = (i - row * 96) * 4;
    float4 v = *(const float4*)(src + (size_t)row * 384 + col);
    __half h0,h1,h2,h3,l0,l1,l2,l3;
    split2h(v.x,h0,l0); split2h(v.y,h1,l1); split2h(v.z,h2,l2); split2h(v.w,h3,l3);
    __half* d = dst + (size_t)row * 768 + col;
    d[0]=h0; d[1]=h1; d[2]=h2; d[3]=h3;
    d[384]=l0; d[385]=l1; d[386]=l2; d[387]=l3;
}

// ================================================================ depthwise conv 3x3, NCHW -> NHWC fp16 (hi only)
__global__ void dwconv_k(const float* __restrict__ x, const float* __restrict__ w9,
                         const float* __restrict__ bias, __half* __restrict__ outp)
{
    const int bh = blockIdx.x;
    const int c  = threadIdx.x;
    const int b  = bh >> 6, h = bh & 63;
    const float* xp = x + (size_t)(b * 384 + c) * 64 * 64;
    float k0 = w9[c*9+0], k1 = w9[c*9+1], k2 = w9[c*9+2];
    float k3 = w9[c*9+3], k4 = w9[c*9+4], k5 = w9[c*9+5];
    float k6 = w9[c*9+6], k7 = w9[c*9+7], k8 = w9[c*9+8];
    const float bi = bias[c];
    const float* r0 = (h > 0)  ? xp + (h-1)*64 : 0;
    const float* r1 = xp + h*64;
    const float* r2 = (h < 63) ? xp + (h+1)*64 : 0;
    float a0 = 0.f, a1 = 0.f, a2 = 0.f;
    float m0 = r0 ? r0[0] : 0.f;
    float m1 = r1[0];
    float m2 = r2 ? r2[0] : 0.f;
    __half* ob = outp + (size_t)bh * 64 * 768 + c;
    #pragma unroll 4
    for (int w = 0; w < 64; w++) {
        float n0, n1, n2;
        if (w < 63) {
            n0 = r0 ? r0[w+1] : 0.f;
            n1 = r1[w+1];
            n2 = r2 ? r2[w+1] : 0.f;
        } else { n0 = n1 = n2 = 0.f; }
        float acc = bi
            + a0*k0 + m0*k1 + n0*k2
            + a1*k3 + m1*k4 + n1*k5
            + a2*k6 + m2*k7 + n2*k8;
        ob[(size_t)w * 768] = __float2half_rn(acc);
        a0 = m0; a1 = m1; a2 = m2;
        m0 = n0; m1 = n1; m2 = n2;
    }
}

// ================================================================ mma.sync fp16 GEMM, BK=64, 3-stage cp.async pipeline
// 128x128 tile, 512 threads (16 warps, warp tile 32x32)
// PROD==1: out = Ahi*Bhi
// PROD==2: out = Ahi*Bhi + Alo*Bhi
template<int MODE, int PROD>
__global__ void __launch_bounds__(512) tgemm_k(
    const __half* __restrict__ A, const __half* __restrict__ Wt,
    const float* __restrict__ bias,
    float* __restrict__ o0, float* __restrict__ o1,
    const float* __restrict__ cp_, const float* __restrict__ ap)
{
    extern __shared__ char sm[];
    const int t    = threadIdx.x;
    const int wid  = t >> 5;
    const int lane = t & 31;
    const int m0 = blockIdx.y * 128;
    const int n0 = blockIdx.x * 128;
    const uint32_t smemBase = smem_u32(sm);

    const __half* srcP[4];
    uint32_t dstS[4];
    bool act[4];
    #pragma unroll
    for (int r = 0; r < 4; r++) {
        int u = t + 512 * r;
        int mat = u >> 10;
        int v = u & 1023;
        int row = v >> 3;
        int s7 = v & 7;
        act[r] = (s7 < 4) || (PROD == 2 && mat == 0);
        const __half* base = mat ? (Wt + (size_t)(n0 + row) * 768)
                                 : (A  + (size_t)(m0 + row) * 768);
        int col = (s7 < 4) ? s7 * 8 : 384 + (s7 - 4) * 8;
        srcP[r] = base + col;
        dstS[r] = smemBase + mat * 32768 + swz((unsigned)(row * 128 + s7 * 16));
    }

    #define TG_ISSUE(CH, STG) do {                                               \
        const unsigned so_ = (unsigned)(STG) * 65536u;                           \
        _Pragma("unroll")                                                        \
        for (int r_ = 0; r_ < 4; r_++)                                           \
            if (act[r_]) {                                                       \
                cp16(dstS[r_] + so_,          srcP[r_] + (CH) * 64);             \
                cp16(dstS[r_] + so_ + 16384u, srcP[r_] + (CH) * 64 + 32);        \
            }                                                                    \
        cp_commit();                                                             \
    } while (0)

    TG_ISSUE(0, 0);
    TG_ISSUE(1, 1);

    const int wm = wid & 3;
    const int wn = wid >> 2;
    float acc[2][4][4];
    #pragma unroll
    for (int i = 0; i < 2; i++)
        #pragma unroll
        for (int j = 0; j < 4; j++)
            #pragma unroll
            for (int q = 0; q < 4; q++) acc[i][j][q] = 0.f;

    const int lrow = lane & 15;
    const int lkc  = (lane >> 4) << 3;

    const int NCH = KDIM / 64;   // 6
    int stg = 0;
    int istg = 2;
    for (int ch = 0; ch < NCH; ch++) {
        if (ch < NCH - 1) cp_wait<1>(); else cp_wait<0>();
        __syncthreads();
        if (ch + 2 < NCH) TG_ISSUE(ch + 2, istg);

        #pragma unroll
        for (int sub = 0; sub < 2; sub++) {
            const uint32_t aS = smemBase + (unsigned)stg * 65536u + (unsigned)sub * 16384u;
            const uint32_t bS = aS + 32768u;
            #pragma unroll
            for (int ks = 0; ks < 2; ks++) {
                const unsigned kc2 = (unsigned)(ks * 16 + lkc) * 2;
                uint32_t ahi[2][4];
                #pragma unroll
                for (int mt = 0; mt < 2; mt++) {
                    unsigned off = (unsigned)(wm * 32 + mt * 16 + lrow) * 128 + kc2;
                    ldsm4(ahi[mt], aS + swz(off));
                }
                uint32_t bhi[2][4];
                #pragma unroll
                for (int ng = 0; ng < 2; ng++) {
                    unsigned off = (unsigned)(wn * 32 + ng * 16 + lrow) * 128 + kc2;
                    ldsm4(bhi[ng], bS + swz(off));
                }
                #pragma unroll
                for (int mt = 0; mt < 2; mt++)
                    #pragma unroll
                    for (int ng = 0; ng < 2; ng++) {
                        mma16816h(acc[mt][2*ng],   ahi[mt], bhi[ng][0], bhi[ng][2]);
                        mma16816h(acc[mt][2*ng+1], ahi[mt], bhi[ng][1], bhi[ng][3]);
                    }
                if (PROD >= 2) {
                    uint32_t alo[2][4];
                    #pragma unroll
                    for (int mt = 0; mt < 2; mt++) {
                        unsigned off = (unsigned)(wm * 32 + mt * 16 + lrow) * 128 + kc2;
                        ldsm4(alo[mt], aS + swz(off + 64));
                    }
                    #pragma unroll
                    for (int mt = 0; mt < 2; mt++)
                        #pragma unroll
                        for (int ng = 0; ng < 2; ng++) {
                            mma16816h(acc[mt][2*ng],   alo[mt], bhi[ng][0], bhi[ng][2]);
                            mma16816h(acc[mt][2*ng+1], alo[mt], bhi[ng][1], bhi[ng][3]);
                        }
                }
            }
        }
        stg  = (stg  == 2) ? 0 : stg  + 1;
        istg = (istg == 2) ? 0 : istg + 1;
    }
    #undef TG_ISSUE

    // ---- epilogue: warp tile 32x32
    const int qr = lane >> 2;
    const int qc = lane & 3;
    const int mbw = m0 + wm * 32;
    const int nbw = n0 + wn * 32;

    float cc0 = 0.f, css = 0.f;
    if (MODE == 1) {
        cc0 = cp_[0];
        css = (1.0f + 0.5f * ap[0]) / (cc0 + 1e-8f);
    }

    #pragma unroll
    for (int mt = 0; mt < 2; mt++) {
        #pragma unroll
        for (int half = 0; half < 2; half++) {
            const int m = mbw + mt * 16 + qr + half * 8;
            float ee = 0.f;
            if (MODE == 1) {
                const float kp = 3.14159265358979323846f / 64.0f;
                int hh = (m >> 6) & 63, ww = m & 63;
                ee = kp * kp * (float)(hh * hh + ww * ww);
            }
            #pragma unroll
            for (int nt = 0; nt < 4; nt++) {
                const int n = nbw + nt * 8 + qc * 2;
                float v0 = acc[mt][nt][half * 2 + 0] + __ldg(bias + n);
                float v1 = acc[mt][nt][half * 2 + 1] + __ldg(bias + n + 1);
                if (MODE == 0) {
                    if (n0 >= 384) {
                        v0 *= 1.0f / (1.0f + __expf(-v0));
                        v1 *= 1.0f / (1.0f + __expf(-v1));
                        *(float2*)(o1 + (size_t)m * 384 + (n - 384)) = make_float2(v0, v1);
                    } else {
                        *(float2*)(o0 + (size_t)m * 384 + n) = make_float2(v0, v1);
                    }
                } else if (MODE == 1) {
                    float tg0 = 0.5f * v0 * (1.0f + erff(v0 * 0.70710678118654752f));
                    float tg1 = 0.5f * v1 * (1.0f + erff(v1 * 0.70710678118654752f));
                    float ct0 = cc0 * tg0, ct1 = cc0 * tg1;
                    float r0 = (__cosf(ct0) + __sinf(ct0) * css) * __expf(-ee * tg0);
                    float r1 = (__cosf(ct1) + __sinf(ct1) * css) * __expf(-ee * tg1);
                    *(float2*)(o0 + (size_t)m * 384 + n) = make_float2(r0, r1);
                } else {
                    *(float2*)(o0 + (size_t)m * 384 + n) = make_float2(v0, v1);
                }
            }
        }
    }
}

// ================================================================ tensorized 64-pt cosine transform
// fp16 2-product: (Whi + Wlo) x X(fp16)
// smem: X 64x136 fp16 (17408B) + W 2 planes 64x72 fp16 (18432B)
#define DT_SMEM (17408 + 18432)
template<bool FWD, bool MOD>
__global__ void __launch_bounds__(256) dctT_k(
    float* __restrict__ out, const float* __restrict__ X,
    const float* __restrict__ S, int ldRow)
{
    extern __shared__ char ds[];
    __half* sX  = (__half*)ds;
    __half* sWp = (__half*)(ds + 17408);
    const int t = threadIdx.x;
    const int bb = blockIdx.y;
    const int j0 = blockIdx.x << 7;

    {
        const uint4* src = (const uint4*)&g_Wsp[FWD ? 0 : 1][0][0][0];
        uint4* dst = (uint4*)sWp;
        for (int u = t; u < 1152; u += 256) dst[u] = src[u];
    }
    const float* Xb = X + (size_t)bb * 64 * ldRow + j0;
    #pragma unroll
    for (int it = 0; it < 8; it++) {
        int idx = t + 256 * it;
        int row = idx >> 5, c4 = (idx & 31) << 2;
        float4 v = *(const float4*)(Xb + (size_t)row * ldRow + c4);
        __half2 p0 = __floats2half2_rn(v.x, v.y);
        __half2 p1 = __floats2half2_rn(v.z, v.w);
        *(uint2*)(sX + row * 136 + c4) =
            make_uint2(*(uint32_t*)&p0, *(uint32_t*)&p1);
    }
    __syncthreads();

    const int wid = t >> 5, lane = t & 31;
    const int wm = wid & 1, wn = wid >> 1;
    const uint32_t xB   = smem_u32(sX);
    const uint32_t whiB = smem_u32(sWp);
    const uint32_t wloB = whiB + 9216;

    float acc[2][4][4];
    #pragma unroll
    for (int i = 0; i < 2; i++)
        #pragma unroll
        for (int j = 0; j < 4; j++)
            #pragma unroll
            for (int q = 0; q < 4; q++) acc[i][j][q] = 0.f;

    const int lr = lane & 15, lh = lane >> 4;
    #pragma unroll
    for (int ks = 0; ks < 4; ks++) {
        uint32_t ahi[2][4], alo[2][4];
        #pragma unroll
        for (int mt = 0; mt < 2; mt++) {
            unsigned off = (unsigned)(wm * 32 + mt * 16 + lr) * 144 + (unsigned)(ks * 16 + lh * 8) * 2;
            ldsm4(ahi[mt], whiB + off);
            ldsm4(alo[mt], wloB + off);
        }
        uint32_t bh[2][4];
        #pragma unroll
        for (int ng = 0; ng < 2; ng++) {
            unsigned off = (unsigned)(ks * 16 + lr) * 272 + (unsigned)(wn * 32 + ng * 16 + lh * 8) * 2;
            ldsm4t(bh[ng], xB + off);
        }
        #pragma unroll
        for (int mt = 0; mt < 2; mt++)
            #pragma unroll
            for (int ng = 0; ng < 2; ng++) {
                mma16816h(acc[mt][2*ng],   ahi[mt], bh[ng][0], bh[ng][1]);
                mma16816h(acc[mt][2*ng+1], ahi[mt], bh[ng][2], bh[ng][3]);
            }
        #pragma unroll
        for (int mt = 0; mt < 2; mt++)
            #pragma unroll
            for (int ng = 0; ng < 2; ng++) {
                mma16816h(acc[mt][2*ng],   alo[mt], bh[ng][0], bh[ng][1]);
                mma16816h(acc[mt][2*ng+1], alo[mt], bh[ng][2], bh[ng][3]);
            }
    }

    const int qr = lane >> 2, qc = lane & 3;
    float* ob = out + (size_t)bb * 64 * ldRow + j0;
    const float* sb = S + (size_t)bb * 64 * ldRow + j0;
    #pragma unroll
    for (int mt = 0; mt < 2; mt++)
        #pragma unroll
        for (int half = 0; half < 2; half++) {
            const int i = wm * 32 + mt * 16 + qr + half * 8;
            #pragma unroll
            for (int ng = 0; ng < 4; ng++) {
                const int j = wn * 32 + ng * 8 + qc * 2;
                float v0 = acc[mt][ng][half * 2 + 0];
                float v1 = acc[mt][ng][half * 2 + 1];
                if (MOD) {
                    float2 s2 = *(const float2*)(sb + (size_t)i * ldRow + j);
                    v0 *= s2.x; v1 *= s2.y;
                }
                *(float2*)(ob + (size_t)i * ldRow + j) = make_float2(v0, v1);
            }
        }
}

// ================================================================ fused IDCT(w) + LayerNorm + silu-gate (fp16 hi only)
#define DL_SMEM ((4096 + 2*64*392) * 4)
__global__ void __launch_bounds__(256) dct_ln_k(
    const float* __restrict__ X, const float* __restrict__ z,
    const float* __restrict__ gam, const float* __restrict__ bet,
    __half* __restrict__ dst)
{
    extern __shared__ float s[];
    float* Ws = s;
    float* Xs = s + 4096;
    float* Os = s + 4096 + 64*392;
    const int t = threadIdx.x;
    const int bb = blockIdx.x;

    for (int idx = t; idx < 4096; idx += 256) Ws[idx] = g_W[idx];
    const float* Xb = X + (size_t)bb * 24576;
    for (int f = t; f < 6144; f += 256) {
        int row = f / 96, col = (f - row * 96) * 4;
        *(float4*)&Xs[row * 392 + col] = *(const float4*)(Xb + (size_t)row * 384 + col);
    }
    __syncthreads();

    const int wpair = t >> 3;
    const int cg = t & 7;
    const int w0 = wpair * 2;
    #pragma unroll
    for (int jb = 0; jb < 4; jb++) {
        float a0[12], a1[12];
        #pragma unroll
        for (int j = 0; j < 12; j++) { a0[j] = 0.f; a1[j] = 0.f; }
        #pragma unroll 4
        for (int m = 0; m < 64; m++) {
            float wv0 = Ws[m * 64 + w0];
            float wv1 = Ws[m * 64 + w0 + 1];
            const float* xr = &Xs[m * 392 + cg + 8 * (jb * 12)];
            #pragma unroll
            for (int j = 0; j < 12; j++) {
                float xv = xr[8 * j];
                a0[j] = fmaf(wv0, xv, a0[j]);
                a1[j] = fmaf(wv1, xv, a1[j]);
            }
        }
        #pragma unroll
        for (int j = 0; j < 12; j++) {
            int c = cg + 8 * (jb * 12 + j);
            Os[w0 * 392 + c]       = a0[j];
            Os[(w0 + 1) * 392 + c] = a1[j];
        }
    }
    __syncthreads();

    const int warp = t >> 5, lane = t & 31;
    float gv[12], bv[12];
    #pragma unroll
    for (int k = 0; k < 12; k++) { gv[k] = gam[lane + 32*k]; bv[k] = bet[lane + 32*k]; }
    for (int w = warp; w < 64; w += 8) {
        float vals[12], sum = 0.f;
        #pragma unroll
        for (int k = 0; k < 12; k++) { vals[k] = Os[w * 392 + lane + 32*k]; sum += vals[k]; }
        #pragma unroll
        for (int o = 16; o; o >>= 1) sum += __shfl_xor_sync(0xffffffffu, sum, o);
        float mu = sum * (1.0f / 384.0f);
        float q = 0.f;
        #pragma unroll
        for (int k = 0; k < 12; k++) { float d = vals[k] - mu; q = fmaf(d, d, q); }
        #pragma unroll
        for (int o = 16; o; o >>= 1) q += __shfl_xor_sync(0xffffffffu, q, o);
        float inv = rsqrtf(q * (1.0f / 384.0f) + 1e-5f);
        const size_t pixel = (size_t)bb * 64 + w;
        const float* zr = z + pixel * 384;
        __half* dr = dst + pixel * 768;
        #pragma unroll
        for (int k = 0; k < 12; k++) {
            int c = lane + 32*k;
            float o = ((vals[k] - mu) * inv * gv[k] + bv[k]) * zr[c];
            dr[c] = __float2half_rn(o);
        }
    }
}

// ================================================================ launcher
#define TG_SMEM 196608

extern "C" void kernel_launch(void* const* d_in, const int* in_sizes, int n_in,
                              void* d_out, int out_size)
{
    const float* x     = (const float*)d_in[0];
    const float* freq  = (const float*)d_in[1];
    const float* dw_w  = (const float*)d_in[2];
    const float* dw_b  = (const float*)d_in[3];
    const float* lin_w = (const float*)d_in[4];
    const float* lin_b = (const float*)d_in[5];
    const float* tok_w = (const float*)d_in[6];
    const float* tok_b = (const float*)d_in[7];
    const float* ln_g  = (const float*)d_in[8];
    const float* ln_b  = (const float*)d_in[9];
    const float* out_w = (const float*)d_in[10];
    const float* out_b = (const float*)d_in[11];
    const float* cp    = (const float*)d_in[12];
    const float* ap    = (const float*)d_in[13];
    float* out = (float*)d_out;

    float *pxs, *pz, *ps, *pf1;
    __half *pxd, *pfq, *pf2, *pwl, *pwt, *pwo;
    cudaGetSymbolAddress((void**)&pxs, g_xs);
    cudaGetSymbolAddress((void**)&pz,  g_z);
    cudaGetSymbolAddress((void**)&ps,  g_s);
    cudaGetSymbolAddress((void**)&pf1, g_f1);
    cudaGetSymbolAddress((void**)&pxd, g_xd);
    cudaGetSymbolAddress((void**)&pfq, g_fq);
    cudaGetSymbolAddress((void**)&pf2, g_f2);
    cudaGetSymbolAddress((void**)&pwl, g_wl);
    cudaGetSymbolAddress((void**)&pwt, g_wt);
    cudaGetSymbolAddress((void**)&pwo, g_wo);

    cudaFuncSetAttribute((const void*)(tgemm_k<0,1>), cudaFuncAttributeMaxDynamicSharedMemorySize, TG_SMEM);
    cudaFuncSetAttribute((const void*)(tgemm_k<1,2>), cudaFuncAttributeMaxDynamicSharedMemorySize, TG_SMEM);
    cudaFuncSetAttribute((const void*)(tgemm_k<2,1>), cudaFuncAttributeMaxDynamicSharedMemorySize, TG_SMEM);
    cudaFuncSetAttribute((const void*)(dctT_k<true,  false>), cudaFuncAttributeMaxDynamicSharedMemorySize, DT_SMEM);
    cudaFuncSetAttribute((const void*)(dctT_k<true,  true >), cudaFuncAttributeMaxDynamicSharedMemorySize, DT_SMEM);
    cudaFuncSetAttribute((const void*)(dctT_k<false, false>), cudaFuncAttributeMaxDynamicSharedMemorySize, DT_SMEM);
    cudaFuncSetAttribute((const void*)dct_ln_k,   cudaFuncAttributeMaxDynamicSharedMemorySize, DL_SMEM);

    build_w_k<<<16, 256>>>();
    split_k<<<(768*96 + 255)/256, 256>>>(lin_w, pwl, 768*96);
    dwconv_k<<<1024, 384>>>(x, dw_w, dw_b, pxd);
    split_k<<<(384*96 + 255)/256, 256>>>(tok_w, pwt, 384*96);
    split_k<<<(65536*96 + 255)/256, 256>>>(freq, pfq, 65536*96);
    // xz = xd @ lin_w^T : xs + silu(z)   (single-product fp16)
    tgemm_k<0,1><<<dim3(6, 512), 512, TG_SMEM>>>(pxd, pwl, lin_b, pxs, pz, nullptr, nullptr);
    split_k<<<(384*96 + 255)/256, 256>>>(out_w, pwo, 384*96);
    // s = modulation(gelu(freq @ tok_w^T))  (2-product fp16: A split, B rounded)
    tgemm_k<1,2><<<dim3(3, 512), 512, TG_SMEM>>>(pfq, pwt, tok_b, ps, nullptr, cp, ap);
    // DCT over h (fp16 2-product)
    dctT_k<true,  false><<<dim3(192, 16),   256, DT_SMEM>>>(pf1, pxs, pf1, 24576);
    // DCT over w + modulate by s
    dctT_k<true,  true ><<<dim3(3,  1024),  256, DT_SMEM>>>((float*)pf2, pf1, ps, 384);
    // IDCT over n
    dctT_k<false, false><<<dim3(192, 16),   256, DT_SMEM>>>(pf1, (float*)pf2, pf1, 24576);
    // fused IDCT over m + LayerNorm + silu-gate -> fp16 (hi only)
    dct_ln_k<<<1024, 256, DL_SMEM>>>(pf1, pz, ln_g, ln_b, pf2);
    // out = xo @ out_w^T + out_b  (single-product fp16)
    tgemm_k<2,1><<<dim3(3, 512), 512, TG_SMEM>>>(pf2, pwo, out_b, out, nullptr, nullptr, nullptr);
}

// round 15
// speedup vs baseline: 1.5823x; 1.0171x over previous
#include <cuda_runtime.h>
#include <cuda_bf16.h>
#include <cuda_fp16.h>
#include <math.h>
#include <stdint.h>

#define KDIM 384
#define NEL 25165824   // 16*64*64*384

// fp32 buffers
static __device__ float g_z [NEL];      // silu(z)
static __device__ float g_s [NEL];      // modulation scalar
static __device__ float g_f1[NEL];      // pass3 output (fp32, read by dct_ln)
static __device__ float g_W[4096];      // 64x64 DCT-II matrix (fp32, for dct_ln)
// fp16 split W planes for DCT: [orient][plane hi/lo][64][72]
static __device__ __half g_Wsp[2][2][64][72];
// fp16 buffers
static __device__ float g_xd[NEL];      // conv output [pix][768] hi-only; reused as pass1 out
static __device__ float g_xs[NEL];      // xs fp16 [pix][384]; reused as pass2 out
static __device__ float g_fq[NEL];      // split freq_embed (hi+lo)
static __device__ float g_f2[NEL];      // LN output fp16 [pix][768] hi-only
static __device__ float g_wl[294912];   // split lin_w  (768 rows)
static __device__ float g_wt[147456];   // split tok_w  (384 rows)
static __device__ float g_wo[147456];   // split out_w  (384 rows)

// ================================================================ helpers
__device__ __forceinline__ uint32_t smem_u32(const void* p) {
    uint32_t a;
    asm("{ .reg .u64 t; cvta.to.shared.u64 t, %1; cvt.u32.u64 %0, t; }" : "=r"(a) : "l"(p));
    return a;
}
__device__ __forceinline__ void ldsm4(uint32_t (&r)[4], uint32_t addr) {
    asm volatile("ldmatrix.sync.aligned.m8n8.x4.shared.b16 {%0,%1,%2,%3}, [%4];"
                 : "=r"(r[0]), "=r"(r[1]), "=r"(r[2]), "=r"(r[3]) : "r"(addr));
}
__device__ __forceinline__ void ldsm4t(uint32_t (&r)[4], uint32_t addr) {
    asm volatile("ldmatrix.sync.aligned.m8n8.x4.trans.shared.b16 {%0,%1,%2,%3}, [%4];"
                 : "=r"(r[0]), "=r"(r[1]), "=r"(r[2]), "=r"(r[3]) : "r"(addr));
}
__device__ __forceinline__ void mma16816h(float (&d)[4], const uint32_t (&a)[4],
                                          uint32_t b0, uint32_t b1) {
    asm volatile(
        "mma.sync.aligned.m16n8k16.row.col.f32.f16.f16.f32 "
        "{%0,%1,%2,%3}, {%4,%5,%6,%7}, {%8,%9}, {%0,%1,%2,%3};"
        : "+f"(d[0]), "+f"(d[1]), "+f"(d[2]), "+f"(d[3])
        : "r"(a[0]), "r"(a[1]), "r"(a[2]), "r"(a[3]), "r"(b0), "r"(b1));
}
__device__ __forceinline__ unsigned swz(unsigned off) {
    return off ^ ((off >> 3) & 0x70);
}
__device__ __forceinline__ void cp16(uint32_t dst, const void* src) {
    asm volatile("cp.async.cg.shared.global [%0], [%1], 16;" :: "r"(dst), "l"(src) : "memory");
}
__device__ __forceinline__ void cp_commit() {
    asm volatile("cp.async.commit_group;" ::: "memory");
}
template<int N> __device__ __forceinline__ void cp_wait() {
    asm volatile("cp.async.wait_group %0;" :: "n"(N) : "memory");
}
__device__ __forceinline__ void split2h(float v, __half& h, __half& l) {
    h = __float2half_rn(v);
    l = __float2half_rn(v - __half2float(h));
}
// typed pair store (fp16 or fp32 output)
__device__ __forceinline__ void st2(__half* p, float v0, float v1) {
    *(__half2*)p = __floats2half2_rn(v0, v1);
}
__device__ __forceinline__ void st2(float* p, float v0, float v1) {
    *(float2*)p = make_float2(v0, v1);
}

// ================================================================ build W
__global__ void build_w_k() {
    int i = blockIdx.x * 256 + threadIdx.x;
    int n = i >> 6, h = i & 63;
    float v = cosf((float)n * (((float)h + 0.5f) * (3.14159265358979323846f / 64.0f)))
            * 0.17677669529663687f;
    if (n == 0) v *= 0.70710678118654752f;
    g_W[i] = v;
    __half hi, lo; split2h(v, hi, lo);
    g_Wsp[0][0][n][h] = hi;
    g_Wsp[0][1][n][h] = lo;
    g_Wsp[1][0][h][n] = hi;
    g_Wsp[1][1][h][n] = lo;
}

// ================================================================ split fp32 [rows][384] -> fp16 [rows][768] (hi|lo)
__global__ void split_k(const float* __restrict__ src, __half* __restrict__ dst, int n4) {
    int i = blockIdx.x * 256 + threadIdx.x;
    if (i >= n4) return;
    int row = i / 96;
    int col = (i - row * 96) * 4;
    float4 v = *(const float4*)(src + (size_t)row * 384 + col);
    __half h0,h1,h2,h3,l0,l1,l2,l3;
    split2h(v.x,h0,l0); split2h(v.y,h1,l1); split2h(v.z,h2,l2); split2h(v.w,h3,l3);
    __half* d = dst + (size_t)row * 768 + col;
    d[0]=h0; d[1]=h1; d[2]=h2; d[3]=h3;
    d[384]=l0; d[385]=l1; d[386]=l2; d[387]=l3;
}

// ================================================================ depthwise conv 3x3, NCHW -> NHWC fp16 (hi only)
__global__ void dwconv_k(const float* __restrict__ x, const float* __restrict__ w9,
                         const float* __restrict__ bias, __half* __restrict__ outp)
{
    const int bh = blockIdx.x;
    const int c  = threadIdx.x;
    const int b  = bh >> 6, h = bh & 63;
    const float* xp = x + (size_t)(b * 384 + c) * 64 * 64;
    float k0 = w9[c*9+0], k1 = w9[c*9+1], k2 = w9[c*9+2];
    float k3 = w9[c*9+3], k4 = w9[c*9+4], k5 = w9[c*9+5];
    float k6 = w9[c*9+6], k7 = w9[c*9+7], k8 = w9[c*9+8];
    const float bi = bias[c];
    const float* r0 = (h > 0)  ? xp + (h-1)*64 : 0;
    const float* r1 = xp + h*64;
    const float* r2 = (h < 63) ? xp + (h+1)*64 : 0;
    float a0 = 0.f, a1 = 0.f, a2 = 0.f;
    float m0 = r0 ? r0[0] : 0.f;
    float m1 = r1[0];
    float m2 = r2 ? r2[0] : 0.f;
    __half* ob = outp + (size_t)bh * 64 * 768 + c;
    #pragma unroll 4
    for (int w = 0; w < 64; w++) {
        float n0, n1, n2;
        if (w < 63) {
            n0 = r0 ? r0[w+1] : 0.f;
            n1 = r1[w+1];
            n2 = r2 ? r2[w+1] : 0.f;
        } else { n0 = n1 = n2 = 0.f; }
        float acc = bi
            + a0*k0 + m0*k1 + n0*k2
            + a1*k3 + m1*k4 + n1*k5
            + a2*k6 + m2*k7 + n2*k8;
        ob[(size_t)w * 768] = __float2half_rn(acc);
        a0 = m0; a1 = m1; a2 = m2;
        m0 = n0; m1 = n1; m2 = n2;
    }
}

// ================================================================ mma.sync fp16 GEMM, BK=64, 3-stage cp.async pipeline
// 128x128 tile, 512 threads (16 warps, warp tile 32x32)
// PROD==1: out = Ahi*Bhi ; PROD==2: out = Ahi*Bhi + Alo*Bhi
// MODE 0: n<384 -> xs fp16 (o0 as __half*), n>=384 -> silu fp32 (o1)
// MODE 1: modulation scalar fp32 -> o0
// MODE 2: plain bias fp32 -> o0
template<int MODE, int PROD>
__global__ void __launch_bounds__(512) tgemm_k(
    const __half* __restrict__ A, const __half* __restrict__ Wt,
    const float* __restrict__ bias,
    void* __restrict__ o0, float* __restrict__ o1,
    const float* __restrict__ cp_, const float* __restrict__ ap)
{
    extern __shared__ char sm[];
    const int t    = threadIdx.x;
    const int wid  = t >> 5;
    const int lane = t & 31;
    const int m0 = blockIdx.y * 128;
    const int n0 = blockIdx.x * 128;
    const uint32_t smemBase = smem_u32(sm);

    const __half* srcP[4];
    uint32_t dstS[4];
    bool act[4];
    #pragma unroll
    for (int r = 0; r < 4; r++) {
        int u = t + 512 * r;
        int mat = u >> 10;
        int v = u & 1023;
        int row = v >> 3;
        int s7 = v & 7;
        act[r] = (s7 < 4) || (PROD == 2 && mat == 0);
        const __half* base = mat ? (Wt + (size_t)(n0 + row) * 768)
                                 : (A  + (size_t)(m0 + row) * 768);
        int col = (s7 < 4) ? s7 * 8 : 384 + (s7 - 4) * 8;
        srcP[r] = base + col;
        dstS[r] = smemBase + mat * 32768 + swz((unsigned)(row * 128 + s7 * 16));
    }

    #define TG_ISSUE(CH, STG) do {                                               \
        const unsigned so_ = (unsigned)(STG) * 65536u;                           \
        _Pragma("unroll")                                                        \
        for (int r_ = 0; r_ < 4; r_++)                                           \
            if (act[r_]) {                                                       \
                cp16(dstS[r_] + so_,          srcP[r_] + (CH) * 64);             \
                cp16(dstS[r_] + so_ + 16384u, srcP[r_] + (CH) * 64 + 32);        \
            }                                                                    \
        cp_commit();                                                             \
    } while (0)

    TG_ISSUE(0, 0);
    TG_ISSUE(1, 1);

    const int wm = wid & 3;
    const int wn = wid >> 2;
    float acc[2][4][4];
    #pragma unroll
    for (int i = 0; i < 2; i++)
        #pragma unroll
        for (int j = 0; j < 4; j++)
            #pragma unroll
            for (int q = 0; q < 4; q++) acc[i][j][q] = 0.f;

    const int lrow = lane & 15;
    const int lkc  = (lane >> 4) << 3;

    const int NCH = KDIM / 64;   // 6
    int stg = 0;
    int istg = 2;
    for (int ch = 0; ch < NCH; ch++) {
        if (ch < NCH - 1) cp_wait<1>(); else cp_wait<0>();
        __syncthreads();
        if (ch + 2 < NCH) TG_ISSUE(ch + 2, istg);

        #pragma unroll
        for (int sub = 0; sub < 2; sub++) {
            const uint32_t aS = smemBase + (unsigned)stg * 65536u + (unsigned)sub * 16384u;
            const uint32_t bS = aS + 32768u;
            #pragma unroll
            for (int ks = 0; ks < 2; ks++) {
                const unsigned kc2 = (unsigned)(ks * 16 + lkc) * 2;
                uint32_t ahi[2][4];
                #pragma unroll
                for (int mt = 0; mt < 2; mt++) {
                    unsigned off = (unsigned)(wm * 32 + mt * 16 + lrow) * 128 + kc2;
                    ldsm4(ahi[mt], aS + swz(off));
                }
                uint32_t bhi[2][4];
                #pragma unroll
                for (int ng = 0; ng < 2; ng++) {
                    unsigned off = (unsigned)(wn * 32 + ng * 16 + lrow) * 128 + kc2;
                    ldsm4(bhi[ng], bS + swz(off));
                }
                #pragma unroll
                for (int mt = 0; mt < 2; mt++)
                    #pragma unroll
                    for (int ng = 0; ng < 2; ng++) {
                        mma16816h(acc[mt][2*ng],   ahi[mt], bhi[ng][0], bhi[ng][2]);
                        mma16816h(acc[mt][2*ng+1], ahi[mt], bhi[ng][1], bhi[ng][3]);
                    }
                if (PROD >= 2) {
                    uint32_t alo[2][4];
                    #pragma unroll
                    for (int mt = 0; mt < 2; mt++) {
                        unsigned off = (unsigned)(wm * 32 + mt * 16 + lrow) * 128 + kc2;
                        ldsm4(alo[mt], aS + swz(off + 64));
                    }
                    #pragma unroll
                    for (int mt = 0; mt < 2; mt++)
                        #pragma unroll
                        for (int ng = 0; ng < 2; ng++) {
                            mma16816h(acc[mt][2*ng],   alo[mt], bhi[ng][0], bhi[ng][2]);
                            mma16816h(acc[mt][2*ng+1], alo[mt], bhi[ng][1], bhi[ng][3]);
                        }
                }
            }
        }
        stg  = (stg  == 2) ? 0 : stg  + 1;
        istg = (istg == 2) ? 0 : istg + 1;
    }
    #undef TG_ISSUE

    // ---- epilogue: warp tile 32x32
    const int qr = lane >> 2;
    const int qc = lane & 3;
    const int mbw = m0 + wm * 32;
    const int nbw = n0 + wn * 32;

    float cc0 = 0.f, css = 0.f;
    if (MODE == 1) {
        cc0 = cp_[0];
        css = (1.0f + 0.5f * ap[0]) / (cc0 + 1e-8f);
    }

    #pragma unroll
    for (int mt = 0; mt < 2; mt++) {
        #pragma unroll
        for (int half = 0; half < 2; half++) {
            const int m = mbw + mt * 16 + qr + half * 8;
            float ee = 0.f;
            if (MODE == 1) {
                const float kp = 3.14159265358979323846f / 64.0f;
                int hh = (m >> 6) & 63, ww = m & 63;
                ee = kp * kp * (float)(hh * hh + ww * ww);
            }
            #pragma unroll
            for (int nt = 0; nt < 4; nt++) {
                const int n = nbw + nt * 8 + qc * 2;
                float v0 = acc[mt][nt][half * 2 + 0] + __ldg(bias + n);
                float v1 = acc[mt][nt][half * 2 + 1] + __ldg(bias + n + 1);
                if (MODE == 0) {
                    if (n0 >= 384) {
                        v0 *= 1.0f / (1.0f + __expf(-v0));
                        v1 *= 1.0f / (1.0f + __expf(-v1));
                        *(float2*)(o1 + (size_t)m * 384 + (n - 384)) = make_float2(v0, v1);
                    } else {
                        st2((__half*)o0 + (size_t)m * 384 + n, v0, v1);
                    }
                } else if (MODE == 1) {
                    float tg0 = 0.5f * v0 * (1.0f + erff(v0 * 0.70710678118654752f));
                    float tg1 = 0.5f * v1 * (1.0f + erff(v1 * 0.70710678118654752f));
                    float ct0 = cc0 * tg0, ct1 = cc0 * tg1;
                    float r0 = (__cosf(ct0) + __sinf(ct0) * css) * __expf(-ee * tg0);
                    float r1 = (__cosf(ct1) + __sinf(ct1) * css) * __expf(-ee * tg1);
                    *(float2*)((float*)o0 + (size_t)m * 384 + n) = make_float2(r0, r1);
                } else {
                    *(float2*)((float*)o0 + (size_t)m * 384 + n) = make_float2(v0, v1);
                }
            }
        }
    }
}

// ================================================================ tensorized 64-pt cosine transform
// fp16 2-product: (Whi + Wlo) x X(fp16); input fp16, output OT (fp16 or fp32)
#define DT_SMEM (17408 + 18432)
template<bool FWD, bool MOD, typename OT>
__global__ void __launch_bounds__(256) dctT_k(
    OT* __restrict__ out, const __half* __restrict__ X,
    const float* __restrict__ S, int ldRow)
{
    extern __shared__ char ds[];
    __half* sX  = (__half*)ds;
    __half* sWp = (__half*)(ds + 17408);
    const int t = threadIdx.x;
    const int bb = blockIdx.y;
    const int j0 = blockIdx.x << 7;

    {
        const uint4* src = (const uint4*)&g_Wsp[FWD ? 0 : 1][0][0][0];
        uint4* dst = (uint4*)sWp;
        for (int u = t; u < 1152; u += 256) dst[u] = src[u];
    }
    const __half* Xb = X + (size_t)bb * 64 * ldRow + j0;
    #pragma unroll
    for (int it = 0; it < 4; it++) {
        int idx = t + 256 * it;
        int row = idx >> 4, q = (idx & 15) << 3;
        *(uint4*)(sX + row * 136 + q) = *(const uint4*)(Xb + (size_t)row * ldRow + q);
    }
    __syncthreads();

    const int wid = t >> 5, lane = t & 31;
    const int wm = wid & 1, wn = wid >> 1;
    const uint32_t xB   = smem_u32(sX);
    const uint32_t whiB = smem_u32(sWp);
    const uint32_t wloB = whiB + 9216;

    float acc[2][4][4];
    #pragma unroll
    for (int i = 0; i < 2; i++)
        #pragma unroll
        for (int j = 0; j < 4; j++)
            #pragma unroll
            for (int q = 0; q < 4; q++) acc[i][j][q] = 0.f;

    const int lr = lane & 15, lh = lane >> 4;
    #pragma unroll
    for (int ks = 0; ks < 4; ks++) {
        uint32_t ahi[2][4], alo[2][4];
        #pragma unroll
        for (int mt = 0; mt < 2; mt++) {
            unsigned off = (unsigned)(wm * 32 + mt * 16 + lr) * 144 + (unsigned)(ks * 16 + lh * 8) * 2;
            ldsm4(ahi[mt], whiB + off);
            ldsm4(alo[mt], wloB + off);
        }
        uint32_t bh[2][4];
        #pragma unroll
        for (int ng = 0; ng < 2; ng++) {
            unsigned off = (unsigned)(ks * 16 + lr) * 272 + (unsigned)(wn * 32 + ng * 16 + lh * 8) * 2;
            ldsm4t(bh[ng], xB + off);
        }
        #pragma unroll
        for (int mt = 0; mt < 2; mt++)
            #pragma unroll
            for (int ng = 0; ng < 2; ng++) {
                mma16816h(acc[mt][2*ng],   ahi[mt], bh[ng][0], bh[ng][1]);
                mma16816h(acc[mt][2*ng+1], ahi[mt], bh[ng][2], bh[ng][3]);
            }
        #pragma unroll
        for (int mt = 0; mt < 2; mt++)
            #pragma unroll
            for (int ng = 0; ng < 2; ng++) {
                mma16816h(acc[mt][2*ng],   alo[mt], bh[ng][0], bh[ng][1]);
                mma16816h(acc[mt][2*ng+1], alo[mt], bh[ng][2], bh[ng][3]);
            }
    }

    const int qr = lane >> 2, qc = lane & 3;
    OT* ob = out + (size_t)bb * 64 * ldRow + j0;
    const float* sb = S + (size_t)bb * 64 * ldRow + j0;
    #pragma unroll
    for (int mt = 0; mt < 2; mt++)
        #pragma unroll
        for (int half = 0; half < 2; half++) {
            const int i = wm * 32 + mt * 16 + qr + half * 8;
            #pragma unroll
            for (int ng = 0; ng < 4; ng++) {
                const int j = wn * 32 + ng * 8 + qc * 2;
                float v0 = acc[mt][ng][half * 2 + 0];
                float v1 = acc[mt][ng][half * 2 + 1];
                if (MOD) {
                    float2 s2 = *(const float2*)(sb + (size_t)i * ldRow + j);
                    v0 *= s2.x; v1 *= s2.y;
                }
                st2(ob + (size_t)i * ldRow + j, v0, v1);
            }
        }
}

// ================================================================ fused IDCT(w) + LayerNorm + silu-gate (fp16 hi only)
#define DL_SMEM ((4096 + 2*64*392) * 4)
__global__ void __launch_bounds__(256) dct_ln_k(
    const float* __restrict__ X, const float* __restrict__ z,
    const float* __restrict__ gam, const float* __restrict__ bet,
    __half* __restrict__ dst)
{
    extern __shared__ float s[];
    float* Ws = s;
    float* Xs = s + 4096;
    float* Os = s + 4096 + 64*392;
    const int t = threadIdx.x;
    const int bb = blockIdx.x;

    for (int idx = t; idx < 4096; idx += 256) Ws[idx] = g_W[idx];
    const float* Xb = X + (size_t)bb * 24576;
    for (int f = t; f < 6144; f += 256) {
        int row = f / 96, col = (f - row * 96) * 4;
        *(float4*)&Xs[row * 392 + col] = *(const float4*)(Xb + (size_t)row * 384 + col);
    }
    __syncthreads();

    const int wpair = t >> 3;
    const int cg = t & 7;
    const int w0 = wpair * 2;
    #pragma unroll
    for (int jb = 0; jb < 4; jb++) {
        float a0[12], a1[12];
        #pragma unroll
        for (int j = 0; j < 12; j++) { a0[j] = 0.f; a1[j] = 0.f; }
        #pragma unroll 4
        for (int m = 0; m < 64; m++) {
            float wv0 = Ws[m * 64 + w0];
            float wv1 = Ws[m * 64 + w0 + 1];
            const float* xr = &Xs[m * 392 + cg + 8 * (jb * 12)];
            #pragma unroll
            for (int j = 0; j < 12; j++) {
                float xv = xr[8 * j];
                a0[j] = fmaf(wv0, xv, a0[j]);
                a1[j] = fmaf(wv1, xv, a1[j]);
            }
        }
        #pragma unroll
        for (int j = 0; j < 12; j++) {
            int c = cg + 8 * (jb * 12 + j);
            Os[w0 * 392 + c]       = a0[j];
            Os[(w0 + 1) * 392 + c] = a1[j];
        }
    }
    __syncthreads();

    const int warp = t >> 5, lane = t & 31;
    float gv[12], bv[12];
    #pragma unroll
    for (int k = 0; k < 12; k++) { gv[k] = gam[lane + 32*k]; bv[k] = bet[lane + 32*k]; }
    for (int w = warp; w < 64; w += 8) {
        float vals[12], sum = 0.f;
        #pragma unroll
        for (int k = 0; k < 12; k++) { vals[k] = Os[w * 392 + lane + 32*k]; sum += vals[k]; }
        #pragma unroll
        for (int o = 16; o; o >>= 1) sum += __shfl_xor_sync(0xffffffffu, sum, o);
        float mu = sum * (1.0f / 384.0f);
        float q = 0.f;
        #pragma unroll
        for (int k = 0; k < 12; k++) { float d = vals[k] - mu; q = fmaf(d, d, q); }
        #pragma unroll
        for (int o = 16; o; o >>= 1) q += __shfl_xor_sync(0xffffffffu, q, o);
        float inv = rsqrtf(q * (1.0f / 384.0f) + 1e-5f);
        const size_t pixel = (size_t)bb * 64 + w;
        const float* zr = z + pixel * 384;
        __half* dr = dst + pixel * 768;
        #pragma unroll
        for (int k = 0; k < 12; k++) {
            int c = lane + 32*k;
            float o = ((vals[k] - mu) * inv * gv[k] + bv[k]) * zr[c];
            dr[c] = __float2half_rn(o);
        }
    }
}

// ================================================================ launcher
#define TG_SMEM 196608

extern "C" void kernel_launch(void* const* d_in, const int* in_sizes, int n_in,
                              void* d_out, int out_size)
{
    const float* x     = (const float*)d_in[0];
    const float* freq  = (const float*)d_in[1];
    const float* dw_w  = (const float*)d_in[2];
    const float* dw_b  = (const float*)d_in[3];
    const float* lin_w = (const float*)d_in[4];
    const float* lin_b = (const float*)d_in[5];
    const float* tok_w = (const float*)d_in[6];
    const float* tok_b = (const float*)d_in[7];
    const float* ln_g  = (const float*)d_in[8];
    const float* ln_b  = (const float*)d_in[9];
    const float* out_w = (const float*)d_in[10];
    const float* out_b = (const float*)d_in[11];
    const float* cp    = (const float*)d_in[12];
    const float* ap    = (const float*)d_in[13];
    float* out = (float*)d_out;

    float *pz, *ps, *pf1;
    __half *pxd, *pxs, *pfq, *pf2, *pwl, *pwt, *pwo;
    cudaGetSymbolAddress((void**)&pz,  g_z);
    cudaGetSymbolAddress((void**)&ps,  g_s);
    cudaGetSymbolAddress((void**)&pf1, g_f1);
    cudaGetSymbolAddress((void**)&pxd, g_xd);
    cudaGetSymbolAddress((void**)&pxs, g_xs);
    cudaGetSymbolAddress((void**)&pfq, g_fq);
    cudaGetSymbolAddress((void**)&pf2, g_f2);
    cudaGetSymbolAddress((void**)&pwl, g_wl);
    cudaGetSymbolAddress((void**)&pwt, g_wt);
    cudaGetSymbolAddress((void**)&pwo, g_wo);

    cudaFuncSetAttribute((const void*)(tgemm_k<0,1>), cudaFuncAttributeMaxDynamicSharedMemorySize, TG_SMEM);
    cudaFuncSetAttribute((const void*)(tgemm_k<1,2>), cudaFuncAttributeMaxDynamicSharedMemorySize, TG_SMEM);
    cudaFuncSetAttribute((const void*)(tgemm_k<2,1>), cudaFuncAttributeMaxDynamicSharedMemorySize, TG_SMEM);
    cudaFuncSetAttribute((const void*)(dctT_k<true,  false, __half>), cudaFuncAttributeMaxDynamicSharedMemorySize, DT_SMEM);
    cudaFuncSetAttribute((const void*)(dctT_k<true,  true,  __half>), cudaFuncAttributeMaxDynamicSharedMemorySize, DT_SMEM);
    cudaFuncSetAttribute((const void*)(dctT_k<false, false, float >), cudaFuncAttributeMaxDynamicSharedMemorySize, DT_SMEM);
    cudaFuncSetAttribute((const void*)dct_ln_k,   cudaFuncAttributeMaxDynamicSharedMemorySize, DL_SMEM);

    build_w_k<<<16, 256>>>();
    split_k<<<(768*96 + 255)/256, 256>>>(lin_w, pwl, 768*96);
    dwconv_k<<<1024, 384>>>(x, dw_w, dw_b, pxd);
    split_k<<<(384*96 + 255)/256, 256>>>(tok_w, pwt, 384*96);
    split_k<<<(65536*96 + 255)/256, 256>>>(freq, pfq, 65536*96);
    // xz = xd @ lin_w^T : xs(fp16) + silu(z)(fp32)   (single-product fp16)
    tgemm_k<0,1><<<dim3(6, 512), 512, TG_SMEM>>>(pxd, pwl, lin_b, (void*)pxs, pz, nullptr, nullptr);
    split_k<<<(384*96 + 255)/256, 256>>>(out_w, pwo, 384*96);
    // s = modulation(gelu(freq @ tok_w^T))  (2-product fp16)
    tgemm_k<1,2><<<dim3(3, 512), 512, TG_SMEM>>>(pfq, pwt, tok_b, (void*)ps, nullptr, cp, ap);
    // DCT over h: xs(fp16) -> g_xd(fp16)   [xd is dead after lin GEMM]
    dctT_k<true,  false, __half><<<dim3(192, 16),  256, DT_SMEM>>>(pxd, pxs, ps, 24576);
    // DCT over w + modulate: g_xd(fp16) -> g_xs(fp16)   [xs dead after pass1]
    dctT_k<true,  true,  __half><<<dim3(3,  1024), 256, DT_SMEM>>>(pxs, pxd, ps, 384);
    // IDCT over n: g_xs(fp16) -> g_f1(fp32)
    dctT_k<false, false, float ><<<dim3(192, 16),  256, DT_SMEM>>>(pf1, pxs, ps, 24576);
    // fused IDCT over m + LayerNorm + silu-gate -> fp16 (hi only)
    dct_ln_k<<<1024, 256, DL_SMEM>>>(pf1, pz, ln_g, ln_b, pf2);
    // out = xo @ out_w^T + out_b  (single-product fp16)
    tgemm_k<2,1><<<dim3(3, 512), 512, TG_SMEM>>>(pf2, pwo, out_b, (void*)out, nullptr, nullptr, nullptr);
}

// round 16
// speedup vs baseline: 1.6296x; 1.0299x over previous
#include <cuda_runtime.h>
#include <cuda_bf16.h>
#include <cuda_fp16.h>
#include <math.h>
#include <stdint.h>

#define KDIM 384
#define NEL 25165824   // 16*64*64*384

// fp32 buffers
static __device__ float g_W[4096];      // 64x64 DCT-II matrix (fp32, for dct_ln)
// fp16 split W planes for DCT: [orient][plane hi/lo][64][72]
static __device__ __half g_Wsp[2][2][64][72];
// fp16 buffers (declared float for sizing)
static __device__ float g_xd[NEL];      // conv out [pix][768] hi-only; reused pass1/pass3 out
static __device__ float g_xs[NEL];      // xs fp16 [pix][384]; reused pass2 out
static __device__ float g_fq[NEL];      // freq fp16 [pix][768] hi-only
static __device__ float g_f2[NEL];      // LN out fp16 [pix][768] hi-only
static __device__ float g_z [NEL];      // silu(z) fp16 [pix][384]
static __device__ float g_s [NEL];      // modulation fp16 [pix][384]
static __device__ float g_wl[294912];   // split lin_w  (768 rows)
static __device__ float g_wt[147456];   // split tok_w  (384 rows)
static __device__ float g_wo[147456];   // split out_w  (384 rows)

// ================================================================ helpers
__device__ __forceinline__ uint32_t smem_u32(const void* p) {
    uint32_t a;
    asm("{ .reg .u64 t; cvta.to.shared.u64 t, %1; cvt.u32.u64 %0, t; }" : "=r"(a) : "l"(p));
    return a;
}
__device__ __forceinline__ void ldsm4(uint32_t (&r)[4], uint32_t addr) {
    asm volatile("ldmatrix.sync.aligned.m8n8.x4.shared.b16 {%0,%1,%2,%3}, [%4];"
                 : "=r"(r[0]), "=r"(r[1]), "=r"(r[2]), "=r"(r[3]) : "r"(addr));
}
__device__ __forceinline__ void ldsm4t(uint32_t (&r)[4], uint32_t addr) {
    asm volatile("ldmatrix.sync.aligned.m8n8.x4.trans.shared.b16 {%0,%1,%2,%3}, [%4];"
                 : "=r"(r[0]), "=r"(r[1]), "=r"(r[2]), "=r"(r[3]) : "r"(addr));
}
__device__ __forceinline__ void mma16816h(float (&d)[4], const uint32_t (&a)[4],
                                          uint32_t b0, uint32_t b1) {
    asm volatile(
        "mma.sync.aligned.m16n8k16.row.col.f32.f16.f16.f32 "
        "{%0,%1,%2,%3}, {%4,%5,%6,%7}, {%8,%9}, {%0,%1,%2,%3};"
        : "+f"(d[0]), "+f"(d[1]), "+f"(d[2]), "+f"(d[3])
        : "r"(a[0]), "r"(a[1]), "r"(a[2]), "r"(a[3]), "r"(b0), "r"(b1));
}
__device__ __forceinline__ unsigned swz(unsigned off) {
    return off ^ ((off >> 3) & 0x70);
}
__device__ __forceinline__ void cp16(uint32_t dst, const void* src) {
    asm volatile("cp.async.cg.shared.global [%0], [%1], 16;" :: "r"(dst), "l"(src) : "memory");
}
__device__ __forceinline__ void cp_commit() {
    asm volatile("cp.async.commit_group;" ::: "memory");
}
template<int N> __device__ __forceinline__ void cp_wait() {
    asm volatile("cp.async.wait_group %0;" :: "n"(N) : "memory");
}
__device__ __forceinline__ void split2h(float v, __half& h, __half& l) {
    h = __float2half_rn(v);
    l = __float2half_rn(v - __half2float(h));
}
__device__ __forceinline__ void st2(__half* p, float v0, float v1) {
    *(__half2*)p = __floats2half2_rn(v0, v1);
}
__device__ __forceinline__ void st2(float* p, float v0, float v1) {
    *(float2*)p = make_float2(v0, v1);
}

// ================================================================ build W
__global__ void build_w_k() {
    int i = blockIdx.x * 256 + threadIdx.x;
    int n = i >> 6, h = i & 63;
    float v = cosf((float)n * (((float)h + 0.5f) * (3.14159265358979323846f / 64.0f)))
            * 0.17677669529663687f;
    if (n == 0) v *= 0.70710678118654752f;
    g_W[i] = v;
    __half hi, lo; split2h(v, hi, lo);
    g_Wsp[0][0][n][h] = hi;
    g_Wsp[0][1][n][h] = lo;
    g_Wsp[1][0][h][n] = hi;
    g_Wsp[1][1][h][n] = lo;
}

// ================================================================ split fp32 [rows][384] -> fp16 [rows][768] (hi|lo)
__global__ void split_k(const float* __restrict__ src, __half* __restrict__ dst, int n4) {
    int i = blockIdx.x * 256 + threadIdx.x;
    if (i >= n4) return;
    int row = i / 96;
    int col = (i - row * 96) * 4;
    float4 v = *(const float4*)(src + (size_t)row * 384 + col);
    __half h0,h1,h2,h3,l0,l1,l2,l3;
    split2h(v.x,h0,l0); split2h(v.y,h1,l1); split2h(v.z,h2,l2); split2h(v.w,h3,l3);
    __half* d = dst + (size_t)row * 768 + col;
    d[0]=h0; d[1]=h1; d[2]=h2; d[3]=h3;
    d[384]=l0; d[385]=l1; d[386]=l2; d[387]=l3;
}

// ================================================================ round fp32 [rows][384] -> fp16 [rows][768] hi plane only
__global__ void roundh_k(const float* __restrict__ src, __half* __restrict__ dst, int n4) {
    int i = blockIdx.x * 256 + threadIdx.x;
    if (i >= n4) return;
    int row = i / 96;
    int col = (i - row * 96) * 4;
    float4 v = *(const float4*)(src + (size_t)row * 384 + col);
    __half* d = dst + (size_t)row * 768 + col;
    __half2 p0 = __floats2half2_rn(v.x, v.y);
    __half2 p1 = __floats2half2_rn(v.z, v.w);
    *(uint2*)d = make_uint2(*(uint32_t*)&p0, *(uint32_t*)&p1);
}

// ================================================================ depthwise conv 3x3, NCHW -> NHWC fp16 (hi only)
__global__ void dwconv_k(const float* __restrict__ x, const float* __restrict__ w9,
                         const float* __restrict__ bias, __half* __restrict__ outp)
{
    const int bh = blockIdx.x;
    const int c  = threadIdx.x;
    const int b  = bh >> 6, h = bh & 63;
    const float* xp = x + (size_t)(b * 384 + c) * 64 * 64;
    float k0 = w9[c*9+0], k1 = w9[c*9+1], k2 = w9[c*9+2];
    float k3 = w9[c*9+3], k4 = w9[c*9+4], k5 = w9[c*9+5];
    float k6 = w9[c*9+6], k7 = w9[c*9+7], k8 = w9[c*9+8];
    const float bi = bias[c];
    const float* r0 = (h > 0)  ? xp + (h-1)*64 : 0;
    const float* r1 = xp + h*64;
    const float* r2 = (h < 63) ? xp + (h+1)*64 : 0;
    float a0 = 0.f, a1 = 0.f, a2 = 0.f;
    float m0 = r0 ? r0[0] : 0.f;
    float m1 = r1[0];
    float m2 = r2 ? r2[0] : 0.f;
    __half* ob = outp + (size_t)bh * 64 * 768 + c;
    #pragma unroll 4
    for (int w = 0; w < 64; w++) {
        float n0, n1, n2;
        if (w < 63) {
            n0 = r0 ? r0[w+1] : 0.f;
            n1 = r1[w+1];
            n2 = r2 ? r2[w+1] : 0.f;
        } else { n0 = n1 = n2 = 0.f; }
        float acc = bi
            + a0*k0 + m0*k1 + n0*k2
            + a1*k3 + m1*k4 + n1*k5
            + a2*k6 + m2*k7 + n2*k8;
        ob[(size_t)w * 768] = __float2half_rn(acc);
        a0 = m0; a1 = m1; a2 = m2;
        m0 = n0; m1 = n1; m2 = n2;
    }
}

// ================================================================ mma.sync fp16 GEMM, BK=64, 3-stage cp.async pipeline
// 128x128 tile, 512 threads (16 warps, warp tile 32x32)
// PROD==1: Ahi*Bhi ; PROD==2: Ahi*Bhi + Alo*Bhi ; PROD==4: Ahi*Bhi + Ahi*Blo
// MODE 0: n<384 -> xs fp16, n>=384 -> silu fp16 (o1)
// MODE 1: modulation scalar fp16 -> o0
// MODE 2: plain bias fp32 -> o0
template<int MODE, int PROD>
__global__ void __launch_bounds__(512) tgemm_k(
    const __half* __restrict__ A, const __half* __restrict__ Wt,
    const float* __restrict__ bias,
    void* __restrict__ o0, void* __restrict__ o1,
    const float* __restrict__ cp_, const float* __restrict__ ap)
{
    extern __shared__ char sm[];
    const int t    = threadIdx.x;
    const int wid  = t >> 5;
    const int lane = t & 31;
    const int m0 = blockIdx.y * 128;
    const int n0 = blockIdx.x * 128;
    const uint32_t smemBase = smem_u32(sm);

    const __half* srcP[4];
    uint32_t dstS[4];
    bool act[4];
    #pragma unroll
    for (int r = 0; r < 4; r++) {
        int u = t + 512 * r;
        int mat = u >> 10;
        int v = u & 1023;
        int row = v >> 3;
        int s7 = v & 7;
        act[r] = (s7 < 4) || (PROD == 2 && mat == 0) || (PROD == 4 && mat == 1);
        const __half* base = mat ? (Wt + (size_t)(n0 + row) * 768)
                                 : (A  + (size_t)(m0 + row) * 768);
        int col = (s7 < 4) ? s7 * 8 : 384 + (s7 - 4) * 8;
        srcP[r] = base + col;
        dstS[r] = smemBase + mat * 32768 + swz((unsigned)(row * 128 + s7 * 16));
    }

    #define TG_ISSUE(CH, STG) do {                                               \
        const unsigned so_ = (unsigned)(STG) * 65536u;                           \
        _Pragma("unroll")                                                        \
        for (int r_ = 0; r_ < 4; r_++)                                           \
            if (act[r_]) {                                                       \
                cp16(dstS[r_] + so_,          srcP[r_] + (CH) * 64);             \
                cp16(dstS[r_] + so_ + 16384u, srcP[r_] + (CH) * 64 + 32);        \
            }                                                                    \
        cp_commit();                                                             \
    } while (0)

    TG_ISSUE(0, 0);
    TG_ISSUE(1, 1);

    const int wm = wid & 3;
    const int wn = wid >> 2;
    float acc[2][4][4];
    #pragma unroll
    for (int i = 0; i < 2; i++)
        #pragma unroll
        for (int j = 0; j < 4; j++)
            #pragma unroll
            for (int q = 0; q < 4; q++) acc[i][j][q] = 0.f;

    const int lrow = lane & 15;
    const int lkc  = (lane >> 4) << 3;

    const int NCH = KDIM / 64;   // 6
    int stg = 0;
    int istg = 2;
    for (int ch = 0; ch < NCH; ch++) {
        if (ch < NCH - 1) cp_wait<1>(); else cp_wait<0>();
        __syncthreads();
        if (ch + 2 < NCH) TG_ISSUE(ch + 2, istg);

        #pragma unroll
        for (int sub = 0; sub < 2; sub++) {
            const uint32_t aS = smemBase + (unsigned)stg * 65536u + (unsigned)sub * 16384u;
            const uint32_t bS = aS + 32768u;
            #pragma unroll
            for (int ks = 0; ks < 2; ks++) {
                const unsigned kc2 = (unsigned)(ks * 16 + lkc) * 2;
                uint32_t ahi[2][4];
                #pragma unroll
                for (int mt = 0; mt < 2; mt++) {
                    unsigned off = (unsigned)(wm * 32 + mt * 16 + lrow) * 128 + kc2;
                    ldsm4(ahi[mt], aS + swz(off));
                }
                uint32_t bhi[2][4];
                #pragma unroll
                for (int ng = 0; ng < 2; ng++) {
                    unsigned off = (unsigned)(wn * 32 + ng * 16 + lrow) * 128 + kc2;
                    ldsm4(bhi[ng], bS + swz(off));
                }
                #pragma unroll
                for (int mt = 0; mt < 2; mt++)
                    #pragma unroll
                    for (int ng = 0; ng < 2; ng++) {
                        mma16816h(acc[mt][2*ng],   ahi[mt], bhi[ng][0], bhi[ng][2]);
                        mma16816h(acc[mt][2*ng+1], ahi[mt], bhi[ng][1], bhi[ng][3]);
                    }
                if (PROD == 2) {
                    uint32_t alo[2][4];
                    #pragma unroll
                    for (int mt = 0; mt < 2; mt++) {
                        unsigned off = (unsigned)(wm * 32 + mt * 16 + lrow) * 128 + kc2;
                        ldsm4(alo[mt], aS + swz(off + 64));
                    }
                    #pragma unroll
                    for (int mt = 0; mt < 2; mt++)
                        #pragma unroll
                        for (int ng = 0; ng < 2; ng++) {
                            mma16816h(acc[mt][2*ng],   alo[mt], bhi[ng][0], bhi[ng][2]);
                            mma16816h(acc[mt][2*ng+1], alo[mt], bhi[ng][1], bhi[ng][3]);
                        }
                }
                if (PROD == 4) {
                    uint32_t blo[2][4];
                    #pragma unroll
                    for (int ng = 0; ng < 2; ng++) {
                        unsigned off = (unsigned)(wn * 32 + ng * 16 + lrow) * 128 + kc2;
                        ldsm4(blo[ng], bS + swz(off + 64));
                    }
                    #pragma unroll
                    for (int mt = 0; mt < 2; mt++)
                        #pragma unroll
                        for (int ng = 0; ng < 2; ng++) {
                            mma16816h(acc[mt][2*ng],   ahi[mt], blo[ng][0], blo[ng][2]);
                            mma16816h(acc[mt][2*ng+1], ahi[mt], blo[ng][1], blo[ng][3]);
                        }
                }
            }
        }
        stg  = (stg  == 2) ? 0 : stg  + 1;
        istg = (istg == 2) ? 0 : istg + 1;
    }
    #undef TG_ISSUE

    // ---- epilogue: warp tile 32x32
    const int qr = lane >> 2;
    const int qc = lane & 3;
    const int mbw = m0 + wm * 32;
    const int nbw = n0 + wn * 32;

    float cc0 = 0.f, css = 0.f;
    if (MODE == 1) {
        cc0 = cp_[0];
        css = (1.0f + 0.5f * ap[0]) / (cc0 + 1e-8f);
    }

    #pragma unroll
    for (int mt = 0; mt < 2; mt++) {
        #pragma unroll
        for (int half = 0; half < 2; half++) {
            const int m = mbw + mt * 16 + qr + half * 8;
            float ee = 0.f;
            if (MODE == 1) {
                const float kp = 3.14159265358979323846f / 64.0f;
                int hh = (m >> 6) & 63, ww = m & 63;
                ee = kp * kp * (float)(hh * hh + ww * ww);
            }
            #pragma unroll
            for (int nt = 0; nt < 4; nt++) {
                const int n = nbw + nt * 8 + qc * 2;
                float v0 = acc[mt][nt][half * 2 + 0] + __ldg(bias + n);
                float v1 = acc[mt][nt][half * 2 + 1] + __ldg(bias + n + 1);
                if (MODE == 0) {
                    if (n0 >= 384) {
                        v0 *= 1.0f / (1.0f + __expf(-v0));
                        v1 *= 1.0f / (1.0f + __expf(-v1));
                        st2((__half*)o1 + (size_t)m * 384 + (n - 384), v0, v1);
                    } else {
                        st2((__half*)o0 + (size_t)m * 384 + n, v0, v1);
                    }
                } else if (MODE == 1) {
                    float tg0 = 0.5f * v0 * (1.0f + erff(v0 * 0.70710678118654752f));
                    float tg1 = 0.5f * v1 * (1.0f + erff(v1 * 0.70710678118654752f));
                    float ct0 = cc0 * tg0, ct1 = cc0 * tg1;
                    float r0 = (__cosf(ct0) + __sinf(ct0) * css) * __expf(-ee * tg0);
                    float r1 = (__cosf(ct1) + __sinf(ct1) * css) * __expf(-ee * tg1);
                    st2((__half*)o0 + (size_t)m * 384 + n, r0, r1);
                } else {
                    *(float2*)((float*)o0 + (size_t)m * 384 + n) = make_float2(v0, v1);
                }
            }
        }
    }
}

// ================================================================ tensorized 64-pt cosine transform
// fp16 2-product: (Whi + Wlo) x X(fp16); input fp16, output OT (fp16 or fp32)
#define DT_SMEM (17408 + 18432)
template<bool FWD, bool MOD, typename OT>
__global__ void __launch_bounds__(256) dctT_k(
    OT* __restrict__ out, const __half* __restrict__ X,
    const __half* __restrict__ S, int ldRow)
{
    extern __shared__ char ds[];
    __half* sX  = (__half*)ds;
    __half* sWp = (__half*)(ds + 17408);
    const int t = threadIdx.x;
    const int bb = blockIdx.y;
    const int j0 = blockIdx.x << 7;

    {
        const uint4* src = (const uint4*)&g_Wsp[FWD ? 0 : 1][0][0][0];
        uint4* dst = (uint4*)sWp;
        for (int u = t; u < 1152; u += 256) dst[u] = src[u];
    }
    const __half* Xb = X + (size_t)bb * 64 * ldRow + j0;
    #pragma unroll
    for (int it = 0; it < 4; it++) {
        int idx = t + 256 * it;
        int row = idx >> 4, q = (idx & 15) << 3;
        *(uint4*)(sX + row * 136 + q) = *(const uint4*)(Xb + (size_t)row * ldRow + q);
    }
    __syncthreads();

    const int wid = t >> 5, lane = t & 31;
    const int wm = wid & 1, wn = wid >> 1;
    const uint32_t xB   = smem_u32(sX);
    const uint32_t whiB = smem_u32(sWp);
    const uint32_t wloB = whiB + 9216;

    float acc[2][4][4];
    #pragma unroll
    for (int i = 0; i < 2; i++)
        #pragma unroll
        for (int j = 0; j < 4; j++)
            #pragma unroll
            for (int q = 0; q < 4; q++) acc[i][j][q] = 0.f;

    const int lr = lane & 15, lh = lane >> 4;
    #pragma unroll
    for (int ks = 0; ks < 4; ks++) {
        uint32_t ahi[2][4], alo[2][4];
        #pragma unroll
        for (int mt = 0; mt < 2; mt++) {
            unsigned off = (unsigned)(wm * 32 + mt * 16 + lr) * 144 + (unsigned)(ks * 16 + lh * 8) * 2;
            ldsm4(ahi[mt], whiB + off);
            ldsm4(alo[mt], wloB + off);
        }
        uint32_t bh[2][4];
        #pragma unroll
        for (int ng = 0; ng < 2; ng++) {
            unsigned off = (unsigned)(ks * 16 + lr) * 272 + (unsigned)(wn * 32 + ng * 16 + lh * 8) * 2;
            ldsm4t(bh[ng], xB + off);
        }
        #pragma unroll
        for (int mt = 0; mt < 2; mt++)
            #pragma unroll
            for (int ng = 0; ng < 2; ng++) {
                mma16816h(acc[mt][2*ng],   ahi[mt], bh[ng][0], bh[ng][1]);
                mma16816h(acc[mt][2*ng+1], ahi[mt], bh[ng][2], bh[ng][3]);
            }
        #pragma unroll
        for (int mt = 0; mt < 2; mt++)
            #pragma unroll
            for (int ng = 0; ng < 2; ng++) {
                mma16816h(acc[mt][2*ng],   alo[mt], bh[ng][0], bh[ng][1]);
                mma16816h(acc[mt][2*ng+1], alo[mt], bh[ng][2], bh[ng][3]);
            }
    }

    const int qr = lane >> 2, qc = lane & 3;
    OT* ob = out + (size_t)bb * 64 * ldRow + j0;
    const __half* sb = S + (size_t)bb * 64 * ldRow + j0;
    #pragma unroll
    for (int mt = 0; mt < 2; mt++)
        #pragma unroll
        for (int half = 0; half < 2; half++) {
            const int i = wm * 32 + mt * 16 + qr + half * 8;
            #pragma unroll
            for (int ng = 0; ng < 4; ng++) {
                const int j = wn * 32 + ng * 8 + qc * 2;
                float v0 = acc[mt][ng][half * 2 + 0];
                float v1 = acc[mt][ng][half * 2 + 1];
                if (MOD) {
                    __half2 sh = *(const __half2*)(sb + (size_t)i * ldRow + j);
                    float2 s2 = __half22float2(sh);
                    v0 *= s2.x; v1 *= s2.y;
                }
                st2(ob + (size_t)i * ldRow + j, v0, v1);
            }
        }
}

// ================================================================ fused IDCT(w) + LayerNorm + silu-gate (fp16 in/out)
#define DL_SMEM ((4096 + 2*64*392) * 4)
__global__ void __launch_bounds__(256) dct_ln_k(
    const __half* __restrict__ X, const __half* __restrict__ z,
    const float* __restrict__ gam, const float* __restrict__ bet,
    __half* __restrict__ dst)
{
    extern __shared__ float s[];
    float* Ws = s;
    float* Xs = s + 4096;
    float* Os = s + 4096 + 64*392;
    const int t = threadIdx.x;
    const int bb = blockIdx.x;

    for (int idx = t; idx < 4096; idx += 256) Ws[idx] = g_W[idx];
    const __half* Xb = X + (size_t)bb * 24576;
    for (int f = t; f < 3072; f += 256) {
        int row = f / 48, col8 = (f - row * 48) * 8;
        uint4 raw = *(const uint4*)(Xb + (size_t)row * 384 + col8);
        const __half2* hp = (const __half2*)&raw;
        float* xd = &Xs[row * 392 + col8];
        #pragma unroll
        for (int q = 0; q < 4; q++) {
            float2 f2v = __half22float2(hp[q]);
            xd[q*2] = f2v.x; xd[q*2+1] = f2v.y;
        }
    }
    __syncthreads();

    const int wpair = t >> 3;
    const int cg = t & 7;
    const int w0 = wpair * 2;
    #pragma unroll
    for (int jb = 0; jb < 4; jb++) {
        float a0[12], a1[12];
        #pragma unroll
        for (int j = 0; j < 12; j++) { a0[j] = 0.f; a1[j] = 0.f; }
        #pragma unroll 4
        for (int m = 0; m < 64; m++) {
            float wv0 = Ws[m * 64 + w0];
            float wv1 = Ws[m * 64 + w0 + 1];
            const float* xr = &Xs[m * 392 + cg + 8 * (jb * 12)];
            #pragma unroll
            for (int j = 0; j < 12; j++) {
                float xv = xr[8 * j];
                a0[j] = fmaf(wv0, xv, a0[j]);
                a1[j] = fmaf(wv1, xv, a1[j]);
            }
        }
        #pragma unroll
        for (int j = 0; j < 12; j++) {
            int c = cg + 8 * (jb * 12 + j);
            Os[w0 * 392 + c]       = a0[j];
            Os[(w0 + 1) * 392 + c] = a1[j];
        }
    }
    __syncthreads();

    const int warp = t >> 5, lane = t & 31;
    float gv[12], bv[12];
    #pragma unroll
    for (int k = 0; k < 12; k++) { gv[k] = gam[lane + 32*k]; bv[k] = bet[lane + 32*k]; }
    for (int w = warp; w < 64; w += 8) {
        float vals[12], sum = 0.f;
        #pragma unroll
        for (int k = 0; k < 12; k++) { vals[k] = Os[w * 392 + lane + 32*k]; sum += vals[k]; }
        #pragma unroll
        for (int o = 16; o; o >>= 1) sum += __shfl_xor_sync(0xffffffffu, sum, o);
        float mu = sum * (1.0f / 384.0f);
        float q = 0.f;
        #pragma unroll
        for (int k = 0; k < 12; k++) { float d = vals[k] - mu; q = fmaf(d, d, q); }
        #pragma unroll
        for (int o = 16; o; o >>= 1) q += __shfl_xor_sync(0xffffffffu, q, o);
        float inv = rsqrtf(q * (1.0f / 384.0f) + 1e-5f);
        const size_t pixel = (size_t)bb * 64 + w;
        const __half* zr = z + pixel * 384;
        __half* dr = dst + pixel * 768;
        #pragma unroll
        for (int k = 0; k < 12; k++) {
            int c = lane + 32*k;
            float o = ((vals[k] - mu) * inv * gv[k] + bv[k]) * __half2float(zr[c]);
            dr[c] = __float2half_rn(o);
        }
    }
}

// ================================================================ launcher
#define TG_SMEM 196608

extern "C" void kernel_launch(void* const* d_in, const int* in_sizes, int n_in,
                              void* d_out, int out_size)
{
    const float* x     = (const float*)d_in[0];
    const float* freq  = (const float*)d_in[1];
    const float* dw_w  = (const float*)d_in[2];
    const float* dw_b  = (const float*)d_in[3];
    const float* lin_w = (const float*)d_in[4];
    const float* lin_b = (const float*)d_in[5];
    const float* tok_w = (const float*)d_in[6];
    const float* tok_b = (const float*)d_in[7];
    const float* ln_g  = (const float*)d_in[8];
    const float* ln_b  = (const float*)d_in[9];
    const float* out_w = (const float*)d_in[10];
    const float* out_b = (const float*)d_in[11];
    const float* cp    = (const float*)d_in[12];
    const float* ap    = (const float*)d_in[13];
    float* out = (float*)d_out;

    __half *pxd, *pxs, *pfq, *pf2, *pz, *ps, *pwl, *pwt, *pwo;
    cudaGetSymbolAddress((void**)&pxd, g_xd);
    cudaGetSymbolAddress((void**)&pxs, g_xs);
    cudaGetSymbolAddress((void**)&pfq, g_fq);
    cudaGetSymbolAddress((void**)&pf2, g_f2);
    cudaGetSymbolAddress((void**)&pz,  g_z);
    cudaGetSymbolAddress((void**)&ps,  g_s);
    cudaGetSymbolAddress((void**)&pwl, g_wl);
    cudaGetSymbolAddress((void**)&pwt, g_wt);
    cudaGetSymbolAddress((void**)&pwo, g_wo);

    cudaFuncSetAttribute((const void*)(tgemm_k<0,1>), cudaFuncAttributeMaxDynamicSharedMemorySize, TG_SMEM);
    cudaFuncSetAttribute((const void*)(tgemm_k<1,4>), cudaFuncAttributeMaxDynamicSharedMemorySize, TG_SMEM);
    cudaFuncSetAttribute((const void*)(tgemm_k<2,1>), cudaFuncAttributeMaxDynamicSharedMemorySize, TG_SMEM);
    cudaFuncSetAttribute((const void*)(dctT_k<true,  false, __half>), cudaFuncAttributeMaxDynamicSharedMemorySize, DT_SMEM);
    cudaFuncSetAttribute((const void*)(dctT_k<true,  true,  __half>), cudaFuncAttributeMaxDynamicSharedMemorySize, DT_SMEM);
    cudaFuncSetAttribute((const void*)(dctT_k<false, false, __half>), cudaFuncAttributeMaxDynamicSharedMemorySize, DT_SMEM);
    cudaFuncSetAttribute((const void*)dct_ln_k,   cudaFuncAttributeMaxDynamicSharedMemorySize, DL_SMEM);

    build_w_k<<<16, 256>>>();
    split_k<<<(768*96 + 255)/256, 256>>>(lin_w, pwl, 768*96);
    dwconv_k<<<1024, 384>>>(x, dw_w, dw_b, pxd);
    split_k<<<(384*96 + 255)/256, 256>>>(tok_w, pwt, 384*96);
    roundh_k<<<(65536*96 + 255)/256, 256>>>(freq, pfq, 65536*96);   // hi-only
    // xz = xd @ lin_w^T : xs(fp16) + silu(z)(fp16)   (single-product)
    tgemm_k<0,1><<<dim3(6, 512), 512, TG_SMEM>>>(pxd, pwl, lin_b, (void*)pxs, (void*)pz, nullptr, nullptr);
    split_k<<<(384*96 + 255)/256, 256>>>(out_w, pwo, 384*96);
    // s = modulation(gelu(freq @ tok_w^T))  (B-split 2-product: A rounded, B hi+lo)
    tgemm_k<1,4><<<dim3(3, 512), 512, TG_SMEM>>>(pfq, pwt, tok_b, (void*)ps, nullptr, cp, ap);
    // DCT over h: xs(fp16) -> g_xd(fp16)
    dctT_k<true,  false, __half><<<dim3(192, 16),  256, DT_SMEM>>>(pxd, pxs, ps, 24576);
    // DCT over w + modulate(s fp16): g_xd -> g_xs
    dctT_k<true,  true,  __half><<<dim3(3,  1024), 256, DT_SMEM>>>(pxs, pxd, ps, 384);
    // IDCT over n: g_xs -> g_xd (fp16)
    dctT_k<false, false, __half><<<dim3(192, 16),  256, DT_SMEM>>>(pxd, pxs, ps, 24576);
    // fused IDCT over m + LayerNorm + silu-gate(z fp16) -> fp16
    dct_ln_k<<<1024, 256, DL_SMEM>>>(pxd, pz, ln_g, ln_b, pf2);
    // out = xo @ out_w^T + out_b  (single-product, fp32 out)
    tgemm_k<2,1><<<dim3(3, 512), 512, TG_SMEM>>>(pf2, pwo, out_b, (void*)out, nullptr, nullptr, nullptr);
}

// round 17
// speedup vs baseline: 2.0196x; 1.2393x over previous
#include <cuda_runtime.h>
#include <cuda_bf16.h>
#include <cuda_fp16.h>
#include <math.h>
#include <stdint.h>

#define KDIM 384
#define NEL 25165824   // 16*64*64*384

// fp16 split W planes for DCT: [orient][plane hi/lo][64][72]
static __device__ __half g_Wsp[2][2][64][72];
// fp16 buffers (declared float for sizing)
static __device__ float g_xd[NEL];      // conv out [pix][768] hi-only; reused pass1/pass3 out
static __device__ float g_xs[NEL];      // xs fp16 [pix][384]; reused pass2/pass4 out
static __device__ float g_fq[NEL];      // freq fp16 [pix][768] hi-only
static __device__ float g_f2[NEL];      // LN out fp16 [pix][768] hi-only
static __device__ float g_z [NEL];      // silu(z) fp16 [pix][384]
static __device__ float g_s [NEL];      // modulation fp16 [pix][384]
static __device__ float g_wl[294912];   // split lin_w  (768 rows)
static __device__ float g_wt[147456];   // split tok_w  (384 rows)
static __device__ float g_wo[147456];   // split out_w  (384 rows)

// ================================================================ helpers
__device__ __forceinline__ uint32_t smem_u32(const void* p) {
    uint32_t a;
    asm("{ .reg .u64 t; cvta.to.shared.u64 t, %1; cvt.u32.u64 %0, t; }" : "=r"(a) : "l"(p));
    return a;
}
__device__ __forceinline__ void ldsm4(uint32_t (&r)[4], uint32_t addr) {
    asm volatile("ldmatrix.sync.aligned.m8n8.x4.shared.b16 {%0,%1,%2,%3}, [%4];"
                 : "=r"(r[0]), "=r"(r[1]), "=r"(r[2]), "=r"(r[3]) : "r"(addr));
}
__device__ __forceinline__ void ldsm4t(uint32_t (&r)[4], uint32_t addr) {
    asm volatile("ldmatrix.sync.aligned.m8n8.x4.trans.shared.b16 {%0,%1,%2,%3}, [%4];"
                 : "=r"(r[0]), "=r"(r[1]), "=r"(r[2]), "=r"(r[3]) : "r"(addr));
}
__device__ __forceinline__ void mma16816h(float (&d)[4], const uint32_t (&a)[4],
                                          uint32_t b0, uint32_t b1) {
    asm volatile(
        "mma.sync.aligned.m16n8k16.row.col.f32.f16.f16.f32 "
        "{%0,%1,%2,%3}, {%4,%5,%6,%7}, {%8,%9}, {%0,%1,%2,%3};"
        : "+f"(d[0]), "+f"(d[1]), "+f"(d[2]), "+f"(d[3])
        : "r"(a[0]), "r"(a[1]), "r"(a[2]), "r"(a[3]), "r"(b0), "r"(b1));
}
__device__ __forceinline__ unsigned swz(unsigned off) {
    return off ^ ((off >> 3) & 0x70);
}
__device__ __forceinline__ void cp16(uint32_t dst, const void* src) {
    asm volatile("cp.async.cg.shared.global [%0], [%1], 16;" :: "r"(dst), "l"(src) : "memory");
}
__device__ __forceinline__ void cp_commit() {
    asm volatile("cp.async.commit_group;" ::: "memory");
}
template<int N> __device__ __forceinline__ void cp_wait() {
    asm volatile("cp.async.wait_group %0;" :: "n"(N) : "memory");
}
__device__ __forceinline__ void split2h(float v, __half& h, __half& l) {
    h = __float2half_rn(v);
    l = __float2half_rn(v - __half2float(h));
}
__device__ __forceinline__ void st2(__half* p, float v0, float v1) {
    *(__half2*)p = __floats2half2_rn(v0, v1);
}
__device__ __forceinline__ void st2(float* p, float v0, float v1) {
    *(float2*)p = make_float2(v0, v1);
}

// ================================================================ build W (split planes only)
__global__ void build_w_k() {
    int i = blockIdx.x * 256 + threadIdx.x;
    int n = i >> 6, h = i & 63;
    float v = cosf((float)n * (((float)h + 0.5f) * (3.14159265358979323846f / 64.0f)))
            * 0.17677669529663687f;
    if (n == 0) v *= 0.70710678118654752f;
    __half hi, lo; split2h(v, hi, lo);
    g_Wsp[0][0][n][h] = hi;
    g_Wsp[0][1][n][h] = lo;
    g_Wsp[1][0][h][n] = hi;
    g_Wsp[1][1][h][n] = lo;
}

// ================================================================ split fp32 [rows][384] -> fp16 [rows][768] (hi|lo)
__global__ void split_k(const float* __restrict__ src, __half* __restrict__ dst, int n4) {
    int i = blockIdx.x * 256 + threadIdx.x;
    if (i >= n4) return;
    int row = i / 96;
    int col = (i - row * 96) * 4;
    float4 v = *(const float4*)(src + (size_t)row * 384 + col);
    __half h0,h1,h2,h3,l0,l1,l2,l3;
    split2h(v.x,h0,l0); split2h(v.y,h1,l1); split2h(v.z,h2,l2); split2h(v.w,h3,l3);
    __half* d = dst + (size_t)row * 768 + col;
    d[0]=h0; d[1]=h1; d[2]=h2; d[3]=h3;
    d[384]=l0; d[385]=l1; d[386]=l2; d[387]=l3;
}

// ================================================================ round fp32 [rows][384] -> fp16 [rows][768] hi plane only
__global__ void roundh_k(const float* __restrict__ src, __half* __restrict__ dst, int n4) {
    int i = blockIdx.x * 256 + threadIdx.x;
    if (i >= n4) return;
    int row = i / 96;
    int col = (i - row * 96) * 4;
    float4 v = *(const float4*)(src + (size_t)row * 384 + col);
    __half* d = dst + (size_t)row * 768 + col;
    __half2 p0 = __floats2half2_rn(v.x, v.y);
    __half2 p1 = __floats2half2_rn(v.z, v.w);
    *(uint2*)d = make_uint2(*(uint32_t*)&p0, *(uint32_t*)&p1);
}

// ================================================================ depthwise conv 3x3, NCHW -> NHWC fp16 (hi only)
__global__ void dwconv_k(const float* __restrict__ x, const float* __restrict__ w9,
                         const float* __restrict__ bias, __half* __restrict__ outp)
{
    const int bh = blockIdx.x;
    const int c  = threadIdx.x;
    const int b  = bh >> 6, h = bh & 63;
    const float* xp = x + (size_t)(b * 384 + c) * 64 * 64;
    float k0 = w9[c*9+0], k1 = w9[c*9+1], k2 = w9[c*9+2];
    float k3 = w9[c*9+3], k4 = w9[c*9+4], k5 = w9[c*9+5];
    float k6 = w9[c*9+6], k7 = w9[c*9+7], k8 = w9[c*9+8];
    const float bi = bias[c];
    const float* r0 = (h > 0)  ? xp + (h-1)*64 : 0;
    const float* r1 = xp + h*64;
    const float* r2 = (h < 63) ? xp + (h+1)*64 : 0;
    float a0 = 0.f, a1 = 0.f, a2 = 0.f;
    float m0 = r0 ? r0[0] : 0.f;
    float m1 = r1[0];
    float m2 = r2 ? r2[0] : 0.f;
    __half* ob = outp + (size_t)bh * 64 * 768 + c;
    #pragma unroll 4
    for (int w = 0; w < 64; w++) {
        float n0, n1, n2;
        if (w < 63) {
            n0 = r0 ? r0[w+1] : 0.f;
            n1 = r1[w+1];
            n2 = r2 ? r2[w+1] : 0.f;
        } else { n0 = n1 = n2 = 0.f; }
        float acc = bi
            + a0*k0 + m0*k1 + n0*k2
            + a1*k3 + m1*k4 + n1*k5
            + a2*k6 + m2*k7 + n2*k8;
        ob[(size_t)w * 768] = __float2half_rn(acc);
        a0 = m0; a1 = m1; a2 = m2;
        m0 = n0; m1 = n1; m2 = n2;
    }
}

// ================================================================ mma.sync fp16 GEMM, BK=64, 3-stage cp.async pipeline
// PROD==1: Ahi*Bhi ; PROD==2: +Alo*Bhi ; PROD==4: +Ahi*Blo
template<int MODE, int PROD>
__global__ void __launch_bounds__(512) tgemm_k(
    const __half* __restrict__ A, const __half* __restrict__ Wt,
    const float* __restrict__ bias,
    void* __restrict__ o0, void* __restrict__ o1,
    const float* __restrict__ cp_, const float* __restrict__ ap)
{
    extern __shared__ char sm[];
    const int t    = threadIdx.x;
    const int wid  = t >> 5;
    const int lane = t & 31;
    const int m0 = blockIdx.y * 128;
    const int n0 = blockIdx.x * 128;
    const uint32_t smemBase = smem_u32(sm);

    const __half* srcP[4];
    uint32_t dstS[4];
    bool act[4];
    #pragma unroll
    for (int r = 0; r < 4; r++) {
        int u = t + 512 * r;
        int mat = u >> 10;
        int v = u & 1023;
        int row = v >> 3;
        int s7 = v & 7;
        act[r] = (s7 < 4) || (PROD == 2 && mat == 0) || (PROD == 4 && mat == 1);
        const __half* base = mat ? (Wt + (size_t)(n0 + row) * 768)
                                 : (A  + (size_t)(m0 + row) * 768);
        int col = (s7 < 4) ? s7 * 8 : 384 + (s7 - 4) * 8;
        srcP[r] = base + col;
        dstS[r] = smemBase + mat * 32768 + swz((unsigned)(row * 128 + s7 * 16));
    }

    #define TG_ISSUE(CH, STG) do {                                               \
        const unsigned so_ = (unsigned)(STG) * 65536u;                           \
        _Pragma("unroll")                                                        \
        for (int r_ = 0; r_ < 4; r_++)                                           \
            if (act[r_]) {                                                       \
                cp16(dstS[r_] + so_,          srcP[r_] + (CH) * 64);             \
                cp16(dstS[r_] + so_ + 16384u, srcP[r_] + (CH) * 64 + 32);        \
            }                                                                    \
        cp_commit();                                                             \
    } while (0)

    TG_ISSUE(0, 0);
    TG_ISSUE(1, 1);

    const int wm = wid & 3;
    const int wn = wid >> 2;
    float acc[2][4][4];
    #pragma unroll
    for (int i = 0; i < 2; i++)
        #pragma unroll
        for (int j = 0; j < 4; j++)
            #pragma unroll
            for (int q = 0; q < 4; q++) acc[i][j][q] = 0.f;

    const int lrow = lane & 15;
    const int lkc  = (lane >> 4) << 3;

    const int NCH = KDIM / 64;   // 6
    int stg = 0;
    int istg = 2;
    for (int ch = 0; ch < NCH; ch++) {
        if (ch < NCH - 1) cp_wait<1>(); else cp_wait<0>();
        __syncthreads();
        if (ch + 2 < NCH) TG_ISSUE(ch + 2, istg);

        #pragma unroll
        for (int sub = 0; sub < 2; sub++) {
            const uint32_t aS = smemBase + (unsigned)stg * 65536u + (unsigned)sub * 16384u;
            const uint32_t bS = aS + 32768u;
            #pragma unroll
            for (int ks = 0; ks < 2; ks++) {
                const unsigned kc2 = (unsigned)(ks * 16 + lkc) * 2;
                uint32_t ahi[2][4];
                #pragma unroll
                for (int mt = 0; mt < 2; mt++) {
                    unsigned off = (unsigned)(wm * 32 + mt * 16 + lrow) * 128 + kc2;
                    ldsm4(ahi[mt], aS + swz(off));
                }
                uint32_t bhi[2][4];
                #pragma unroll
                for (int ng = 0; ng < 2; ng++) {
                    unsigned off = (unsigned)(wn * 32 + ng * 16 + lrow) * 128 + kc2;
                    ldsm4(bhi[ng], bS + swz(off));
                }
                #pragma unroll
                for (int mt = 0; mt < 2; mt++)
                    #pragma unroll
                    for (int ng = 0; ng < 2; ng++) {
                        mma16816h(acc[mt][2*ng],   ahi[mt], bhi[ng][0], bhi[ng][2]);
                        mma16816h(acc[mt][2*ng+1], ahi[mt], bhi[ng][1], bhi[ng][3]);
                    }
                if (PROD == 2) {
                    uint32_t alo[2][4];
                    #pragma unroll
                    for (int mt = 0; mt < 2; mt++) {
                        unsigned off = (unsigned)(wm * 32 + mt * 16 + lrow) * 128 + kc2;
                        ldsm4(alo[mt], aS + swz(off + 64));
                    }
                    #pragma unroll
                    for (int mt = 0; mt < 2; mt++)
                        #pragma unroll
                        for (int ng = 0; ng < 2; ng++) {
                            mma16816h(acc[mt][2*ng],   alo[mt], bhi[ng][0], bhi[ng][2]);
                            mma16816h(acc[mt][2*ng+1], alo[mt], bhi[ng][1], bhi[ng][3]);
                        }
                }
                if (PROD == 4) {
                    uint32_t blo[2][4];
                    #pragma unroll
                    for (int ng = 0; ng < 2; ng++) {
                        unsigned off = (unsigned)(wn * 32 + ng * 16 + lrow) * 128 + kc2;
                        ldsm4(blo[ng], bS + swz(off + 64));
                    }
                    #pragma unroll
                    for (int mt = 0; mt < 2; mt++)
                        #pragma unroll
                        for (int ng = 0; ng < 2; ng++) {
                            mma16816h(acc[mt][2*ng],   ahi[mt], blo[ng][0], blo[ng][2]);
                            mma16816h(acc[mt][2*ng+1], ahi[mt], blo[ng][1], blo[ng][3]);
                        }
                }
            }
        }
        stg  = (stg  == 2) ? 0 : stg  + 1;
        istg = (istg == 2) ? 0 : istg + 1;
    }
    #undef TG_ISSUE

    // ---- epilogue: warp tile 32x32
    const int qr = lane >> 2;
    const int qc = lane & 3;
    const int mbw = m0 + wm * 32;
    const int nbw = n0 + wn * 32;

    float cc0 = 0.f, css = 0.f;
    if (MODE == 1) {
        cc0 = cp_[0];
        css = (1.0f + 0.5f * ap[0]) / (cc0 + 1e-8f);
    }

    #pragma unroll
    for (int mt = 0; mt < 2; mt++) {
        #pragma unroll
        for (int half = 0; half < 2; half++) {
            const int m = mbw + mt * 16 + qr + half * 8;
            float ee = 0.f;
            if (MODE == 1) {
                const float kp = 3.14159265358979323846f / 64.0f;
                int hh = (m >> 6) & 63, ww = m & 63;
                ee = kp * kp * (float)(hh * hh + ww * ww);
            }
            #pragma unroll
            for (int nt = 0; nt < 4; nt++) {
                const int n = nbw + nt * 8 + qc * 2;
                float v0 = acc[mt][nt][half * 2 + 0] + __ldg(bias + n);
                float v1 = acc[mt][nt][half * 2 + 1] + __ldg(bias + n + 1);
                if (MODE == 0) {
                    if (n0 >= 384) {
                        v0 *= 1.0f / (1.0f + __expf(-v0));
                        v1 *= 1.0f / (1.0f + __expf(-v1));
                        st2((__half*)o1 + (size_t)m * 384 + (n - 384), v0, v1);
                    } else {
                        st2((__half*)o0 + (size_t)m * 384 + n, v0, v1);
                    }
                } else if (MODE == 1) {
                    float tg0 = 0.5f * v0 * (1.0f + erff(v0 * 0.70710678118654752f));
                    float tg1 = 0.5f * v1 * (1.0f + erff(v1 * 0.70710678118654752f));
                    float ct0 = cc0 * tg0, ct1 = cc0 * tg1;
                    float r0 = (__cosf(ct0) + __sinf(ct0) * css) * __expf(-ee * tg0);
                    float r1 = (__cosf(ct1) + __sinf(ct1) * css) * __expf(-ee * tg1);
                    st2((__half*)o0 + (size_t)m * 384 + n, r0, r1);
                } else {
                    *(float2*)((float*)o0 + (size_t)m * 384 + n) = make_float2(v0, v1);
                }
            }
        }
    }
}

// ================================================================ tensorized 64-pt cosine transform
// fp16 2-product: (Whi + Wlo) x X(fp16)
#define DT_SMEM (17408 + 18432)
template<bool FWD, bool MOD, typename OT>
__global__ void __launch_bounds__(256) dctT_k(
    OT* __restrict__ out, const __half* __restrict__ X,
    const __half* __restrict__ S, int ldRow)
{
    extern __shared__ char ds[];
    __half* sX  = (__half*)ds;
    __half* sWp = (__half*)(ds + 17408);
    const int t = threadIdx.x;
    const int bb = blockIdx.y;
    const int j0 = blockIdx.x << 7;

    {
        const uint4* src = (const uint4*)&g_Wsp[FWD ? 0 : 1][0][0][0];
        uint4* dst = (uint4*)sWp;
        for (int u = t; u < 1152; u += 256) dst[u] = src[u];
    }
    const __half* Xb = X + (size_t)bb * 64 * ldRow + j0;
    #pragma unroll
    for (int it = 0; it < 4; it++) {
        int idx = t + 256 * it;
        int row = idx >> 4, q = (idx & 15) << 3;
        *(uint4*)(sX + row * 136 + q) = *(const uint4*)(Xb + (size_t)row * ldRow + q);
    }
    __syncthreads();

    const int wid = t >> 5, lane = t & 31;
    const int wm = wid & 1, wn = wid >> 1;
    const uint32_t xB   = smem_u32(sX);
    const uint32_t whiB = smem_u32(sWp);
    const uint32_t wloB = whiB + 9216;

    float acc[2][4][4];
    #pragma unroll
    for (int i = 0; i < 2; i++)
        #pragma unroll
        for (int j = 0; j < 4; j++)
            #pragma unroll
            for (int q = 0; q < 4; q++) acc[i][j][q] = 0.f;

    const int lr = lane & 15, lh = lane >> 4;
    #pragma unroll
    for (int ks = 0; ks < 4; ks++) {
        uint32_t ahi[2][4], alo[2][4];
        #pragma unroll
        for (int mt = 0; mt < 2; mt++) {
            unsigned off = (unsigned)(wm * 32 + mt * 16 + lr) * 144 + (unsigned)(ks * 16 + lh * 8) * 2;
            ldsm4(ahi[mt], whiB + off);
            ldsm4(alo[mt], wloB + off);
        }
        uint32_t bh[2][4];
        #pragma unroll
        for (int ng = 0; ng < 2; ng++) {
            unsigned off = (unsigned)(ks * 16 + lr) * 272 + (unsigned)(wn * 32 + ng * 16 + lh * 8) * 2;
            ldsm4t(bh[ng], xB + off);
        }
        #pragma unroll
        for (int mt = 0; mt < 2; mt++)
            #pragma unroll
            for (int ng = 0; ng < 2; ng++) {
                mma16816h(acc[mt][2*ng],   ahi[mt], bh[ng][0], bh[ng][1]);
                mma16816h(acc[mt][2*ng+1], ahi[mt], bh[ng][2], bh[ng][3]);
            }
        #pragma unroll
        for (int mt = 0; mt < 2; mt++)
            #pragma unroll
            for (int ng = 0; ng < 2; ng++) {
                mma16816h(acc[mt][2*ng],   alo[mt], bh[ng][0], bh[ng][1]);
                mma16816h(acc[mt][2*ng+1], alo[mt], bh[ng][2], bh[ng][3]);
            }
    }

    const int qr = lane >> 2, qc = lane & 3;
    OT* ob = out + (size_t)bb * 64 * ldRow + j0;
    const __half* sb = S + (size_t)bb * 64 * ldRow + j0;
    #pragma unroll
    for (int mt = 0; mt < 2; mt++)
        #pragma unroll
        for (int half = 0; half < 2; half++) {
            const int i = wm * 32 + mt * 16 + qr + half * 8;
            #pragma unroll
            for (int ng = 0; ng < 4; ng++) {
                const int j = wn * 32 + ng * 8 + qc * 2;
                float v0 = acc[mt][ng][half * 2 + 0];
                float v1 = acc[mt][ng][half * 2 + 1];
                if (MOD) {
                    __half2 sh = *(const __half2*)(sb + (size_t)i * ldRow + j);
                    float2 s2 = __half22float2(sh);
                    v0 *= s2.x; v1 *= s2.y;
                }
                st2(ob + (size_t)i * ldRow + j, v0, v1);
            }
        }
}

// ================================================================ LayerNorm(384) * silu-gate, warp-per-row, fp16 in/out
__global__ void __launch_bounds__(256) ln_silu_k(
    const __half* __restrict__ X, const __half* __restrict__ z,
    const float* __restrict__ gam, const float* __restrict__ bet,
    __half* __restrict__ dst)
{
    const int warp = threadIdx.x >> 5, lane = threadIdx.x & 31;
    const size_t row = (size_t)blockIdx.x * 8 + warp;
    const __half* xr = X + row * 384;
    float vals[12];
    float sum = 0.f;
    #pragma unroll
    for (int k = 0; k < 6; k++) {
        __half2 h = *(const __half2*)(xr + 2 * (lane + 32 * k));
        float2 f = __half22float2(h);
        vals[2*k] = f.x; vals[2*k+1] = f.y;
        sum += f.x + f.y;
    }
    #pragma unroll
    for (int o = 16; o; o >>= 1) sum += __shfl_xor_sync(0xffffffffu, sum, o);
    float mu = sum * (1.0f / 384.0f);
    float q = 0.f;
    #pragma unroll
    for (int k = 0; k < 12; k++) { float d = vals[k] - mu; q = fmaf(d, d, q); }
    #pragma unroll
    for (int o = 16; o; o >>= 1) q += __shfl_xor_sync(0xffffffffu, q, o);
    float inv = rsqrtf(q * (1.0f / 384.0f) + 1e-5f);
    const __half* zr = z + row * 384;
    __half* dr = dst + row * 768;
    #pragma unroll
    for (int k = 0; k < 6; k++) {
        int col = 2 * (lane + 32 * k);
        float2 gb0 = *(const float2*)(gam + col);
        float2 bb0 = *(const float2*)(bet + col);
        float2 zz = __half22float2(*(const __half2*)(zr + col));
        float o0 = ((vals[2*k]   - mu) * inv * gb0.x + bb0.x) * zz.x;
        float o1 = ((vals[2*k+1] - mu) * inv * gb0.y + bb0.y) * zz.y;
        st2(dr + col, o0, o1);
    }
}

// ================================================================ launcher
#define TG_SMEM 196608

extern "C" void kernel_launch(void* const* d_in, const int* in_sizes, int n_in,
                              void* d_out, int out_size)
{
    const float* x     = (const float*)d_in[0];
    const float* freq  = (const float*)d_in[1];
    const float* dw_w  = (const float*)d_in[2];
    const float* dw_b  = (const float*)d_in[3];
    const float* lin_w = (const float*)d_in[4];
    const float* lin_b = (const float*)d_in[5];
    const float* tok_w = (const float*)d_in[6];
    const float* tok_b = (const float*)d_in[7];
    const float* ln_g  = (const float*)d_in[8];
    const float* ln_b  = (const float*)d_in[9];
    const float* out_w = (const float*)d_in[10];
    const float* out_b = (const float*)d_in[11];
    const float* cp    = (const float*)d_in[12];
    const float* ap    = (const float*)d_in[13];
    float* out = (float*)d_out;

    __half *pxd, *pxs, *pfq, *pf2, *pz, *ps, *pwl, *pwt, *pwo;
    cudaGetSymbolAddress((void**)&pxd, g_xd);
    cudaGetSymbolAddress((void**)&pxs, g_xs);
    cudaGetSymbolAddress((void**)&pfq, g_fq);
    cudaGetSymbolAddress((void**)&pf2, g_f2);
    cudaGetSymbolAddress((void**)&pz,  g_z);
    cudaGetSymbolAddress((void**)&ps,  g_s);
    cudaGetSymbolAddress((void**)&pwl, g_wl);
    cudaGetSymbolAddress((void**)&pwt, g_wt);
    cudaGetSymbolAddress((void**)&pwo, g_wo);

    cudaFuncSetAttribute((const void*)(tgemm_k<0,1>), cudaFuncAttributeMaxDynamicSharedMemorySize, TG_SMEM);
    cudaFuncSetAttribute((const void*)(tgemm_k<1,4>), cudaFuncAttributeMaxDynamicSharedMemorySize, TG_SMEM);
    cudaFuncSetAttribute((const void*)(tgemm_k<2,1>), cudaFuncAttributeMaxDynamicSharedMemorySize, TG_SMEM);
    cudaFuncSetAttribute((const void*)(dctT_k<true,  false, __half>), cudaFuncAttributeMaxDynamicSharedMemorySize, DT_SMEM);
    cudaFuncSetAttribute((const void*)(dctT_k<true,  true,  __half>), cudaFuncAttributeMaxDynamicSharedMemorySize, DT_SMEM);
    cudaFuncSetAttribute((const void*)(dctT_k<false, false, __half>), cudaFuncAttributeMaxDynamicSharedMemorySize, DT_SMEM);

    build_w_k<<<16, 256>>>();                                               // 1
    split_k<<<(768*96 + 255)/256, 256>>>(lin_w, pwl, 768*96);               // 2
    dwconv_k<<<1024, 384>>>(x, dw_w, dw_b, pxd);                            // 3
    // xz = xd @ lin_w^T : xs(fp16) + silu(z)(fp16)                         // 4 <- profiled
    tgemm_k<0,1><<<dim3(6, 512), 512, TG_SMEM>>>(pxd, pwl, lin_b, (void*)pxs, (void*)pz, nullptr, nullptr);
    split_k<<<(384*96 + 255)/256, 256>>>(tok_w, pwt, 384*96);               // 5
    roundh_k<<<(65536*96 + 255)/256, 256>>>(freq, pfq, 65536*96);           // 6
    // s = modulation(gelu(freq @ tok_w^T))  (B-split 2-product)
    tgemm_k<1,4><<<dim3(3, 512), 512, TG_SMEM>>>(pfq, pwt, tok_b, (void*)ps, nullptr, cp, ap);
    split_k<<<(384*96 + 255)/256, 256>>>(out_w, pwo, 384*96);
    // DCT over h: xs -> g_xd
    dctT_k<true,  false, __half><<<dim3(192, 16),  256, DT_SMEM>>>(pxd, pxs, ps, 24576);
    // DCT over w + modulate(s): g_xd -> g_xs
    dctT_k<true,  true,  __half><<<dim3(3,  1024), 256, DT_SMEM>>>(pxs, pxd, ps, 384);
    // IDCT over n: g_xs -> g_xd
    dctT_k<false, false, __half><<<dim3(192, 16),  256, DT_SMEM>>>(pxd, pxs, ps, 24576);
    // IDCT over m (tensorized): g_xd -> g_xs
    dctT_k<false, false, __half><<<dim3(3,  1024), 256, DT_SMEM>>>(pxs, pxd, ps, 384);
    // LayerNorm * silu-gate: g_xs, z -> g_f2 (hi-only [pix][768])
    ln_silu_k<<<8192, 256>>>(pxs, pz, ln_g, ln_b, pf2);
    // out = xo @ out_w^T + out_b  (single-product, fp32 out)
    tgemm_k<2,1><<<dim3(3, 512), 512, TG_SMEM>>>(pf2, pwo, out_b, (void*)out, nullptr, nullptr, nullptr);
}